// round 6
// baseline (speedup 1.0000x reference)
#include <cuda_runtime.h>
#include <cuda_bf16.h>
#include <cuda_fp16.h>
#include <math.h>

#define N_NODES 100000
#define N_EDGES 1200000
#define N_GRAPHS 128
#define MAX_DEG 64            // Poisson(12): P(deg>=64) ~ 1e-30, guarded anyway

// ---------------- scratch ----------------
__device__ float  g_h[(size_t)N_NODES * 64];
__device__ __half g_hh[(size_t)N_NODES * 64];   // fp16 mirror for neighbor gather
__device__ float  g_agg[(size_t)N_NODES * 64];
__device__ float  g_pooled[N_GRAPHS * 64];
__device__ int    g_bounds[N_GRAPHS + 1];

__device__ int g_cnt[N_NODES];
__device__ int g_adj[(size_t)N_NODES * MAX_DEG];

__device__ __forceinline__ float elu(float v) {
    return v > 0.f ? v : expm1f(v);
}

// ---- packed f32x2 helpers (sm_103a FFMA2) ----
__device__ __forceinline__ void ffma2(unsigned long long& d,
                                      unsigned long long a,
                                      unsigned long long b) {
    asm("fma.rn.f32x2 %0, %1, %2, %0;" : "+l"(d) : "l"(a), "l"(b));
}
__device__ __forceinline__ unsigned long long pack2(float x) {
    unsigned long long r;
    unsigned int u = __float_as_uint(x);
    asm("mov.b64 %0, {%1, %1};" : "=l"(r) : "r"(u));
    return r;
}
__device__ __forceinline__ float2 unpack2(unsigned long long p) {
    unsigned int lo, hi;
    asm("mov.b64 {%0, %1}, %2;" : "=r"(lo), "=r"(hi) : "l"(p));
    return make_float2(__uint_as_float(lo), __uint_as_float(hi));
}

// ---------------- adjacency build ----------------
__global__ void k_zero_cnt() {
    int i = blockIdx.x * blockDim.x + threadIdx.x;
    if (i < N_NODES) g_cnt[i] = 0;
}

__global__ void k_fill(const int* __restrict__ src, const int* __restrict__ dst) {
    int e = blockIdx.x * blockDim.x + threadIdx.x;
    if (e >= N_EDGES) return;
    int d = __ldg(dst + e);
    int slot = atomicAdd(&g_cnt[d], 1);
    if (slot < MAX_DEG)
        g_adj[(size_t)d * MAX_DEG + slot] = __ldg(src + e);
}

// ---------------- embedding gather (writes fp32 + fp16 mirror) --------------
__global__ void k_embed(const int* __restrict__ x, const float* __restrict__ emb) {
    int tid = blockIdx.x * blockDim.x + threadIdx.x;
    if (tid >= N_NODES * 16) return;
    int i = tid >> 4, c = tid & 15;
    int xv = __ldg(x + i);
    float4 v = reinterpret_cast<const float4*>(emb)[(size_t)xv * 16 + c];
    reinterpret_cast<float4*>(g_h)[(size_t)i * 16 + c] = v;
    __half2 p0 = __floats2half2_rn(v.x, v.y);
    __half2 p1 = __floats2half2_rn(v.z, v.w);
    uint2 pk;
    pk.x = *reinterpret_cast<unsigned int*>(&p0);
    pk.y = *reinterpret_cast<unsigned int*>(&p1);
    reinterpret_cast<uint2*>(g_hh)[(size_t)i * 16 + c] = pk;
}

// ---------------- gather: agg[n] = h_fp32[n] + sum_{nb} h_fp16[nb] ----------
__global__ void __launch_bounds__(256) k_gather() {
    int t = threadIdx.x;
    int n = blockIdx.x * 16 + (t >> 4);
    int c = t & 15;
    if (n >= N_NODES) return;
    float4 acc = reinterpret_cast<const float4*>(g_h)[(size_t)n * 16 + c];
    const int* __restrict__ alist = g_adj + (size_t)n * MAX_DEG;
    const uint2* __restrict__ hh2 = reinterpret_cast<const uint2*>(g_hh);
    int e = min(g_cnt[n], MAX_DEG);
    int nxt = (e > 0) ? __ldg(alist) : 0;
    for (int i = 0; i < e; i++) {
        int cur = nxt;
        if (i + 1 < e) nxt = __ldg(alist + i + 1);
        uint2 v = __ldg(&hh2[(size_t)cur * 16 + c]);
        float2 f0 = __half22float2(*reinterpret_cast<__half2*>(&v.x));
        float2 f1 = __half22float2(*reinterpret_cast<__half2*>(&v.y));
        acc.x += f0.x; acc.y += f0.y; acc.z += f1.x; acc.w += f1.y;
    }
    reinterpret_cast<float4*>(g_agg)[(size_t)n * 16 + c] = acc;
}

// ---------------- fused MLP+BN+ELU: h = elu(mlp_bn(agg)) ----------------
// 128 threads, 64-node tile. Thread (rg=t&15, cg=t>>4) computes rows
// {rg,rg+16,rg+32,rg+48} x cols {8cg..8cg+7}, acc as f32x2 pairs (FFMA2).
__global__ void __launch_bounds__(128) k_mlp(
    const float* __restrict__ W1, const float* __restrict__ b1,
    const float* __restrict__ gam, const float* __restrict__ bet,
    const float* __restrict__ W2, const float* __restrict__ b2)
{
    __shared__ float Ws[64 * 64];
    __shared__ float s_in[64 * 65];
    __shared__ float sb1[64], ssc[64], sbe[64], sb2[64];

    const int t = threadIdx.x;
    const int rg = t & 15;
    const int cg = t >> 4;
    const int base = blockIdx.x * 64;

    if (t < 64) {
        sb1[t] = b1[t];
        ssc[t] = gam[t] * rsqrtf(1.0f + 1e-5f);
        sbe[t] = bet[t];
        sb2[t] = b2[t];
    }
    float4* Ws4 = reinterpret_cast<float4*>(Ws);
    const float4* W1_4 = reinterpret_cast<const float4*>(W1);
    const float4* W2_4 = reinterpret_cast<const float4*>(W2);
#pragma unroll
    for (int i = t; i < 1024; i += 128) Ws4[i] = W1_4[i];

    // stage 64 input rows (coalesced: 16 float4 per row)
#pragma unroll
    for (int i = t; i < 1024; i += 128) {
        int r = i >> 4, c = (i & 15) << 2;
        int row = base + r;
        float4 v = make_float4(0.f, 0.f, 0.f, 0.f);
        if (row < N_NODES)
            v = *reinterpret_cast<const float4*>(g_agg + (size_t)row * 64 + c);
        s_in[r * 65 + c + 0] = v.x;
        s_in[r * 65 + c + 1] = v.y;
        s_in[r * 65 + c + 2] = v.z;
        s_in[r * 65 + c + 3] = v.w;
    }
    __syncthreads();

    // ---------- GEMM1 (FFMA2) ----------
    unsigned long long acc[4][4];
#pragma unroll
    for (int m = 0; m < 4; m++)
#pragma unroll
        for (int u = 0; u < 4; u++) acc[m][u] = 0ull;

#pragma unroll 4
    for (int k = 0; k < 64; k++) {
        const float* wrow = Ws + k * 64 + cg * 8;
        ulonglong2 wa = *reinterpret_cast<const ulonglong2*>(wrow);
        ulonglong2 wb = *reinterpret_cast<const ulonglong2*>(wrow + 4);
#pragma unroll
        for (int m = 0; m < 4; m++) {
            unsigned long long a2 = pack2(s_in[(rg + 16 * m) * 65 + k]);
            ffma2(acc[m][0], a2, wa.x);
            ffma2(acc[m][1], a2, wa.y);
            ffma2(acc[m][2], a2, wb.x);
            ffma2(acc[m][3], a2, wb.y);
        }
    }
    __syncthreads();

    // epilogue 1: BN affine + ELU, write back to s_in; swap Ws -> W2
#pragma unroll
    for (int m = 0; m < 4; m++) {
        int row = rg + 16 * m;
#pragma unroll
        for (int u = 0; u < 4; u++) {
            float2 p = unpack2(acc[m][u]);
            int j = cg * 8 + u * 2;
            float v0 = (p.x + sb1[j])     * ssc[j]     + sbe[j];
            float v1 = (p.y + sb1[j + 1]) * ssc[j + 1] + sbe[j + 1];
            s_in[row * 65 + j]     = elu(v0);
            s_in[row * 65 + j + 1] = elu(v1);
        }
    }
#pragma unroll
    for (int i = t; i < 1024; i += 128) Ws4[i] = W2_4[i];
    __syncthreads();

    // ---------- GEMM2 (FFMA2) ----------
#pragma unroll
    for (int m = 0; m < 4; m++)
#pragma unroll
        for (int u = 0; u < 4; u++) acc[m][u] = 0ull;

#pragma unroll 4
    for (int k = 0; k < 64; k++) {
        const float* wrow = Ws + k * 64 + cg * 8;
        ulonglong2 wa = *reinterpret_cast<const ulonglong2*>(wrow);
        ulonglong2 wb = *reinterpret_cast<const ulonglong2*>(wrow + 4);
#pragma unroll
        for (int m = 0; m < 4; m++) {
            unsigned long long a2 = pack2(s_in[(rg + 16 * m) * 65 + k]);
            ffma2(acc[m][0], a2, wa.x);
            ffma2(acc[m][1], a2, wa.y);
            ffma2(acc[m][2], a2, wb.x);
            ffma2(acc[m][3], a2, wb.y);
        }
    }

    // epilogue 2: bias + outer ELU, write h (fp32) + fp16 mirror
#pragma unroll
    for (int m = 0; m < 4; m++) {
        int row = base + rg + 16 * m;
        if (row < N_NODES) {
            float o[8];
#pragma unroll
            for (int u = 0; u < 4; u++) {
                float2 p = unpack2(acc[m][u]);
                int j = cg * 8 + u * 2;
                o[u * 2]     = elu(p.x + sb2[j]);
                o[u * 2 + 1] = elu(p.y + sb2[j + 1]);
            }
            float* orow = g_h + (size_t)row * 64 + cg * 8;
            *reinterpret_cast<float4*>(orow)     = make_float4(o[0], o[1], o[2], o[3]);
            *reinterpret_cast<float4*>(orow + 4) = make_float4(o[4], o[5], o[6], o[7]);

            __half2 q0 = __floats2half2_rn(o[0], o[1]);
            __half2 q1 = __floats2half2_rn(o[2], o[3]);
            __half2 q2 = __floats2half2_rn(o[4], o[5]);
            __half2 q3 = __floats2half2_rn(o[6], o[7]);
            uint4 pk;
            pk.x = *reinterpret_cast<unsigned int*>(&q0);
            pk.y = *reinterpret_cast<unsigned int*>(&q1);
            pk.z = *reinterpret_cast<unsigned int*>(&q2);
            pk.w = *reinterpret_cast<unsigned int*>(&q3);
            *reinterpret_cast<uint4*>(g_hh + (size_t)row * 64 + cg * 8) = pk;
        }
    }
}

// ---------------- group boundaries (batch sorted) ----------------
__global__ void k_bounds(const int* __restrict__ batch) {
    int g = threadIdx.x;
    if (g > N_GRAPHS) return;
    int lo = 0, hi = N_NODES;
    while (lo < hi) {
        int mid = (lo + hi) >> 1;
        if (batch[mid] < g) lo = mid + 1; else hi = mid;
    }
    g_bounds[g] = lo;
}

// ---------------- mean pool ----------------
__global__ void k_pool() {
    int g = blockIdx.x;
    int f = threadIdx.x & 63;
    int s = threadIdx.x >> 6;
    int start = g_bounds[g], end = g_bounds[g + 1];
    float acc = 0.f;
    for (int i = start + s; i < end; i += 4)
        acc += g_h[(size_t)i * 64 + f];
    __shared__ float red[256];
    red[threadIdx.x] = acc;
    __syncthreads();
    if (s == 0) {
        float v = red[f] + red[f + 64] + red[f + 128] + red[f + 192];
        float cnt = (float)(end - start);
        g_pooled[g * 64 + f] = v / fmaxf(cnt, 1.0f);
    }
}

// ---------------- head ----------------
__global__ void __launch_bounds__(64) k_head(
    const float* __restrict__ Wr1, const float* __restrict__ br1,
    const float* __restrict__ Wr2, const float* __restrict__ br2,
    const float* __restrict__ Wo,  const float* __restrict__ bo,
    float* __restrict__ out)
{
    __shared__ float Ws[64 * 64];
    __shared__ float s_p[64 * 65];
    __shared__ float sb[64];
    __shared__ float sWo[64];

    const int t = threadIdx.x;
    const int gbase = blockIdx.x * 64;

    sb[t]  = br1[t];
    sWo[t] = Wo[t];
#pragma unroll
    for (int i = t; i < 4096; i += 64) Ws[i] = Wr1[i];
#pragma unroll
    for (int i = 4 * t; i < 4096; i += 256) {
        int r = i >> 6, c = i & 63;
        float4 v = *reinterpret_cast<const float4*>(g_pooled + (size_t)(gbase + r) * 64 + c);
        s_p[r * 65 + c + 0] = v.x;
        s_p[r * 65 + c + 1] = v.y;
        s_p[r * 65 + c + 2] = v.z;
        s_p[r * 65 + c + 3] = v.w;
    }
    __syncthreads();

    const float* myrow = s_p + t * 65;
    float tt[64];

#pragma unroll
    for (int jt = 0; jt < 64; jt += 8) {
        float acc[8];
#pragma unroll
        for (int u = 0; u < 8; u++) acc[u] = 0.f;
#pragma unroll 4
        for (int k = 0; k < 64; k++) {
            float a = myrow[k];
            const float* w = Ws + k * 64 + jt;
            float4 w0 = *reinterpret_cast<const float4*>(w);
            float4 w1 = *reinterpret_cast<const float4*>(w + 4);
            acc[0] += a * w0.x; acc[1] += a * w0.y;
            acc[2] += a * w0.z; acc[3] += a * w0.w;
            acc[4] += a * w1.x; acc[5] += a * w1.y;
            acc[6] += a * w1.z; acc[7] += a * w1.w;
        }
#pragma unroll
        for (int u = 0; u < 8; u++) tt[jt + u] = elu(acc[u] + sb[jt + u]);
    }

#pragma unroll
    for (int j = 0; j < 64; j++) s_p[t * 65 + j] = tt[j];
    __syncthreads();
#pragma unroll
    for (int i = t; i < 4096; i += 64) Ws[i] = Wr2[i];
    sb[t] = br2[t];
    __syncthreads();

    float oacc = 0.f;
#pragma unroll
    for (int jt = 0; jt < 64; jt += 8) {
        float acc[8];
#pragma unroll
        for (int u = 0; u < 8; u++) acc[u] = 0.f;
#pragma unroll 4
        for (int k = 0; k < 64; k++) {
            float a = myrow[k];
            const float* w = Ws + k * 64 + jt;
            float4 w0 = *reinterpret_cast<const float4*>(w);
            float4 w1 = *reinterpret_cast<const float4*>(w + 4);
            acc[0] += a * w0.x; acc[1] += a * w0.y;
            acc[2] += a * w0.z; acc[3] += a * w0.w;
            acc[4] += a * w1.x; acc[5] += a * w1.y;
            acc[6] += a * w1.z; acc[7] += a * w1.w;
        }
#pragma unroll
        for (int u = 0; u < 8; u++)
            oacc += (acc[u] + sb[jt + u]) * sWo[jt + u];
    }
    out[gbase + t] = oacc + bo[0];
}

// ---------------- launcher ----------------
extern "C" void kernel_launch(void* const* d_in, const int* in_sizes, int n_in,
                              void* d_out, int out_size) {
    const int*   x     = (const int*)d_in[0];
    const int*   ei    = (const int*)d_in[1];
    const int*   batch = (const int*)d_in[2];
    const float* emb   = (const float*)d_in[3];
    const int* src = ei;
    const int* dst = ei + N_EDGES;
    float* out = (float*)d_out;

    const int TPB = 256;
    const int gcpy = (N_NODES * 16 + TPB - 1) / TPB;
    const int gnod = (N_NODES + TPB - 1) / TPB;
    const int gedg = (N_EDGES + TPB - 1) / TPB;
    const int gmlp = (N_NODES + 63) / 64;
    const int ggat = (N_NODES + 15) / 16;

    // launches 1-4 (k_bounds early so ncu capture slot #6 = k_mlp layer 1)
    k_zero_cnt<<<gnod, TPB>>>();
    k_fill<<<gedg, TPB>>>(src, dst);
    k_embed<<<gcpy, TPB>>>(x, emb);
    k_bounds<<<1, 256>>>(batch);

    for (int L = 0; L < 3; L++) {
        const float* W1  = (const float*)d_in[4 + 6 * L + 0];
        const float* b1  = (const float*)d_in[4 + 6 * L + 1];
        const float* gam = (const float*)d_in[4 + 6 * L + 2];
        const float* bet = (const float*)d_in[4 + 6 * L + 3];
        const float* W2  = (const float*)d_in[4 + 6 * L + 4];
        const float* b2  = (const float*)d_in[4 + 6 * L + 5];

        k_gather<<<ggat, 256>>>();
        k_mlp<<<gmlp, 128>>>(W1, b1, gam, bet, W2, b2);
    }

    k_pool<<<N_GRAPHS, 256>>>();
    k_head<<<2, 64>>>((const float*)d_in[22], (const float*)d_in[23],
                      (const float*)d_in[24], (const float*)d_in[25],
                      (const float*)d_in[26], (const float*)d_in[27],
                      out);
}

// round 7
// speedup vs baseline: 1.0092x; 1.0092x over previous
#include <cuda_runtime.h>
#include <cuda_bf16.h>
#include <cuda_fp16.h>
#include <math.h>

#define N_NODES 100000
#define N_EDGES 1200000
#define N_GRAPHS 128
#define MAX_DEG 64            // Poisson(12): P(deg>=64) ~ 1e-30, guarded anyway

// ---------------- scratch ----------------
__device__ float  g_h[(size_t)N_NODES * 64];
__device__ __half g_hh[(size_t)N_NODES * 64];   // fp16 mirror for neighbor gather
__device__ float  g_agg[(size_t)N_NODES * 64];
__device__ float  g_pooled[N_GRAPHS * 64];

__device__ int g_cnt[N_NODES];
__device__ int g_adj[(size_t)N_NODES * MAX_DEG];

__device__ __forceinline__ float elu(float v) {
    return v > 0.f ? v : expm1f(v);
}

// ---- packed f32x2 helpers (sm_103a FFMA2) ----
__device__ __forceinline__ void ffma2(unsigned long long& d,
                                      unsigned long long a,
                                      unsigned long long b) {
    asm("fma.rn.f32x2 %0, %1, %2, %0;" : "+l"(d) : "l"(a), "l"(b));
}
__device__ __forceinline__ unsigned long long pack2(float x) {
    unsigned long long r;
    unsigned int u = __float_as_uint(x);
    asm("mov.b64 %0, {%1, %1};" : "=l"(r) : "r"(u));
    return r;
}
__device__ __forceinline__ float2 unpack2(unsigned long long p) {
    unsigned int lo, hi;
    asm("mov.b64 {%0, %1}, %2;" : "=r"(lo), "=r"(hi) : "l"(p));
    return make_float2(__uint_as_float(lo), __uint_as_float(hi));
}

// ---------------- adjacency build ----------------
__global__ void k_zero_cnt() {
    int i = blockIdx.x * blockDim.x + threadIdx.x;
    if (i < N_NODES) g_cnt[i] = 0;
}

__global__ void k_fill(const int* __restrict__ src, const int* __restrict__ dst) {
    int e = blockIdx.x * blockDim.x + threadIdx.x;
    if (e >= N_EDGES) return;
    int d = __ldg(dst + e);
    int slot = atomicAdd(&g_cnt[d], 1);
    if (slot < MAX_DEG)
        g_adj[(size_t)d * MAX_DEG + slot] = __ldg(src + e);
}

// ------- layer-1 gather straight from embedding: agg[n]=emb[x[n]]+sum emb[x[nb]]
__global__ void __launch_bounds__(256) k_gather1(const int* __restrict__ x,
                                                 const float* __restrict__ emb) {
    int t = threadIdx.x;
    int n = blockIdx.x * 16 + (t >> 4);
    int c = t & 15;
    if (n >= N_NODES) return;
    const float4* __restrict__ e4 = reinterpret_cast<const float4*>(emb);
    int xn = __ldg(x + n);
    float4 acc = e4[(size_t)xn * 16 + c];
    const int* __restrict__ alist = g_adj + (size_t)n * MAX_DEG;
    int e = min(g_cnt[n], MAX_DEG);
    for (int i = 0; i < e; i++) {
        int s = __ldg(alist + i);
        int xs = __ldg(x + s);
        float4 v = e4[(size_t)xs * 16 + c];
        acc.x += v.x; acc.y += v.y; acc.z += v.z; acc.w += v.w;
    }
    reinterpret_cast<float4*>(g_agg)[(size_t)n * 16 + c] = acc;
}

// ---------------- gather (layers 2-3): agg[n] = h_fp32[n] + sum h_fp16[nb] ---
__global__ void __launch_bounds__(256) k_gather() {
    int t = threadIdx.x;
    int n = blockIdx.x * 16 + (t >> 4);
    int c = t & 15;
    if (n >= N_NODES) return;
    float4 acc = reinterpret_cast<const float4*>(g_h)[(size_t)n * 16 + c];
    const int* __restrict__ alist = g_adj + (size_t)n * MAX_DEG;
    const uint2* __restrict__ hh2 = reinterpret_cast<const uint2*>(g_hh);
    int e = min(g_cnt[n], MAX_DEG);
    int nxt = (e > 0) ? __ldg(alist) : 0;
    for (int i = 0; i < e; i++) {
        int cur = nxt;
        if (i + 1 < e) nxt = __ldg(alist + i + 1);
        uint2 v = __ldg(&hh2[(size_t)cur * 16 + c]);
        float2 f0 = __half22float2(*reinterpret_cast<__half2*>(&v.x));
        float2 f1 = __half22float2(*reinterpret_cast<__half2*>(&v.y));
        acc.x += f0.x; acc.y += f0.y; acc.z += f1.x; acc.w += f1.y;
    }
    reinterpret_cast<float4*>(g_agg)[(size_t)n * 16 + c] = acc;
}

// ---------------- fused MLP+BN+ELU: h = elu(mlp_bn(agg)) ----------------
// 128 threads, 64-node tile. Thread (rg=t&15, cg=t>>4) computes rows
// {rg,rg+16,rg+32,rg+48} x cols {8cg..8cg+7}, acc as f32x2 pairs (FFMA2).
__global__ void __launch_bounds__(128) k_mlp(
    const float* __restrict__ W1, const float* __restrict__ b1,
    const float* __restrict__ gam, const float* __restrict__ bet,
    const float* __restrict__ W2, const float* __restrict__ b2,
    int write_fp16)
{
    __shared__ float Ws[64 * 64];
    __shared__ float s_in[64 * 65];
    __shared__ float sb1[64], ssc[64], sbe[64], sb2[64];

    const int t = threadIdx.x;
    const int rg = t & 15;
    const int cg = t >> 4;
    const int base = blockIdx.x * 64;

    if (t < 64) {
        sb1[t] = b1[t];
        ssc[t] = gam[t] * rsqrtf(1.0f + 1e-5f);
        sbe[t] = bet[t];
        sb2[t] = b2[t];
    }
    float4* Ws4 = reinterpret_cast<float4*>(Ws);
    const float4* W1_4 = reinterpret_cast<const float4*>(W1);
    const float4* W2_4 = reinterpret_cast<const float4*>(W2);
#pragma unroll
    for (int i = t; i < 1024; i += 128) Ws4[i] = W1_4[i];

    // stage 64 input rows (coalesced: 16 float4 per row)
#pragma unroll
    for (int i = t; i < 1024; i += 128) {
        int r = i >> 4, c = (i & 15) << 2;
        int row = base + r;
        float4 v = make_float4(0.f, 0.f, 0.f, 0.f);
        if (row < N_NODES)
            v = *reinterpret_cast<const float4*>(g_agg + (size_t)row * 64 + c);
        s_in[r * 65 + c + 0] = v.x;
        s_in[r * 65 + c + 1] = v.y;
        s_in[r * 65 + c + 2] = v.z;
        s_in[r * 65 + c + 3] = v.w;
    }
    __syncthreads();

    // ---------- GEMM1 (FFMA2) ----------
    unsigned long long acc[4][4];
#pragma unroll
    for (int m = 0; m < 4; m++)
#pragma unroll
        for (int u = 0; u < 4; u++) acc[m][u] = 0ull;

#pragma unroll 4
    for (int k = 0; k < 64; k++) {
        const float* wrow = Ws + k * 64 + cg * 8;
        ulonglong2 wa = *reinterpret_cast<const ulonglong2*>(wrow);
        ulonglong2 wb = *reinterpret_cast<const ulonglong2*>(wrow + 4);
#pragma unroll
        for (int m = 0; m < 4; m++) {
            unsigned long long a2 = pack2(s_in[(rg + 16 * m) * 65 + k]);
            ffma2(acc[m][0], a2, wa.x);
            ffma2(acc[m][1], a2, wa.y);
            ffma2(acc[m][2], a2, wb.x);
            ffma2(acc[m][3], a2, wb.y);
        }
    }
    __syncthreads();

    // epilogue 1: BN affine + ELU, write back to s_in; swap Ws -> W2
#pragma unroll
    for (int m = 0; m < 4; m++) {
        int row = rg + 16 * m;
#pragma unroll
        for (int u = 0; u < 4; u++) {
            float2 p = unpack2(acc[m][u]);
            int j = cg * 8 + u * 2;
            float v0 = (p.x + sb1[j])     * ssc[j]     + sbe[j];
            float v1 = (p.y + sb1[j + 1]) * ssc[j + 1] + sbe[j + 1];
            s_in[row * 65 + j]     = elu(v0);
            s_in[row * 65 + j + 1] = elu(v1);
        }
    }
#pragma unroll
    for (int i = t; i < 1024; i += 128) Ws4[i] = W2_4[i];
    __syncthreads();

    // ---------- GEMM2 (FFMA2) ----------
#pragma unroll
    for (int m = 0; m < 4; m++)
#pragma unroll
        for (int u = 0; u < 4; u++) acc[m][u] = 0ull;

#pragma unroll 4
    for (int k = 0; k < 64; k++) {
        const float* wrow = Ws + k * 64 + cg * 8;
        ulonglong2 wa = *reinterpret_cast<const ulonglong2*>(wrow);
        ulonglong2 wb = *reinterpret_cast<const ulonglong2*>(wrow + 4);
#pragma unroll
        for (int m = 0; m < 4; m++) {
            unsigned long long a2 = pack2(s_in[(rg + 16 * m) * 65 + k]);
            ffma2(acc[m][0], a2, wa.x);
            ffma2(acc[m][1], a2, wa.y);
            ffma2(acc[m][2], a2, wb.x);
            ffma2(acc[m][3], a2, wb.y);
        }
    }

    // epilogue 2: bias + outer ELU, write h (fp32) + optional fp16 mirror
#pragma unroll
    for (int m = 0; m < 4; m++) {
        int row = base + rg + 16 * m;
        if (row < N_NODES) {
            float o[8];
#pragma unroll
            for (int u = 0; u < 4; u++) {
                float2 p = unpack2(acc[m][u]);
                int j = cg * 8 + u * 2;
                o[u * 2]     = elu(p.x + sb2[j]);
                o[u * 2 + 1] = elu(p.y + sb2[j + 1]);
            }
            float* orow = g_h + (size_t)row * 64 + cg * 8;
            *reinterpret_cast<float4*>(orow)     = make_float4(o[0], o[1], o[2], o[3]);
            *reinterpret_cast<float4*>(orow + 4) = make_float4(o[4], o[5], o[6], o[7]);

            if (write_fp16) {
                __half2 q0 = __floats2half2_rn(o[0], o[1]);
                __half2 q1 = __floats2half2_rn(o[2], o[3]);
                __half2 q2 = __floats2half2_rn(o[4], o[5]);
                __half2 q3 = __floats2half2_rn(o[6], o[7]);
                uint4 pk;
                pk.x = *reinterpret_cast<unsigned int*>(&q0);
                pk.y = *reinterpret_cast<unsigned int*>(&q1);
                pk.z = *reinterpret_cast<unsigned int*>(&q2);
                pk.w = *reinterpret_cast<unsigned int*>(&q3);
                *reinterpret_cast<uint4*>(g_hh + (size_t)row * 64 + cg * 8) = pk;
            }
        }
    }
}

// ---------------- mean pool (bounds inlined) ----------------
__global__ void k_pool(const int* __restrict__ batch) {
    int g = blockIdx.x;
    __shared__ int sbounds[2];
    if (threadIdx.x < 2) {
        int target = g + threadIdx.x;       // search for first batch[m] >= target
        int lo = 0, hi = N_NODES;
        while (lo < hi) {
            int mid = (lo + hi) >> 1;
            if (__ldg(batch + mid) < target) lo = mid + 1; else hi = mid;
        }
        sbounds[threadIdx.x] = lo;
    }
    __syncthreads();
    int start = sbounds[0], end = sbounds[1];

    int f = threadIdx.x & 63;
    int s = threadIdx.x >> 6;
    float acc = 0.f;
    for (int i = start + s; i < end; i += 4)
        acc += g_h[(size_t)i * 64 + f];
    __shared__ float red[256];
    red[threadIdx.x] = acc;
    __syncthreads();
    if (s == 0) {
        float v = red[f] + red[f + 64] + red[f + 128] + red[f + 192];
        float cnt = (float)(end - start);
        g_pooled[g * 64 + f] = v / fmaxf(cnt, 1.0f);
    }
}

// ---------------- head ----------------
__global__ void __launch_bounds__(64) k_head(
    const float* __restrict__ Wr1, const float* __restrict__ br1,
    const float* __restrict__ Wr2, const float* __restrict__ br2,
    const float* __restrict__ Wo,  const float* __restrict__ bo,
    float* __restrict__ out)
{
    __shared__ float Ws[64 * 64];
    __shared__ float s_p[64 * 65];
    __shared__ float sb[64];
    __shared__ float sWo[64];

    const int t = threadIdx.x;
    const int gbase = blockIdx.x * 64;

    sb[t]  = br1[t];
    sWo[t] = Wo[t];
#pragma unroll
    for (int i = t; i < 4096; i += 64) Ws[i] = Wr1[i];
#pragma unroll
    for (int i = 4 * t; i < 4096; i += 256) {
        int r = i >> 6, c = i & 63;
        float4 v = *reinterpret_cast<const float4*>(g_pooled + (size_t)(gbase + r) * 64 + c);
        s_p[r * 65 + c + 0] = v.x;
        s_p[r * 65 + c + 1] = v.y;
        s_p[r * 65 + c + 2] = v.z;
        s_p[r * 65 + c + 3] = v.w;
    }
    __syncthreads();

    const float* myrow = s_p + t * 65;
    float tt[64];

#pragma unroll
    for (int jt = 0; jt < 64; jt += 8) {
        float acc[8];
#pragma unroll
        for (int u = 0; u < 8; u++) acc[u] = 0.f;
#pragma unroll 4
        for (int k = 0; k < 64; k++) {
            float a = myrow[k];
            const float* w = Ws + k * 64 + jt;
            float4 w0 = *reinterpret_cast<const float4*>(w);
            float4 w1 = *reinterpret_cast<const float4*>(w + 4);
            acc[0] += a * w0.x; acc[1] += a * w0.y;
            acc[2] += a * w0.z; acc[3] += a * w0.w;
            acc[4] += a * w1.x; acc[5] += a * w1.y;
            acc[6] += a * w1.z; acc[7] += a * w1.w;
        }
#pragma unroll
        for (int u = 0; u < 8; u++) tt[jt + u] = elu(acc[u] + sb[jt + u]);
    }

#pragma unroll
    for (int j = 0; j < 64; j++) s_p[t * 65 + j] = tt[j];
    __syncthreads();
#pragma unroll
    for (int i = t; i < 4096; i += 64) Ws[i] = Wr2[i];
    sb[t] = br2[t];
    __syncthreads();

    float oacc = 0.f;
#pragma unroll
    for (int jt = 0; jt < 64; jt += 8) {
        float acc[8];
#pragma unroll
        for (int u = 0; u < 8; u++) acc[u] = 0.f;
#pragma unroll 4
        for (int k = 0; k < 64; k++) {
            float a = myrow[k];
            const float* w = Ws + k * 64 + jt;
            float4 w0 = *reinterpret_cast<const float4*>(w);
            float4 w1 = *reinterpret_cast<const float4*>(w + 4);
            acc[0] += a * w0.x; acc[1] += a * w0.y;
            acc[2] += a * w0.z; acc[3] += a * w0.w;
            acc[4] += a * w1.x; acc[5] += a * w1.y;
            acc[6] += a * w1.z; acc[7] += a * w1.w;
        }
#pragma unroll
        for (int u = 0; u < 8; u++)
            oacc += (acc[u] + sb[jt + u]) * sWo[jt + u];
    }
    out[gbase + t] = oacc + bo[0];
}

// ---------------- launcher ----------------
extern "C" void kernel_launch(void* const* d_in, const int* in_sizes, int n_in,
                              void* d_out, int out_size) {
    const int*   x     = (const int*)d_in[0];
    const int*   ei    = (const int*)d_in[1];
    const int*   batch = (const int*)d_in[2];
    const float* emb   = (const float*)d_in[3];
    const int* src = ei;
    const int* dst = ei + N_EDGES;
    float* out = (float*)d_out;

    const int TPB = 256;
    const int gnod = (N_NODES + TPB - 1) / TPB;
    const int gedg = (N_EDGES + TPB - 1) / TPB;
    const int gmlp = (N_NODES + 63) / 64;
    const int ggat = (N_NODES + 15) / 16;

    k_zero_cnt<<<gnod, TPB>>>();                       // launch 1
    k_fill<<<gedg, TPB>>>(src, dst);                   // launch 2

    for (int L = 0; L < 3; L++) {
        const float* W1  = (const float*)d_in[4 + 6 * L + 0];
        const float* b1  = (const float*)d_in[4 + 6 * L + 1];
        const float* gam = (const float*)d_in[4 + 6 * L + 2];
        const float* bet = (const float*)d_in[4 + 6 * L + 3];
        const float* W2  = (const float*)d_in[4 + 6 * L + 4];
        const float* b2  = (const float*)d_in[4 + 6 * L + 5];

        if (L == 0)
            k_gather1<<<ggat, 256>>>(x, emb);          // launch 3
        else
            k_gather<<<ggat, 256>>>();
        // launch 4 = k_mlp (layer 1) -> ncu capture slot
        k_mlp<<<gmlp, 128>>>(W1, b1, gam, bet, W2, b2, (L < 2) ? 1 : 0);
    }

    k_pool<<<N_GRAPHS, 256>>>(batch);
    k_head<<<2, 64>>>((const float*)d_in[22], (const float*)d_in[23],
                      (const float*)d_in[24], (const float*)d_in[25],
                      (const float*)d_in[26], (const float*)d_in[27],
                      out);
}

// round 8
// speedup vs baseline: 1.0282x; 1.0189x over previous
#include <cuda_runtime.h>
#include <cuda_bf16.h>
#include <cuda_fp16.h>
#include <math.h>

#define N_NODES 100000
#define N_EDGES 1200000
#define N_GRAPHS 128
#define MAX_DEG 64            // Poisson(12): P(deg>=64) ~ 1e-30, guarded anyway
#define SROW 66               // s_in row stride (floats): 8B-aligned, conflict-free

// ---------------- scratch ----------------
__device__ float  g_h[(size_t)N_NODES * 64];
__device__ __half g_hh[(size_t)N_NODES * 64];   // fp16 mirror for neighbor gather
__device__ float  g_agg[(size_t)N_NODES * 64];
__device__ float  g_pooled[N_GRAPHS * 64];

__device__ int g_cnt[N_NODES];
__device__ int g_adj[(size_t)N_NODES * MAX_DEG];

__device__ __forceinline__ float elu(float v) {
    return v > 0.f ? v : expm1f(v);
}

// ---- packed f32x2 helpers (sm_103a FFMA2) ----
__device__ __forceinline__ void ffma2(unsigned long long& d,
                                      unsigned long long a,
                                      unsigned long long b) {
    asm("fma.rn.f32x2 %0, %1, %2, %0;" : "+l"(d) : "l"(a), "l"(b));
}
__device__ __forceinline__ unsigned long long pack2(float x) {
    unsigned long long r;
    unsigned int u = __float_as_uint(x);
    asm("mov.b64 %0, {%1, %1};" : "=l"(r) : "r"(u));
    return r;
}
__device__ __forceinline__ float2 unpack2(unsigned long long p) {
    unsigned int lo, hi;
    asm("mov.b64 {%0, %1}, %2;" : "=r"(lo), "=r"(hi) : "l"(p));
    return make_float2(__uint_as_float(lo), __uint_as_float(hi));
}

// ---------------- adjacency build ----------------
__global__ void k_zero_cnt() {
    int i = blockIdx.x * blockDim.x + threadIdx.x;
    if (i < N_NODES) g_cnt[i] = 0;
}

__global__ void k_fill(const int* __restrict__ src, const int* __restrict__ dst) {
    int e = blockIdx.x * blockDim.x + threadIdx.x;
    if (e >= N_EDGES) return;
    int d = __ldg(dst + e);
    int slot = atomicAdd(&g_cnt[d], 1);
    if (slot < MAX_DEG)
        g_adj[(size_t)d * MAX_DEG + slot] = __ldg(src + e);
}

// ------- layer-1 gather straight from embedding: agg[n]=emb[x[n]]+sum emb[x[nb]]
__global__ void __launch_bounds__(256) k_gather1(const int* __restrict__ x,
                                                 const float* __restrict__ emb) {
    int t = threadIdx.x;
    int n = blockIdx.x * 16 + (t >> 4);
    int c = t & 15;
    if (n >= N_NODES) return;
    const float4* __restrict__ e4 = reinterpret_cast<const float4*>(emb);
    int xn = __ldg(x + n);
    float4 acc = e4[(size_t)xn * 16 + c];
    const int* __restrict__ alist = g_adj + (size_t)n * MAX_DEG;
    int e = min(g_cnt[n], MAX_DEG);
    for (int i = 0; i < e; i++) {
        int s = __ldg(alist + i);
        int xs = __ldg(x + s);
        float4 v = e4[(size_t)xs * 16 + c];
        acc.x += v.x; acc.y += v.y; acc.z += v.z; acc.w += v.w;
    }
    reinterpret_cast<float4*>(g_agg)[(size_t)n * 16 + c] = acc;
}

// ---------------- gather (layers 2-3): agg[n] = h_fp32[n] + sum h_fp16[nb] ---
__global__ void __launch_bounds__(256) k_gather() {
    int t = threadIdx.x;
    int n = blockIdx.x * 16 + (t >> 4);
    int c = t & 15;
    if (n >= N_NODES) return;
    float4 acc = reinterpret_cast<const float4*>(g_h)[(size_t)n * 16 + c];
    const int* __restrict__ alist = g_adj + (size_t)n * MAX_DEG;
    const uint2* __restrict__ hh2 = reinterpret_cast<const uint2*>(g_hh);
    int e = min(g_cnt[n], MAX_DEG);
    int nxt = (e > 0) ? __ldg(alist) : 0;
    for (int i = 0; i < e; i++) {
        int cur = nxt;
        if (i + 1 < e) nxt = __ldg(alist + i + 1);
        uint2 v = __ldg(&hh2[(size_t)cur * 16 + c]);
        float2 f0 = __half22float2(*reinterpret_cast<__half2*>(&v.x));
        float2 f1 = __half22float2(*reinterpret_cast<__half2*>(&v.y));
        acc.x += f0.x; acc.y += f0.y; acc.z += f1.x; acc.w += f1.y;
    }
    reinterpret_cast<float4*>(g_agg)[(size_t)n * 16 + c] = acc;
}

// ---------------- fused MLP+BN+ELU: h = elu(mlp_bn(agg)) ----------------
// 128 threads, 64-node tile. Thread (rg=t&15, cg=t>>4) computes rows
// {rg,rg+16,rg+32,rg+48} x cols {8cg..8cg+7}. f32x2 accumulators.
// k stepped by 2 with LDS.64 activation loads (SROW=66 keeps them conflict-free).
__global__ void __launch_bounds__(128) k_mlp(
    const float* __restrict__ W1, const float* __restrict__ b1,
    const float* __restrict__ gam, const float* __restrict__ bet,
    const float* __restrict__ W2, const float* __restrict__ b2,
    int write_fp16)
{
    __shared__ float Ws[64 * 64];
    __shared__ float s_in[64 * SROW];
    __shared__ float sb1[64], ssc[64], sbe[64], sb2[64];

    const int t = threadIdx.x;
    const int rg = t & 15;
    const int cg = t >> 4;
    const int base = blockIdx.x * 64;

    if (t < 64) {
        sb1[t] = b1[t];
        ssc[t] = gam[t] * rsqrtf(1.0f + 1e-5f);
        sbe[t] = bet[t];
        sb2[t] = b2[t];
    }
    float4* Ws4 = reinterpret_cast<float4*>(Ws);
    const float4* W1_4 = reinterpret_cast<const float4*>(W1);
    const float4* W2_4 = reinterpret_cast<const float4*>(W2);
#pragma unroll
    for (int i = t; i < 1024; i += 128) Ws4[i] = W1_4[i];

    // stage 64 input rows (coalesced: 16 float4 per row)
#pragma unroll
    for (int i = t; i < 1024; i += 128) {
        int r = i >> 4, c = (i & 15) << 2;
        int row = base + r;
        float4 v = make_float4(0.f, 0.f, 0.f, 0.f);
        if (row < N_NODES)
            v = *reinterpret_cast<const float4*>(g_agg + (size_t)row * 64 + c);
        float2* p = reinterpret_cast<float2*>(s_in + r * SROW + c);
        p[0] = make_float2(v.x, v.y);
        p[1] = make_float2(v.z, v.w);
    }
    __syncthreads();

    // ---------- GEMM1 ----------
    unsigned long long acc[4][4];
#pragma unroll
    for (int m = 0; m < 4; m++)
#pragma unroll
        for (int u = 0; u < 4; u++) acc[m][u] = 0ull;

#pragma unroll 4
    for (int k = 0; k < 64; k += 2) {
        const float* wr0 = Ws + k * 64 + cg * 8;
        const float* wr1 = wr0 + 64;
        ulonglong2 wa0 = *reinterpret_cast<const ulonglong2*>(wr0);
        ulonglong2 wb0 = *reinterpret_cast<const ulonglong2*>(wr0 + 4);
        ulonglong2 wa1 = *reinterpret_cast<const ulonglong2*>(wr1);
        ulonglong2 wb1 = *reinterpret_cast<const ulonglong2*>(wr1 + 4);
#pragma unroll
        for (int m = 0; m < 4; m++) {
            float2 av = *reinterpret_cast<const float2*>(s_in + (rg + 16 * m) * SROW + k);
            unsigned long long a0 = pack2(av.x);
            unsigned long long a1 = pack2(av.y);
            ffma2(acc[m][0], a0, wa0.x);
            ffma2(acc[m][1], a0, wa0.y);
            ffma2(acc[m][2], a0, wb0.x);
            ffma2(acc[m][3], a0, wb0.y);
            ffma2(acc[m][0], a1, wa1.x);
            ffma2(acc[m][1], a1, wa1.y);
            ffma2(acc[m][2], a1, wb1.x);
            ffma2(acc[m][3], a1, wb1.y);
        }
    }
    __syncthreads();

    // epilogue 1: BN affine + ELU, paired STS.64 back to s_in; swap Ws -> W2
#pragma unroll
    for (int m = 0; m < 4; m++) {
        int row = rg + 16 * m;
#pragma unroll
        for (int u = 0; u < 4; u++) {
            float2 p = unpack2(acc[m][u]);
            int j = cg * 8 + u * 2;
            float v0 = (p.x + sb1[j])     * ssc[j]     + sbe[j];
            float v1 = (p.y + sb1[j + 1]) * ssc[j + 1] + sbe[j + 1];
            *reinterpret_cast<float2*>(s_in + row * SROW + j) =
                make_float2(elu(v0), elu(v1));
        }
    }
#pragma unroll
    for (int i = t; i < 1024; i += 128) Ws4[i] = W2_4[i];
    __syncthreads();

    // ---------- GEMM2 ----------
#pragma unroll
    for (int m = 0; m < 4; m++)
#pragma unroll
        for (int u = 0; u < 4; u++) acc[m][u] = 0ull;

#pragma unroll 4
    for (int k = 0; k < 64; k += 2) {
        const float* wr0 = Ws + k * 64 + cg * 8;
        const float* wr1 = wr0 + 64;
        ulonglong2 wa0 = *reinterpret_cast<const ulonglong2*>(wr0);
        ulonglong2 wb0 = *reinterpret_cast<const ulonglong2*>(wr0 + 4);
        ulonglong2 wa1 = *reinterpret_cast<const ulonglong2*>(wr1);
        ulonglong2 wb1 = *reinterpret_cast<const ulonglong2*>(wr1 + 4);
#pragma unroll
        for (int m = 0; m < 4; m++) {
            float2 av = *reinterpret_cast<const float2*>(s_in + (rg + 16 * m) * SROW + k);
            unsigned long long a0 = pack2(av.x);
            unsigned long long a1 = pack2(av.y);
            ffma2(acc[m][0], a0, wa0.x);
            ffma2(acc[m][1], a0, wa0.y);
            ffma2(acc[m][2], a0, wb0.x);
            ffma2(acc[m][3], a0, wb0.y);
            ffma2(acc[m][0], a1, wa1.x);
            ffma2(acc[m][1], a1, wa1.y);
            ffma2(acc[m][2], a1, wb1.x);
            ffma2(acc[m][3], a1, wb1.y);
        }
    }

    // epilogue 2: bias + outer ELU, write h (fp32) + optional fp16 mirror
#pragma unroll
    for (int m = 0; m < 4; m++) {
        int row = base + rg + 16 * m;
        if (row < N_NODES) {
            float o[8];
#pragma unroll
            for (int u = 0; u < 4; u++) {
                float2 p = unpack2(acc[m][u]);
                int j = cg * 8 + u * 2;
                o[u * 2]     = elu(p.x + sb2[j]);
                o[u * 2 + 1] = elu(p.y + sb2[j + 1]);
            }
            float* orow = g_h + (size_t)row * 64 + cg * 8;
            *reinterpret_cast<float4*>(orow)     = make_float4(o[0], o[1], o[2], o[3]);
            *reinterpret_cast<float4*>(orow + 4) = make_float4(o[4], o[5], o[6], o[7]);

            if (write_fp16) {
                __half2 q0 = __floats2half2_rn(o[0], o[1]);
                __half2 q1 = __floats2half2_rn(o[2], o[3]);
                __half2 q2 = __floats2half2_rn(o[4], o[5]);
                __half2 q3 = __floats2half2_rn(o[6], o[7]);
                uint4 pk;
                pk.x = *reinterpret_cast<unsigned int*>(&q0);
                pk.y = *reinterpret_cast<unsigned int*>(&q1);
                pk.z = *reinterpret_cast<unsigned int*>(&q2);
                pk.w = *reinterpret_cast<unsigned int*>(&q3);
                *reinterpret_cast<uint4*>(g_hh + (size_t)row * 64 + cg * 8) = pk;
            }
        }
    }
}

// ---------------- mean pool (bounds inlined) ----------------
__global__ void k_pool(const int* __restrict__ batch) {
    int g = blockIdx.x;
    __shared__ int sbounds[2];
    if (threadIdx.x < 2) {
        int target = g + threadIdx.x;       // search for first batch[m] >= target
        int lo = 0, hi = N_NODES;
        while (lo < hi) {
            int mid = (lo + hi) >> 1;
            if (__ldg(batch + mid) < target) lo = mid + 1; else hi = mid;
        }
        sbounds[threadIdx.x] = lo;
    }
    __syncthreads();
    int start = sbounds[0], end = sbounds[1];

    int f = threadIdx.x & 63;
    int s = threadIdx.x >> 6;
    float acc = 0.f;
    for (int i = start + s; i < end; i += 4)
        acc += g_h[(size_t)i * 64 + f];
    __shared__ float red[256];
    red[threadIdx.x] = acc;
    __syncthreads();
    if (s == 0) {
        float v = red[f] + red[f + 64] + red[f + 128] + red[f + 192];
        float cnt = (float)(end - start);
        g_pooled[g * 64 + f] = v / fmaxf(cnt, 1.0f);
    }
}

// ---------------- head ----------------
__global__ void __launch_bounds__(64) k_head(
    const float* __restrict__ Wr1, const float* __restrict__ br1,
    const float* __restrict__ Wr2, const float* __restrict__ br2,
    const float* __restrict__ Wo,  const float* __restrict__ bo,
    float* __restrict__ out)
{
    __shared__ float Ws[64 * 64];
    __shared__ float s_p[64 * 65];
    __shared__ float sb[64];
    __shared__ float sWo[64];

    const int t = threadIdx.x;
    const int gbase = blockIdx.x * 64;

    sb[t]  = br1[t];
    sWo[t] = Wo[t];
#pragma unroll
    for (int i = t; i < 4096; i += 64) Ws[i] = Wr1[i];
#pragma unroll
    for (int i = 4 * t; i < 4096; i += 256) {
        int r = i >> 6, c = i & 63;
        float4 v = *reinterpret_cast<const float4*>(g_pooled + (size_t)(gbase + r) * 64 + c);
        s_p[r * 65 + c + 0] = v.x;
        s_p[r * 65 + c + 1] = v.y;
        s_p[r * 65 + c + 2] = v.z;
        s_p[r * 65 + c + 3] = v.w;
    }
    __syncthreads();

    const float* myrow = s_p + t * 65;
    float tt[64];

#pragma unroll
    for (int jt = 0; jt < 64; jt += 8) {
        float acc[8];
#pragma unroll
        for (int u = 0; u < 8; u++) acc[u] = 0.f;
#pragma unroll 4
        for (int k = 0; k < 64; k++) {
            float a = myrow[k];
            const float* w = Ws + k * 64 + jt;
            float4 w0 = *reinterpret_cast<const float4*>(w);
            float4 w1 = *reinterpret_cast<const float4*>(w + 4);
            acc[0] += a * w0.x; acc[1] += a * w0.y;
            acc[2] += a * w0.z; acc[3] += a * w0.w;
            acc[4] += a * w1.x; acc[5] += a * w1.y;
            acc[6] += a * w1.z; acc[7] += a * w1.w;
        }
#pragma unroll
        for (int u = 0; u < 8; u++) tt[jt + u] = elu(acc[u] + sb[jt + u]);
    }

#pragma unroll
    for (int j = 0; j < 64; j++) s_p[t * 65 + j] = tt[j];
    __syncthreads();
#pragma unroll
    for (int i = t; i < 4096; i += 64) Ws[i] = Wr2[i];
    sb[t] = br2[t];
    __syncthreads();

    float oacc = 0.f;
#pragma unroll
    for (int jt = 0; jt < 64; jt += 8) {
        float acc[8];
#pragma unroll
        for (int u = 0; u < 8; u++) acc[u] = 0.f;
#pragma unroll 4
        for (int k = 0; k < 64; k++) {
            float a = myrow[k];
            const float* w = Ws + k * 64 + jt;
            float4 w0 = *reinterpret_cast<const float4*>(w);
            float4 w1 = *reinterpret_cast<const float4*>(w + 4);
            acc[0] += a * w0.x; acc[1] += a * w0.y;
            acc[2] += a * w0.z; acc[3] += a * w0.w;
            acc[4] += a * w1.x; acc[5] += a * w1.y;
            acc[6] += a * w1.z; acc[7] += a * w1.w;
        }
#pragma unroll
        for (int u = 0; u < 8; u++)
            oacc += (acc[u] + sb[jt + u]) * sWo[jt + u];
    }
    out[gbase + t] = oacc + bo[0];
}

// ---------------- launcher ----------------
extern "C" void kernel_launch(void* const* d_in, const int* in_sizes, int n_in,
                              void* d_out, int out_size) {
    const int*   x     = (const int*)d_in[0];
    const int*   ei    = (const int*)d_in[1];
    const int*   batch = (const int*)d_in[2];
    const float* emb   = (const float*)d_in[3];
    const int* src = ei;
    const int* dst = ei + N_EDGES;
    float* out = (float*)d_out;

    const int TPB = 256;
    const int gnod = (N_NODES + TPB - 1) / TPB;
    const int gedg = (N_EDGES + TPB - 1) / TPB;
    const int gmlp = (N_NODES + 63) / 64;
    const int ggat = (N_NODES + 15) / 16;

    k_zero_cnt<<<gnod, TPB>>>();                       // launch 1
    k_fill<<<gedg, TPB>>>(src, dst);                   // launch 2

    for (int L = 0; L < 3; L++) {
        const float* W1  = (const float*)d_in[4 + 6 * L + 0];
        const float* b1  = (const float*)d_in[4 + 6 * L + 1];
        const float* gam = (const float*)d_in[4 + 6 * L + 2];
        const float* bet = (const float*)d_in[4 + 6 * L + 3];
        const float* W2  = (const float*)d_in[4 + 6 * L + 4];
        const float* b2  = (const float*)d_in[4 + 6 * L + 5];

        if (L == 0)
            k_gather1<<<ggat, 256>>>(x, emb);          // launch 3
        else
            k_gather<<<ggat, 256>>>();
        // launch 4 = k_mlp (layer 1) -> ncu capture slot
        k_mlp<<<gmlp, 128>>>(W1, b1, gam, bet, W2, b2, (L < 2) ? 1 : 0);
    }

    k_pool<<<N_GRAPHS, 256>>>(batch);
    k_head<<<2, 64>>>((const float*)d_in[22], (const float*)d_in[23],
                      (const float*)d_in[24], (const float*)d_in[25],
                      (const float*)d_in[26], (const float*)d_in[27],
                      out);
}

// round 10
// speedup vs baseline: 1.1319x; 1.1008x over previous
#include <cuda_runtime.h>
#include <cuda_bf16.h>
#include <cuda_fp16.h>
#include <math.h>

#define N_NODES 100000
#define N_EDGES 1200000
#define N_GRAPHS 128
#define MAX_DEG 64            // Poisson(12): P(deg>=64) ~ 1e-30, guarded anyway
#define AROW 72               // smem row stride in halves (144B): conflict-free fragments

// ---------------- scratch ----------------
__device__ float  g_h[(size_t)N_NODES * 64];
__device__ __half g_hh[(size_t)N_NODES * 64];   // fp16 mirror for neighbor gather
__device__ float  g_agg[(size_t)N_NODES * 64];
__device__ float  g_pooled[N_GRAPHS * 64];

__device__ int g_cnt[N_NODES];
__device__ int g_adj[(size_t)N_NODES * MAX_DEG];

__device__ __forceinline__ float elu(float v) {
    return v > 0.f ? v : expm1f(v);
}

// ---- HMMA m16n8k16 row.col f16f16f32 ----
__device__ __forceinline__ void mma16816(float* d,
    unsigned a0, unsigned a1, unsigned a2, unsigned a3,
    unsigned b0, unsigned b1)
{
    asm volatile(
        "mma.sync.aligned.m16n8k16.row.col.f32.f16.f16.f32 "
        "{%0,%1,%2,%3}, {%4,%5,%6,%7}, {%8,%9}, {%0,%1,%2,%3};"
        : "+f"(d[0]), "+f"(d[1]), "+f"(d[2]), "+f"(d[3])
        : "r"(a0), "r"(a1), "r"(a2), "r"(a3), "r"(b0), "r"(b1));
}

// split float into fp16 hi + fp16 lo (a ~= hi + lo)
__device__ __forceinline__ void split16(float a, __half& hi, __half& lo) {
    hi = __float2half_rn(a);
    lo = __float2half_rn(a - __half2float(hi));
}

// ---------------- adjacency build ----------------
__global__ void k_zero_cnt() {
    int i = blockIdx.x * blockDim.x + threadIdx.x;
    if (i < N_NODES) g_cnt[i] = 0;
}

__global__ void k_fill(const int* __restrict__ src, const int* __restrict__ dst) {
    int e = blockIdx.x * blockDim.x + threadIdx.x;
    if (e >= N_EDGES) return;
    int d = __ldg(dst + e);
    int slot = atomicAdd(&g_cnt[d], 1);
    if (slot < MAX_DEG)
        g_adj[(size_t)d * MAX_DEG + slot] = __ldg(src + e);
}

// ------- layer-1 gather straight from embedding: agg[n]=emb[x[n]]+sum emb[x[nb]]
__global__ void __launch_bounds__(256) k_gather1(const int* __restrict__ x,
                                                 const float* __restrict__ emb) {
    int t = threadIdx.x;
    int n = blockIdx.x * 16 + (t >> 4);
    int c = t & 15;
    if (n >= N_NODES) return;
    const float4* __restrict__ e4 = reinterpret_cast<const float4*>(emb);
    int xn = __ldg(x + n);
    float4 acc = e4[(size_t)xn * 16 + c];
    const int* __restrict__ alist = g_adj + (size_t)n * MAX_DEG;
    int e = min(g_cnt[n], MAX_DEG);
    for (int i = 0; i < e; i++) {
        int s = __ldg(alist + i);
        int xs = __ldg(x + s);
        float4 v = e4[(size_t)xs * 16 + c];
        acc.x += v.x; acc.y += v.y; acc.z += v.z; acc.w += v.w;
    }
    reinterpret_cast<float4*>(g_agg)[(size_t)n * 16 + c] = acc;
}

// ---------------- gather (layers 2-3): agg[n] = h_fp32[n] + sum h_fp16[nb] ---
__global__ void __launch_bounds__(256) k_gather() {
    int t = threadIdx.x;
    int n = blockIdx.x * 16 + (t >> 4);
    int c = t & 15;
    if (n >= N_NODES) return;
    float4 acc = reinterpret_cast<const float4*>(g_h)[(size_t)n * 16 + c];
    const int* __restrict__ alist = g_adj + (size_t)n * MAX_DEG;
    const uint2* __restrict__ hh2 = reinterpret_cast<const uint2*>(g_hh);
    int e = min(g_cnt[n], MAX_DEG);
    int nxt = (e > 0) ? __ldg(alist) : 0;
    for (int i = 0; i < e; i++) {
        int cur = nxt;
        if (i + 1 < e) nxt = __ldg(alist + i + 1);
        uint2 v = __ldg(&hh2[(size_t)cur * 16 + c]);
        float2 f0 = __half22float2(*reinterpret_cast<__half2*>(&v.x));
        float2 f1 = __half22float2(*reinterpret_cast<__half2*>(&v.y));
        acc.x += f0.x; acc.y += f0.y; acc.z += f1.x; acc.w += f1.y;
    }
    reinterpret_cast<float4*>(g_agg)[(size_t)n * 16 + c] = acc;
}

// ---------------- fused MLP+BN+ELU via split-fp16 HMMA ----------------------
// 128 threads = 4 warps; warp w owns rows 16w..16w+15 of the 64-node tile.
// Operands split into fp16 hi+lo; per n-block 3 MMAs: ah*bh + ah*bl + al*bh.
// Dropped al*bl term ~ 2^-22 relative -> fp32-grade accuracy on tensor cores.
__global__ void __launch_bounds__(128) k_mlp(
    const float* __restrict__ W1, const float* __restrict__ b1,
    const float* __restrict__ gam, const float* __restrict__ bet,
    const float* __restrict__ W2, const float* __restrict__ b2,
    int write_fp16)
{
    __shared__ __half sAh[64 * AROW];
    __shared__ __half sAl[64 * AROW];
    __shared__ __half sWh[64 * AROW];
    __shared__ __half sWl[64 * AROW];
    __shared__ float sb1[64], ssc[64], sbe[64], sb2[64];

    const int t = threadIdx.x;
    const int w = t >> 5;
    const int lane = t & 31;
    const int g = lane >> 2;       // 0..7
    const int tq = lane & 3;       // 0..3
    const int base = blockIdx.x * 64;

    if (t < 64) {
        sb1[t] = b1[t];
        ssc[t] = gam[t] * rsqrtf(1.0f + 1e-5f);
        sbe[t] = bet[t];
        sb2[t] = b2[t];
    }

    // stage W1^T split: sW{h,l}[n][k] = split(W1[k][n])
    for (int i = t; i < 4096; i += 128) {
        int k = i >> 6, n = i & 63;
        __half hi, lo;
        split16(__ldg(W1 + i), hi, lo);
        sWh[n * AROW + k] = hi;
        sWl[n * AROW + k] = lo;
    }
    // stage activations split (coalesced float4 reads)
    for (int i = t; i < 1024; i += 128) {
        int r = i >> 4, c = (i & 15) << 2;
        int row = base + r;
        float4 v = make_float4(0.f, 0.f, 0.f, 0.f);
        if (row < N_NODES)
            v = *reinterpret_cast<const float4*>(g_agg + (size_t)row * 64 + c);
        __half hx, lx, hy, ly, hz, lz, hw, lw;
        split16(v.x, hx, lx); split16(v.y, hy, ly);
        split16(v.z, hz, lz); split16(v.w, hw, lw);
        __half2* ph = reinterpret_cast<__half2*>(sAh + r * AROW + c);
        __half2* pl = reinterpret_cast<__half2*>(sAl + r * AROW + c);
        ph[0] = __halves2half2(hx, hy); ph[1] = __halves2half2(hz, hw);
        pl[0] = __halves2half2(lx, ly); pl[1] = __halves2half2(lz, lw);
    }
    __syncthreads();

    const int r0 = 16 * w + g;          // local row (first half)

    float acc[8][4];
#pragma unroll
    for (int nb = 0; nb < 8; nb++)
#pragma unroll
        for (int u = 0; u < 4; u++) acc[nb][u] = 0.f;

    // ---------- GEMM1 (split HMMA) ----------
#pragma unroll
    for (int kb = 0; kb < 4; kb++) {
        int ko = kb * 16 + 2 * tq;
        const __half* ah0p = sAh + r0 * AROW + ko;
        const __half* ah1p = sAh + (r0 + 8) * AROW + ko;
        const __half* al0p = sAl + r0 * AROW + ko;
        const __half* al1p = sAl + (r0 + 8) * AROW + ko;
        unsigned ah0 = *reinterpret_cast<const unsigned*>(ah0p);
        unsigned ah1 = *reinterpret_cast<const unsigned*>(ah1p);
        unsigned ah2 = *reinterpret_cast<const unsigned*>(ah0p + 8);
        unsigned ah3 = *reinterpret_cast<const unsigned*>(ah1p + 8);
        unsigned al0 = *reinterpret_cast<const unsigned*>(al0p);
        unsigned al1 = *reinterpret_cast<const unsigned*>(al1p);
        unsigned al2 = *reinterpret_cast<const unsigned*>(al0p + 8);
        unsigned al3 = *reinterpret_cast<const unsigned*>(al1p + 8);
#pragma unroll
        for (int nb = 0; nb < 8; nb++) {
            int boff = (8 * nb + g) * AROW + ko;
            unsigned bh0 = *reinterpret_cast<const unsigned*>(sWh + boff);
            unsigned bh1 = *reinterpret_cast<const unsigned*>(sWh + boff + 8);
            unsigned bl0 = *reinterpret_cast<const unsigned*>(sWl + boff);
            unsigned bl1 = *reinterpret_cast<const unsigned*>(sWl + boff + 8);
            mma16816(acc[nb], ah0, ah1, ah2, ah3, bh0, bh1);
            mma16816(acc[nb], ah0, ah1, ah2, ah3, bl0, bl1);
            mma16816(acc[nb], al0, al1, al2, al3, bh0, bh1);
        }
    }

    // epilogue 1: BN affine + ELU -> own rows, split fp16
#pragma unroll
    for (int nb = 0; nb < 8; nb++) {
        int j = 8 * nb + 2 * tq;
        float2 bv = *reinterpret_cast<const float2*>(&sb1[j]);
        float2 sv = *reinterpret_cast<const float2*>(&ssc[j]);
        float2 ev = *reinterpret_cast<const float2*>(&sbe[j]);
        float v00 = elu((acc[nb][0] + bv.x) * sv.x + ev.x);
        float v01 = elu((acc[nb][1] + bv.y) * sv.y + ev.y);
        float v10 = elu((acc[nb][2] + bv.x) * sv.x + ev.x);
        float v11 = elu((acc[nb][3] + bv.y) * sv.y + ev.y);
        __half h00, l00, h01, l01, h10, l10, h11, l11;
        split16(v00, h00, l00); split16(v01, h01, l01);
        split16(v10, h10, l10); split16(v11, h11, l11);
        *reinterpret_cast<__half2*>(sAh + r0 * AROW + j)       = __halves2half2(h00, h01);
        *reinterpret_cast<__half2*>(sAl + r0 * AROW + j)       = __halves2half2(l00, l01);
        *reinterpret_cast<__half2*>(sAh + (r0 + 8) * AROW + j) = __halves2half2(h10, h11);
        *reinterpret_cast<__half2*>(sAl + (r0 + 8) * AROW + j) = __halves2half2(l10, l11);
    }
    __syncthreads();   // all warps done reading W1 tiles

    // stage W2^T split
    for (int i = t; i < 4096; i += 128) {
        int k = i >> 6, n = i & 63;
        __half hi, lo;
        split16(__ldg(W2 + i), hi, lo);
        sWh[n * AROW + k] = hi;
        sWl[n * AROW + k] = lo;
    }
    __syncthreads();

#pragma unroll
    for (int nb = 0; nb < 8; nb++)
#pragma unroll
        for (int u = 0; u < 4; u++) acc[nb][u] = 0.f;

    // ---------- GEMM2 (split HMMA) ----------
#pragma unroll
    for (int kb = 0; kb < 4; kb++) {
        int ko = kb * 16 + 2 * tq;
        const __half* ah0p = sAh + r0 * AROW + ko;
        const __half* ah1p = sAh + (r0 + 8) * AROW + ko;
        const __half* al0p = sAl + r0 * AROW + ko;
        const __half* al1p = sAl + (r0 + 8) * AROW + ko;
        unsigned ah0 = *reinterpret_cast<const unsigned*>(ah0p);
        unsigned ah1 = *reinterpret_cast<const unsigned*>(ah1p);
        unsigned ah2 = *reinterpret_cast<const unsigned*>(ah0p + 8);
        unsigned ah3 = *reinterpret_cast<const unsigned*>(ah1p + 8);
        unsigned al0 = *reinterpret_cast<const unsigned*>(al0p);
        unsigned al1 = *reinterpret_cast<const unsigned*>(al1p);
        unsigned al2 = *reinterpret_cast<const unsigned*>(al0p + 8);
        unsigned al3 = *reinterpret_cast<const unsigned*>(al1p + 8);
#pragma unroll
        for (int nb = 0; nb < 8; nb++) {
            int boff = (8 * nb + g) * AROW + ko;
            unsigned bh0 = *reinterpret_cast<const unsigned*>(sWh + boff);
            unsigned bh1 = *reinterpret_cast<const unsigned*>(sWh + boff + 8);
            unsigned bl0 = *reinterpret_cast<const unsigned*>(sWl + boff);
            unsigned bl1 = *reinterpret_cast<const unsigned*>(sWl + boff + 8);
            mma16816(acc[nb], ah0, ah1, ah2, ah3, bh0, bh1);
            mma16816(acc[nb], ah0, ah1, ah2, ah3, bl0, bl1);
            mma16816(acc[nb], al0, al1, al2, al3, bh0, bh1);
        }
    }

    // epilogue 2: bias + outer ELU -> g_h fp32 (+ optional fp16 mirror)
    int grow0 = base + r0;
    int grow1 = grow0 + 8;
#pragma unroll
    for (int nb = 0; nb < 8; nb++) {
        int j = 8 * nb + 2 * tq;
        float2 bv = *reinterpret_cast<const float2*>(&sb2[j]);
        float o00 = elu(acc[nb][0] + bv.x);
        float o01 = elu(acc[nb][1] + bv.y);
        float o10 = elu(acc[nb][2] + bv.x);
        float o11 = elu(acc[nb][3] + bv.y);
        if (grow0 < N_NODES) {
            *reinterpret_cast<float2*>(g_h + (size_t)grow0 * 64 + j) = make_float2(o00, o01);
            if (write_fp16)
                *reinterpret_cast<__half2*>(g_hh + (size_t)grow0 * 64 + j) = __floats2half2_rn(o00, o01);
        }
        if (grow1 < N_NODES) {
            *reinterpret_cast<float2*>(g_h + (size_t)grow1 * 64 + j) = make_float2(o10, o11);
            if (write_fp16)
                *reinterpret_cast<__half2*>(g_hh + (size_t)grow1 * 64 + j) = __floats2half2_rn(o10, o11);
        }
    }
}

// ---------------- mean pool (bounds inlined) ----------------
__global__ void k_pool(const int* __restrict__ batch) {
    int g = blockIdx.x;
    __shared__ int sbounds[2];
    if (threadIdx.x < 2) {
        int target = g + threadIdx.x;       // first batch[m] >= target
        int lo = 0, hi = N_NODES;
        while (lo < hi) {
            int mid = (lo + hi) >> 1;
            if (__ldg(batch + mid) < target) lo = mid + 1; else hi = mid;
        }
        sbounds[threadIdx.x] = lo;
    }
    __syncthreads();
    int start = sbounds[0], end = sbounds[1];

    int f = threadIdx.x & 63;
    int s = threadIdx.x >> 6;
    float acc = 0.f;
    for (int i = start + s; i < end; i += 4)
        acc += g_h[(size_t)i * 64 + f];
    __shared__ float red[256];
    red[threadIdx.x] = acc;
    __syncthreads();
    if (s == 0) {
        float v = red[f] + red[f + 64] + red[f + 128] + red[f + 192];
        float cnt = (float)(end - start);
        g_pooled[g * 64 + f] = v / fmaxf(cnt, 1.0f);
    }
}

// ---------------- head ----------------
__global__ void __launch_bounds__(64) k_head(
    const float* __restrict__ Wr1, const float* __restrict__ br1,
    const float* __restrict__ Wr2, const float* __restrict__ br2,
    const float* __restrict__ Wo,  const float* __restrict__ bo,
    float* __restrict__ out)
{
    __shared__ float Ws[64 * 64];
    __shared__ float s_p[64 * 65];
    __shared__ float sb[64];
    __shared__ float sWo[64];

    const int t = threadIdx.x;
    const int gbase = blockIdx.x * 64;

    sb[t]  = br1[t];
    sWo[t] = Wo[t];
#pragma unroll
    for (int i = t; i < 4096; i += 64) Ws[i] = Wr1[i];
#pragma unroll
    for (int i = 4 * t; i < 4096; i += 256) {
        int r = i >> 6, c = i & 63;
        float4 v = *reinterpret_cast<const float4*>(g_pooled + (size_t)(gbase + r) * 64 + c);
        s_p[r * 65 + c + 0] = v.x;
        s_p[r * 65 + c + 1] = v.y;
        s_p[r * 65 + c + 2] = v.z;
        s_p[r * 65 + c + 3] = v.w;
    }
    __syncthreads();

    const float* myrow = s_p + t * 65;
    float tt[64];

#pragma unroll
    for (int jt = 0; jt < 64; jt += 8) {
        float acc[8];
#pragma unroll
        for (int u = 0; u < 8; u++) acc[u] = 0.f;
#pragma unroll 4
        for (int k = 0; k < 64; k++) {
            float a = myrow[k];
            const float* w = Ws + k * 64 + jt;
            float4 w0 = *reinterpret_cast<const float4*>(w);
            float4 w1 = *reinterpret_cast<const float4*>(w + 4);
            acc[0] += a * w0.x; acc[1] += a * w0.y;
            acc[2] += a * w0.z; acc[3] += a * w0.w;
            acc[4] += a * w1.x; acc[5] += a * w1.y;
            acc[6] += a * w1.z; acc[7] += a * w1.w;
        }
#pragma unroll
        for (int u = 0; u < 8; u++) tt[jt + u] = elu(acc[u] + sb[jt + u]);
    }

#pragma unroll
    for (int j = 0; j < 64; j++) s_p[t * 65 + j] = tt[j];
    __syncthreads();
#pragma unroll
    for (int i = t; i < 4096; i += 64) Ws[i] = Wr2[i];
    sb[t] = br2[t];
    __syncthreads();

    float oacc = 0.f;
#pragma unroll
    for (int jt = 0; jt < 64; jt += 8) {
        float acc[8];
#pragma unroll
        for (int u = 0; u < 8; u++) acc[u] = 0.f;
#pragma unroll 4
        for (int k = 0; k < 64; k++) {
            float a = myrow[k];
            const float* w = Ws + k * 64 + jt;
            float4 w0 = *reinterpret_cast<const float4*>(w);
            float4 w1 = *reinterpret_cast<const float4*>(w + 4);
            acc[0] += a * w0.x; acc[1] += a * w0.y;
            acc[2] += a * w0.z; acc[3] += a * w0.w;
            acc[4] += a * w1.x; acc[5] += a * w1.y;
            acc[6] += a * w1.z; acc[7] += a * w1.w;
        }
#pragma unroll
        for (int u = 0; u < 8; u++)
            oacc += (acc[u] + sb[jt + u]) * sWo[jt + u];
    }
    out[gbase + t] = oacc + bo[0];
}

// ---------------- launcher ----------------
extern "C" void kernel_launch(void* const* d_in, const int* in_sizes, int n_in,
                              void* d_out, int out_size) {
    const int*   x     = (const int*)d_in[0];
    const int*   ei    = (const int*)d_in[1];
    const int*   batch = (const int*)d_in[2];
    const float* emb   = (const float*)d_in[3];
    const int* src = ei;
    const int* dst = ei + N_EDGES;
    float* out = (float*)d_out;

    const int TPB = 256;
    const int gnod = (N_NODES + TPB - 1) / TPB;
    const int gedg = (N_EDGES + TPB - 1) / TPB;
    const int gmlp = (N_NODES + 63) / 64;
    const int ggat = (N_NODES + 15) / 16;

    k_zero_cnt<<<gnod, TPB>>>();                       // launch 1
    k_fill<<<gedg, TPB>>>(src, dst);                   // launch 2

    for (int L = 0; L < 3; L++) {
        const float* W1  = (const float*)d_in[4 + 6 * L + 0];
        const float* b1  = (const float*)d_in[4 + 6 * L + 1];
        const float* gam = (const float*)d_in[4 + 6 * L + 2];
        const float* bet = (const float*)d_in[4 + 6 * L + 3];
        const float* W2  = (const float*)d_in[4 + 6 * L + 4];
        const float* b2  = (const float*)d_in[4 + 6 * L + 5];

        if (L == 0)
            k_gather1<<<ggat, 256>>>(x, emb);          // launch 3
        else
            k_gather<<<ggat, 256>>>();
        // launch 4 = k_mlp (layer 1) -> ncu capture slot
        k_mlp<<<gmlp, 128>>>(W1, b1, gam, bet, W2, b2, (L < 2) ? 1 : 0);
    }

    k_pool<<<N_GRAPHS, 256>>>(batch);
    k_head<<<2, 64>>>((const float*)d_in[22], (const float*)d_in[23],
                      (const float*)d_in[24], (const float*)d_in[25],
                      (const float*)d_in[26], (const float*)d_in[27],
                      out);
}

// round 11
// speedup vs baseline: 1.2574x; 1.1109x over previous
#include <cuda_runtime.h>
#include <cuda_bf16.h>
#include <cuda_fp16.h>
#include <math.h>

#define N_NODES 100000
#define N_EDGES 1200000
#define N_GRAPHS 128
#define MAX_DEG 64            // Poisson(12): P(deg>=64) ~ 1e-30, guarded anyway
#define AROW 72               // smem row stride in halves (144B): conflict-free fragments

// ---------------- scratch ----------------
__device__ float  g_h[(size_t)N_NODES * 64];
__device__ __half g_hh[(size_t)N_NODES * 64];   // fp16 mirror for neighbor gather
__device__ float  g_agg[(size_t)N_NODES * 64];
__device__ float  g_pooled[N_GRAPHS * 64];

__device__ int g_cnt[N_NODES];
__device__ int g_adj[(size_t)N_NODES * MAX_DEG];

// pre-split transposed weights: [matrix][n*64+k], matrices 2L=W1, 2L+1=W2
__device__ __align__(16) __half g_wh[6 * 4096];
__device__ __align__(16) __half g_wl[6 * 4096];

__device__ __forceinline__ float elu(float v) {
    return v > 0.f ? v : expm1f(v);
}

// ---- HMMA m16n8k16 row.col f16f16f32 ----
__device__ __forceinline__ void mma16816(float* d,
    unsigned a0, unsigned a1, unsigned a2, unsigned a3,
    unsigned b0, unsigned b1)
{
    asm volatile(
        "mma.sync.aligned.m16n8k16.row.col.f32.f16.f16.f32 "
        "{%0,%1,%2,%3}, {%4,%5,%6,%7}, {%8,%9}, {%0,%1,%2,%3};"
        : "+f"(d[0]), "+f"(d[1]), "+f"(d[2]), "+f"(d[3])
        : "r"(a0), "r"(a1), "r"(a2), "r"(a3), "r"(b0), "r"(b1));
}

// split float into fp16 hi + fp16 lo (a ~= hi + lo)
__device__ __forceinline__ void split16(float a, __half& hi, __half& lo) {
    hi = __float2half_rn(a);
    lo = __float2half_rn(a - __half2float(hi));
}

// ------- weight pre-split (once per launch) + g_cnt zeroing, merged ---------
__global__ void k_split_zero(const float* __restrict__ w0, const float* __restrict__ w1,
                             const float* __restrict__ w2, const float* __restrict__ w3,
                             const float* __restrict__ w4, const float* __restrict__ w5)
{
    int i = blockIdx.x * blockDim.x + threadIdx.x;
    if (i < N_NODES) g_cnt[i] = 0;
    if (i < 6 * 4096) {
        int m = i >> 12, j = i & 4095;
        const float* W;
        switch (m) {
            case 0: W = w0; break;
            case 1: W = w1; break;
            case 2: W = w2; break;
            case 3: W = w3; break;
            case 4: W = w4; break;
            default: W = w5; break;
        }
        float v = __ldg(W + j);
        int k = j >> 6, n = j & 63;           // W[k][n] -> Wt[n][k]
        __half hi, lo;
        split16(v, hi, lo);
        g_wh[m * 4096 + n * 64 + k] = hi;
        g_wl[m * 4096 + n * 64 + k] = lo;
    }
}

__global__ void k_fill(const int* __restrict__ src, const int* __restrict__ dst) {
    int e = blockIdx.x * blockDim.x + threadIdx.x;
    if (e >= N_EDGES) return;
    int d = __ldg(dst + e);
    int slot = atomicAdd(&g_cnt[d], 1);
    if (slot < MAX_DEG)
        g_adj[(size_t)d * MAX_DEG + slot] = __ldg(src + e);
}

// ------- layer-1 gather straight from embedding: agg[n]=emb[x[n]]+sum emb[x[nb]]
__global__ void __launch_bounds__(256) k_gather1(const int* __restrict__ x,
                                                 const float* __restrict__ emb) {
    int t = threadIdx.x;
    int n = blockIdx.x * 16 + (t >> 4);
    int c = t & 15;
    if (n >= N_NODES) return;
    const float4* __restrict__ e4 = reinterpret_cast<const float4*>(emb);
    int xn = __ldg(x + n);
    float4 acc = e4[(size_t)xn * 16 + c];
    const int* __restrict__ alist = g_adj + (size_t)n * MAX_DEG;
    int e = min(g_cnt[n], MAX_DEG);
    for (int i = 0; i < e; i++) {
        int s = __ldg(alist + i);
        int xs = __ldg(x + s);
        float4 v = e4[(size_t)xs * 16 + c];
        acc.x += v.x; acc.y += v.y; acc.z += v.z; acc.w += v.w;
    }
    reinterpret_cast<float4*>(g_agg)[(size_t)n * 16 + c] = acc;
}

// ---------------- gather (layers 2-3): agg[n] = h_fp32[n] + sum h_fp16[nb] ---
__global__ void __launch_bounds__(256) k_gather() {
    int t = threadIdx.x;
    int n = blockIdx.x * 16 + (t >> 4);
    int c = t & 15;
    if (n >= N_NODES) return;
    float4 acc = reinterpret_cast<const float4*>(g_h)[(size_t)n * 16 + c];
    const int* __restrict__ alist = g_adj + (size_t)n * MAX_DEG;
    const uint2* __restrict__ hh2 = reinterpret_cast<const uint2*>(g_hh);
    int e = min(g_cnt[n], MAX_DEG);
    int nxt = (e > 0) ? __ldg(alist) : 0;
    for (int i = 0; i < e; i++) {
        int cur = nxt;
        if (i + 1 < e) nxt = __ldg(alist + i + 1);
        uint2 v = __ldg(&hh2[(size_t)cur * 16 + c]);
        float2 f0 = __half22float2(*reinterpret_cast<__half2*>(&v.x));
        float2 f1 = __half22float2(*reinterpret_cast<__half2*>(&v.y));
        acc.x += f0.x; acc.y += f0.y; acc.z += f1.x; acc.w += f1.y;
    }
    reinterpret_cast<float4*>(g_agg)[(size_t)n * 16 + c] = acc;
}

// ---------------- fused MLP+BN+ELU via split-fp16 HMMA ----------------------
// 128 threads = 4 warps; warp w owns rows 16w..16w+15 of the 64-node tile.
// Weights arrive pre-split/pre-transposed in g_wh/g_wl -> staging is pure copy.
__global__ void __launch_bounds__(128) k_mlp(
    int widx,
    const float* __restrict__ b1,
    const float* __restrict__ gam, const float* __restrict__ bet,
    const float* __restrict__ b2,
    int write_fp16)
{
    __shared__ __half sAh[64 * AROW];
    __shared__ __half sAl[64 * AROW];
    __shared__ __half sWh[64 * AROW];
    __shared__ __half sWl[64 * AROW];
    __shared__ float sb1[64], ssc[64], sbe[64], sb2[64];

    const int t = threadIdx.x;
    const int w = t >> 5;
    const int lane = t & 31;
    const int g = lane >> 2;       // 0..7
    const int tq = lane & 3;       // 0..3
    const int base = blockIdx.x * 64;

    if (t < 64) {
        sb1[t] = b1[t];
        ssc[t] = gam[t] * rsqrtf(1.0f + 1e-5f);
        sbe[t] = bet[t];
        sb2[t] = b2[t];
    }

    // stage W1^T hi/lo: pure vectorized copy (8 halves per uint4)
    {
        const uint4* s1h = reinterpret_cast<const uint4*>(g_wh + (size_t)widx * 4096);
        const uint4* s1l = reinterpret_cast<const uint4*>(g_wl + (size_t)widx * 4096);
#pragma unroll
        for (int i = t; i < 512; i += 128) {
            int n = i >> 3, kc = i & 7;
            *reinterpret_cast<uint4*>(sWh + n * AROW + kc * 8) = s1h[i];
            *reinterpret_cast<uint4*>(sWl + n * AROW + kc * 8) = s1l[i];
        }
    }
    // stage activations split (coalesced float4 reads)
    for (int i = t; i < 1024; i += 128) {
        int r = i >> 4, c = (i & 15) << 2;
        int row = base + r;
        float4 v = make_float4(0.f, 0.f, 0.f, 0.f);
        if (row < N_NODES)
            v = *reinterpret_cast<const float4*>(g_agg + (size_t)row * 64 + c);
        __half hx, lx, hy, ly, hz, lz, hw, lw;
        split16(v.x, hx, lx); split16(v.y, hy, ly);
        split16(v.z, hz, lz); split16(v.w, hw, lw);
        __half2* ph = reinterpret_cast<__half2*>(sAh + r * AROW + c);
        __half2* pl = reinterpret_cast<__half2*>(sAl + r * AROW + c);
        ph[0] = __halves2half2(hx, hy); ph[1] = __halves2half2(hz, hw);
        pl[0] = __halves2half2(lx, ly); pl[1] = __halves2half2(lz, lw);
    }
    __syncthreads();

    const int r0 = 16 * w + g;          // local row (first half)

    float acc[8][4];
#pragma unroll
    for (int nb = 0; nb < 8; nb++)
#pragma unroll
        for (int u = 0; u < 4; u++) acc[nb][u] = 0.f;

    // ---------- GEMM1 (split HMMA) ----------
#pragma unroll
    for (int kb = 0; kb < 4; kb++) {
        int ko = kb * 16 + 2 * tq;
        const __half* ah0p = sAh + r0 * AROW + ko;
        const __half* ah1p = sAh + (r0 + 8) * AROW + ko;
        const __half* al0p = sAl + r0 * AROW + ko;
        const __half* al1p = sAl + (r0 + 8) * AROW + ko;
        unsigned ah0 = *reinterpret_cast<const unsigned*>(ah0p);
        unsigned ah1 = *reinterpret_cast<const unsigned*>(ah1p);
        unsigned ah2 = *reinterpret_cast<const unsigned*>(ah0p + 8);
        unsigned ah3 = *reinterpret_cast<const unsigned*>(ah1p + 8);
        unsigned al0 = *reinterpret_cast<const unsigned*>(al0p);
        unsigned al1 = *reinterpret_cast<const unsigned*>(al1p);
        unsigned al2 = *reinterpret_cast<const unsigned*>(al0p + 8);
        unsigned al3 = *reinterpret_cast<const unsigned*>(al1p + 8);
#pragma unroll
        for (int nb = 0; nb < 8; nb++) {
            int boff = (8 * nb + g) * AROW + ko;
            unsigned bh0 = *reinterpret_cast<const unsigned*>(sWh + boff);
            unsigned bh1 = *reinterpret_cast<const unsigned*>(sWh + boff + 8);
            unsigned bl0 = *reinterpret_cast<const unsigned*>(sWl + boff);
            unsigned bl1 = *reinterpret_cast<const unsigned*>(sWl + boff + 8);
            mma16816(acc[nb], ah0, ah1, ah2, ah3, bh0, bh1);
            mma16816(acc[nb], ah0, ah1, ah2, ah3, bl0, bl1);
            mma16816(acc[nb], al0, al1, al2, al3, bh0, bh1);
        }
    }

    // epilogue 1: BN affine + ELU -> own rows, split fp16
#pragma unroll
    for (int nb = 0; nb < 8; nb++) {
        int j = 8 * nb + 2 * tq;
        float2 bv = *reinterpret_cast<const float2*>(&sb1[j]);
        float2 sv = *reinterpret_cast<const float2*>(&ssc[j]);
        float2 ev = *reinterpret_cast<const float2*>(&sbe[j]);
        float v00 = elu((acc[nb][0] + bv.x) * sv.x + ev.x);
        float v01 = elu((acc[nb][1] + bv.y) * sv.y + ev.y);
        float v10 = elu((acc[nb][2] + bv.x) * sv.x + ev.x);
        float v11 = elu((acc[nb][3] + bv.y) * sv.y + ev.y);
        __half h00, l00, h01, l01, h10, l10, h11, l11;
        split16(v00, h00, l00); split16(v01, h01, l01);
        split16(v10, h10, l10); split16(v11, h11, l11);
        *reinterpret_cast<__half2*>(sAh + r0 * AROW + j)       = __halves2half2(h00, h01);
        *reinterpret_cast<__half2*>(sAl + r0 * AROW + j)       = __halves2half2(l00, l01);
        *reinterpret_cast<__half2*>(sAh + (r0 + 8) * AROW + j) = __halves2half2(h10, h11);
        *reinterpret_cast<__half2*>(sAl + (r0 + 8) * AROW + j) = __halves2half2(l10, l11);
    }
    __syncthreads();   // all warps done reading W1 tiles

    // stage W2^T hi/lo (pure copy)
    {
        const uint4* s2h = reinterpret_cast<const uint4*>(g_wh + (size_t)(widx + 1) * 4096);
        const uint4* s2l = reinterpret_cast<const uint4*>(g_wl + (size_t)(widx + 1) * 4096);
#pragma unroll
        for (int i = t; i < 512; i += 128) {
            int n = i >> 3, kc = i & 7;
            *reinterpret_cast<uint4*>(sWh + n * AROW + kc * 8) = s2h[i];
            *reinterpret_cast<uint4*>(sWl + n * AROW + kc * 8) = s2l[i];
        }
    }
    __syncthreads();

#pragma unroll
    for (int nb = 0; nb < 8; nb++)
#pragma unroll
        for (int u = 0; u < 4; u++) acc[nb][u] = 0.f;

    // ---------- GEMM2 (split HMMA) ----------
#pragma unroll
    for (int kb = 0; kb < 4; kb++) {
        int ko = kb * 16 + 2 * tq;
        const __half* ah0p = sAh + r0 * AROW + ko;
        const __half* ah1p = sAh + (r0 + 8) * AROW + ko;
        const __half* al0p = sAl + r0 * AROW + ko;
        const __half* al1p = sAl + (r0 + 8) * AROW + ko;
        unsigned ah0 = *reinterpret_cast<const unsigned*>(ah0p);
        unsigned ah1 = *reinterpret_cast<const unsigned*>(ah1p);
        unsigned ah2 = *reinterpret_cast<const unsigned*>(ah0p + 8);
        unsigned ah3 = *reinterpret_cast<const unsigned*>(ah1p + 8);
        unsigned al0 = *reinterpret_cast<const unsigned*>(al0p);
        unsigned al1 = *reinterpret_cast<const unsigned*>(al1p);
        unsigned al2 = *reinterpret_cast<const unsigned*>(al0p + 8);
        unsigned al3 = *reinterpret_cast<const unsigned*>(al1p + 8);
#pragma unroll
        for (int nb = 0; nb < 8; nb++) {
            int boff = (8 * nb + g) * AROW + ko;
            unsigned bh0 = *reinterpret_cast<const unsigned*>(sWh + boff);
            unsigned bh1 = *reinterpret_cast<const unsigned*>(sWh + boff + 8);
            unsigned bl0 = *reinterpret_cast<const unsigned*>(sWl + boff);
            unsigned bl1 = *reinterpret_cast<const unsigned*>(sWl + boff + 8);
            mma16816(acc[nb], ah0, ah1, ah2, ah3, bh0, bh1);
            mma16816(acc[nb], ah0, ah1, ah2, ah3, bl0, bl1);
            mma16816(acc[nb], al0, al1, al2, al3, bh0, bh1);
        }
    }

    // epilogue 2: bias + outer ELU -> g_h fp32 (+ optional fp16 mirror)
    int grow0 = base + r0;
    int grow1 = grow0 + 8;
#pragma unroll
    for (int nb = 0; nb < 8; nb++) {
        int j = 8 * nb + 2 * tq;
        float2 bv = *reinterpret_cast<const float2*>(&sb2[j]);
        float o00 = elu(acc[nb][0] + bv.x);
        float o01 = elu(acc[nb][1] + bv.y);
        float o10 = elu(acc[nb][2] + bv.x);
        float o11 = elu(acc[nb][3] + bv.y);
        if (grow0 < N_NODES) {
            *reinterpret_cast<float2*>(g_h + (size_t)grow0 * 64 + j) = make_float2(o00, o01);
            if (write_fp16)
                *reinterpret_cast<__half2*>(g_hh + (size_t)grow0 * 64 + j) = __floats2half2_rn(o00, o01);
        }
        if (grow1 < N_NODES) {
            *reinterpret_cast<float2*>(g_h + (size_t)grow1 * 64 + j) = make_float2(o10, o11);
            if (write_fp16)
                *reinterpret_cast<__half2*>(g_hh + (size_t)grow1 * 64 + j) = __floats2half2_rn(o10, o11);
        }
    }
}

// ---------------- mean pool (bounds inlined) ----------------
__global__ void k_pool(const int* __restrict__ batch) {
    int g = blockIdx.x;
    __shared__ int sbounds[2];
    if (threadIdx.x < 2) {
        int target = g + threadIdx.x;       // first batch[m] >= target
        int lo = 0, hi = N_NODES;
        while (lo < hi) {
            int mid = (lo + hi) >> 1;
            if (__ldg(batch + mid) < target) lo = mid + 1; else hi = mid;
        }
        sbounds[threadIdx.x] = lo;
    }
    __syncthreads();
    int start = sbounds[0], end = sbounds[1];

    int f = threadIdx.x & 63;
    int s = threadIdx.x >> 6;
    float acc = 0.f;
    for (int i = start + s; i < end; i += 4)
        acc += g_h[(size_t)i * 64 + f];
    __shared__ float red[256];
    red[threadIdx.x] = acc;
    __syncthreads();
    if (s == 0) {
        float v = red[f] + red[f + 64] + red[f + 128] + red[f + 192];
        float cnt = (float)(end - start);
        g_pooled[g * 64 + f] = v / fmaxf(cnt, 1.0f);
    }
}

// ---------------- head ----------------
__global__ void __launch_bounds__(64) k_head(
    const float* __restrict__ Wr1, const float* __restrict__ br1,
    const float* __restrict__ Wr2, const float* __restrict__ br2,
    const float* __restrict__ Wo,  const float* __restrict__ bo,
    float* __restrict__ out)
{
    __shared__ float Ws[64 * 64];
    __shared__ float s_p[64 * 65];
    __shared__ float sb[64];
    __shared__ float sWo[64];

    const int t = threadIdx.x;
    const int gbase = blockIdx.x * 64;

    sb[t]  = br1[t];
    sWo[t] = Wo[t];
#pragma unroll
    for (int i = t; i < 4096; i += 64) Ws[i] = Wr1[i];
#pragma unroll
    for (int i = 4 * t; i < 4096; i += 256) {
        int r = i >> 6, c = i & 63;
        float4 v = *reinterpret_cast<const float4*>(g_pooled + (size_t)(gbase + r) * 64 + c);
        s_p[r * 65 + c + 0] = v.x;
        s_p[r * 65 + c + 1] = v.y;
        s_p[r * 65 + c + 2] = v.z;
        s_p[r * 65 + c + 3] = v.w;
    }
    __syncthreads();

    const float* myrow = s_p + t * 65;
    float tt[64];

#pragma unroll
    for (int jt = 0; jt < 64; jt += 8) {
        float acc[8];
#pragma unroll
        for (int u = 0; u < 8; u++) acc[u] = 0.f;
#pragma unroll 4
        for (int k = 0; k < 64; k++) {
            float a = myrow[k];
            const float* w = Ws + k * 64 + jt;
            float4 w0 = *reinterpret_cast<const float4*>(w);
            float4 w1 = *reinterpret_cast<const float4*>(w + 4);
            acc[0] += a * w0.x; acc[1] += a * w0.y;
            acc[2] += a * w0.z; acc[3] += a * w0.w;
            acc[4] += a * w1.x; acc[5] += a * w1.y;
            acc[6] += a * w1.z; acc[7] += a * w1.w;
        }
#pragma unroll
        for (int u = 0; u < 8; u++) tt[jt + u] = elu(acc[u] + sb[jt + u]);
    }

#pragma unroll
    for (int j = 0; j < 64; j++) s_p[t * 65 + j] = tt[j];
    __syncthreads();
#pragma unroll
    for (int i = t; i < 4096; i += 64) Ws[i] = Wr2[i];
    sb[t] = br2[t];
    __syncthreads();

    float oacc = 0.f;
#pragma unroll
    for (int jt = 0; jt < 64; jt += 8) {
        float acc[8];
#pragma unroll
        for (int u = 0; u < 8; u++) acc[u] = 0.f;
#pragma unroll 4
        for (int k = 0; k < 64; k++) {
            float a = myrow[k];
            const float* w = Ws + k * 64 + jt;
            float4 w0 = *reinterpret_cast<const float4*>(w);
            float4 w1 = *reinterpret_cast<const float4*>(w + 4);
            acc[0] += a * w0.x; acc[1] += a * w0.y;
            acc[2] += a * w0.z; acc[3] += a * w0.w;
            acc[4] += a * w1.x; acc[5] += a * w1.y;
            acc[6] += a * w1.z; acc[7] += a * w1.w;
        }
#pragma unroll
        for (int u = 0; u < 8; u++)
            oacc += (acc[u] + sb[jt + u]) * sWo[jt + u];
    }
    out[gbase + t] = oacc + bo[0];
}

// ---------------- launcher ----------------
extern "C" void kernel_launch(void* const* d_in, const int* in_sizes, int n_in,
                              void* d_out, int out_size) {
    const int*   x     = (const int*)d_in[0];
    const int*   ei    = (const int*)d_in[1];
    const int*   batch = (const int*)d_in[2];
    const float* emb   = (const float*)d_in[3];
    const int* src = ei;
    const int* dst = ei + N_EDGES;
    float* out = (float*)d_out;

    const int TPB = 256;
    const int gnod = (N_NODES + TPB - 1) / TPB;
    const int gedg = (N_EDGES + TPB - 1) / TPB;
    const int gmlp = (N_NODES + 63) / 64;
    const int ggat = (N_NODES + 15) / 16;

    // launch 1: weight pre-split + cnt zeroing (merged)
    k_split_zero<<<gnod, TPB>>>(
        (const float*)d_in[4],  (const float*)d_in[8],   // W1a, W2a
        (const float*)d_in[10], (const float*)d_in[14],  // W1b, W2b
        (const float*)d_in[16], (const float*)d_in[20]); // W1c, W2c
    k_fill<<<gedg, TPB>>>(src, dst);                     // launch 2

    for (int L = 0; L < 3; L++) {
        const float* b1  = (const float*)d_in[4 + 6 * L + 1];
        const float* gam = (const float*)d_in[4 + 6 * L + 2];
        const float* bet = (const float*)d_in[4 + 6 * L + 3];
        const float* b2  = (const float*)d_in[4 + 6 * L + 5];

        if (L == 0)
            k_gather1<<<ggat, 256>>>(x, emb);            // launch 3
        else
            k_gather<<<ggat, 256>>>();
        // launch 4 = k_mlp (layer 1) -> ncu capture slot
        k_mlp<<<gmlp, 128>>>(2 * L, b1, gam, bet, b2, (L < 2) ? 1 : 0);
    }

    k_pool<<<N_GRAPHS, 256>>>(batch);
    k_head<<<2, 64>>>((const float*)d_in[22], (const float*)d_in[23],
                      (const float*)d_in[24], (const float*)d_in[25],
                      (const float*)d_in[26], (const float*)d_in[27],
                      out);
}

// round 12
// speedup vs baseline: 1.2925x; 1.0279x over previous
#include <cuda_runtime.h>
#include <cuda_bf16.h>
#include <cuda_fp16.h>
#include <math.h>

#define N_NODES 100000
#define N_EDGES 1200000
#define N_GRAPHS 128
#define MAX_DEG 64            // Poisson(12): P(deg>=64) ~ 1e-30, guarded anyway
#define AROW 72               // smem row stride in halves (144B): conflict-free fragments

// ---------------- scratch ----------------
__device__ float  g_h[(size_t)N_NODES * 64];            // final-layer output (pool input)
__device__ __align__(16) __half g_hh[(size_t)N_NODES * 64];  // h hi mirror
__device__ __align__(16) __half g_hl[(size_t)N_NODES * 64];  // h lo mirror
__device__ __align__(16) __half g_aggh[(size_t)N_NODES * 64]; // agg hi (pre-split)
__device__ __align__(16) __half g_aggl[(size_t)N_NODES * 64]; // agg lo (pre-split)
__device__ float  g_pooled[N_GRAPHS * 64];

__device__ int g_cnt[N_NODES];
__device__ int g_adj[(size_t)N_NODES * MAX_DEG];

// pre-split transposed weights: [matrix][n*64+k], matrices 2L=W1, 2L+1=W2
__device__ __align__(16) __half g_wh[6 * 4096];
__device__ __align__(16) __half g_wl[6 * 4096];

__device__ __forceinline__ float elu(float v) {
    return v > 0.f ? v : expm1f(v);
}

// ---- HMMA m16n8k16 row.col f16f16f32 ----
__device__ __forceinline__ void mma16816(float* d,
    unsigned a0, unsigned a1, unsigned a2, unsigned a3,
    unsigned b0, unsigned b1)
{
    asm volatile(
        "mma.sync.aligned.m16n8k16.row.col.f32.f16.f16.f32 "
        "{%0,%1,%2,%3}, {%4,%5,%6,%7}, {%8,%9}, {%0,%1,%2,%3};"
        : "+f"(d[0]), "+f"(d[1]), "+f"(d[2]), "+f"(d[3])
        : "r"(a0), "r"(a1), "r"(a2), "r"(a3), "r"(b0), "r"(b1));
}

// split float into fp16 hi + fp16 lo (a ~= hi + lo)
__device__ __forceinline__ void split16(float a, __half& hi, __half& lo) {
    hi = __float2half_rn(a);
    lo = __float2half_rn(a - __half2float(hi));
}

// split float4 into hi/lo half2 pairs
__device__ __forceinline__ void split4(float4 v, uint2& ph, uint2& pl) {
    __half hx, lx, hy, ly, hz, lz, hw, lw;
    split16(v.x, hx, lx); split16(v.y, hy, ly);
    split16(v.z, hz, lz); split16(v.w, hw, lw);
    __half2 h0 = __halves2half2(hx, hy), h1 = __halves2half2(hz, hw);
    __half2 l0 = __halves2half2(lx, ly), l1 = __halves2half2(lz, lw);
    ph.x = *reinterpret_cast<unsigned*>(&h0);
    ph.y = *reinterpret_cast<unsigned*>(&h1);
    pl.x = *reinterpret_cast<unsigned*>(&l0);
    pl.y = *reinterpret_cast<unsigned*>(&l1);
}

// ------- weight pre-split (once per launch) + g_cnt zeroing, merged ---------
__global__ void k_split_zero(const float* __restrict__ w0, const float* __restrict__ w1,
                             const float* __restrict__ w2, const float* __restrict__ w3,
                             const float* __restrict__ w4, const float* __restrict__ w5)
{
    int i = blockIdx.x * blockDim.x + threadIdx.x;
    if (i < N_NODES) g_cnt[i] = 0;
    if (i < 6 * 4096) {
        int m = i >> 12, j = i & 4095;
        const float* W;
        switch (m) {
            case 0: W = w0; break;
            case 1: W = w1; break;
            case 2: W = w2; break;
            case 3: W = w3; break;
            case 4: W = w4; break;
            default: W = w5; break;
        }
        float v = __ldg(W + j);
        int k = j >> 6, n = j & 63;           // W[k][n] -> Wt[n][k]
        __half hi, lo;
        split16(v, hi, lo);
        g_wh[m * 4096 + n * 64 + k] = hi;
        g_wl[m * 4096 + n * 64 + k] = lo;
    }
}

__global__ void k_fill(const int* __restrict__ src, const int* __restrict__ dst) {
    int e = blockIdx.x * blockDim.x + threadIdx.x;
    if (e >= N_EDGES) return;
    int d = __ldg(dst + e);
    int slot = atomicAdd(&g_cnt[d], 1);
    if (slot < MAX_DEG)
        g_adj[(size_t)d * MAX_DEG + slot] = __ldg(src + e);
}

// ------- layer-1 gather from embedding, writes pre-split agg ---------------
__global__ void __launch_bounds__(256) k_gather1(const int* __restrict__ x,
                                                 const float* __restrict__ emb) {
    int t = threadIdx.x;
    int n = blockIdx.x * 16 + (t >> 4);
    int c = t & 15;
    if (n >= N_NODES) return;
    const float4* __restrict__ e4 = reinterpret_cast<const float4*>(emb);
    int xn = __ldg(x + n);
    float4 acc = e4[(size_t)xn * 16 + c];
    const int* __restrict__ alist = g_adj + (size_t)n * MAX_DEG;
    int e = min(g_cnt[n], MAX_DEG);
    for (int i = 0; i < e; i++) {
        int s = __ldg(alist + i);
        int xs = __ldg(x + s);
        float4 v = e4[(size_t)xs * 16 + c];
        acc.x += v.x; acc.y += v.y; acc.z += v.z; acc.w += v.w;
    }
    uint2 ph, pl;
    split4(acc, ph, pl);
    reinterpret_cast<uint2*>(g_aggh)[(size_t)n * 16 + c] = ph;
    reinterpret_cast<uint2*>(g_aggl)[(size_t)n * 16 + c] = pl;
}

// ------- gather (layers 2-3): agg[n] = (hh+hl)[n] + sum hh[nb], pre-split ---
__global__ void __launch_bounds__(256) k_gather() {
    int t = threadIdx.x;
    int n = blockIdx.x * 16 + (t >> 4);
    int c = t & 15;
    if (n >= N_NODES) return;
    const uint2* __restrict__ hh2 = reinterpret_cast<const uint2*>(g_hh);
    const uint2* __restrict__ hl2 = reinterpret_cast<const uint2*>(g_hl);
    uint2 sh = __ldg(&hh2[(size_t)n * 16 + c]);
    uint2 sl = __ldg(&hl2[(size_t)n * 16 + c]);
    float2 a0 = __half22float2(*reinterpret_cast<__half2*>(&sh.x));
    float2 a1 = __half22float2(*reinterpret_cast<__half2*>(&sh.y));
    float2 b0 = __half22float2(*reinterpret_cast<__half2*>(&sl.x));
    float2 b1 = __half22float2(*reinterpret_cast<__half2*>(&sl.y));
    float4 acc = make_float4(a0.x + b0.x, a0.y + b0.y, a1.x + b1.x, a1.y + b1.y);

    const int* __restrict__ alist = g_adj + (size_t)n * MAX_DEG;
    int e = min(g_cnt[n], MAX_DEG);
    int nxt = (e > 0) ? __ldg(alist) : 0;
    for (int i = 0; i < e; i++) {
        int cur = nxt;
        if (i + 1 < e) nxt = __ldg(alist + i + 1);
        uint2 v = __ldg(&hh2[(size_t)cur * 16 + c]);
        float2 f0 = __half22float2(*reinterpret_cast<__half2*>(&v.x));
        float2 f1 = __half22float2(*reinterpret_cast<__half2*>(&v.y));
        acc.x += f0.x; acc.y += f0.y; acc.z += f1.x; acc.w += f1.y;
    }
    uint2 ph, pl;
    split4(acc, ph, pl);
    reinterpret_cast<uint2*>(g_aggh)[(size_t)n * 16 + c] = ph;
    reinterpret_cast<uint2*>(g_aggl)[(size_t)n * 16 + c] = pl;
}

// ---------------- fused MLP+BN+ELU via split-fp16 HMMA ----------------------
// 128 threads = 4 warps; warp w owns rows 16w..16w+15 of the 64-node tile.
// Weights and activations arrive pre-split -> staging is pure vector copy.
__global__ void __launch_bounds__(128) k_mlp(
    int widx,
    const float* __restrict__ b1,
    const float* __restrict__ gam, const float* __restrict__ bet,
    const float* __restrict__ b2,
    int write_fp16)
{
    __shared__ __half sAh[64 * AROW];
    __shared__ __half sAl[64 * AROW];
    __shared__ __half sWh[64 * AROW];
    __shared__ __half sWl[64 * AROW];
    __shared__ float sb1[64], ssc[64], sbe[64], sb2[64];

    const int t = threadIdx.x;
    const int w = t >> 5;
    const int lane = t & 31;
    const int g = lane >> 2;       // 0..7
    const int tq = lane & 3;       // 0..3
    const int base = blockIdx.x * 64;

    if (t < 64) {
        sb1[t] = b1[t];
        ssc[t] = gam[t] * rsqrtf(1.0f + 1e-5f);
        sbe[t] = bet[t];
        sb2[t] = b2[t];
    }

    // stage W1^T hi/lo: pure vectorized copy (8 halves per uint4)
    {
        const uint4* s1h = reinterpret_cast<const uint4*>(g_wh + (size_t)widx * 4096);
        const uint4* s1l = reinterpret_cast<const uint4*>(g_wl + (size_t)widx * 4096);
#pragma unroll
        for (int i = t; i < 512; i += 128) {
            int n = i >> 3, kc = i & 7;
            *reinterpret_cast<uint4*>(sWh + n * AROW + kc * 8) = s1h[i];
            *reinterpret_cast<uint4*>(sWl + n * AROW + kc * 8) = s1l[i];
        }
    }
    // stage activations: pure vectorized copy of pre-split hi/lo
    {
        const uint4* ah4 = reinterpret_cast<const uint4*>(g_aggh);
        const uint4* al4 = reinterpret_cast<const uint4*>(g_aggl);
        const uint4 z = make_uint4(0, 0, 0, 0);
#pragma unroll
        for (int i = t; i < 512; i += 128) {
            int r = i >> 3, c8 = i & 7;
            int row = base + r;
            uint4 vh = z, vl = z;
            if (row < N_NODES) {
                vh = ah4[(size_t)row * 8 + c8];
                vl = al4[(size_t)row * 8 + c8];
            }
            *reinterpret_cast<uint4*>(sAh + r * AROW + c8 * 8) = vh;
            *reinterpret_cast<uint4*>(sAl + r * AROW + c8 * 8) = vl;
        }
    }
    __syncthreads();

    const int r0 = 16 * w + g;          // local row (first half)

    float acc[8][4];
#pragma unroll
    for (int nb = 0; nb < 8; nb++)
#pragma unroll
        for (int u = 0; u < 4; u++) acc[nb][u] = 0.f;

    // ---------- GEMM1 (split HMMA) ----------
#pragma unroll
    for (int kb = 0; kb < 4; kb++) {
        int ko = kb * 16 + 2 * tq;
        const __half* ah0p = sAh + r0 * AROW + ko;
        const __half* ah1p = sAh + (r0 + 8) * AROW + ko;
        const __half* al0p = sAl + r0 * AROW + ko;
        const __half* al1p = sAl + (r0 + 8) * AROW + ko;
        unsigned ah0 = *reinterpret_cast<const unsigned*>(ah0p);
        unsigned ah1 = *reinterpret_cast<const unsigned*>(ah1p);
        unsigned ah2 = *reinterpret_cast<const unsigned*>(ah0p + 8);
        unsigned ah3 = *reinterpret_cast<const unsigned*>(ah1p + 8);
        unsigned al0 = *reinterpret_cast<const unsigned*>(al0p);
        unsigned al1 = *reinterpret_cast<const unsigned*>(al1p);
        unsigned al2 = *reinterpret_cast<const unsigned*>(al0p + 8);
        unsigned al3 = *reinterpret_cast<const unsigned*>(al1p + 8);
#pragma unroll
        for (int nb = 0; nb < 8; nb++) {
            int boff = (8 * nb + g) * AROW + ko;
            unsigned bh0 = *reinterpret_cast<const unsigned*>(sWh + boff);
            unsigned bh1 = *reinterpret_cast<const unsigned*>(sWh + boff + 8);
            unsigned bl0 = *reinterpret_cast<const unsigned*>(sWl + boff);
            unsigned bl1 = *reinterpret_cast<const unsigned*>(sWl + boff + 8);
            mma16816(acc[nb], ah0, ah1, ah2, ah3, bh0, bh1);
            mma16816(acc[nb], ah0, ah1, ah2, ah3, bl0, bl1);
            mma16816(acc[nb], al0, al1, al2, al3, bh0, bh1);
        }
    }

    // epilogue 1: BN affine + ELU -> own rows, split fp16
#pragma unroll
    for (int nb = 0; nb < 8; nb++) {
        int j = 8 * nb + 2 * tq;
        float2 bv = *reinterpret_cast<const float2*>(&sb1[j]);
        float2 sv = *reinterpret_cast<const float2*>(&ssc[j]);
        float2 ev = *reinterpret_cast<const float2*>(&sbe[j]);
        float v00 = elu((acc[nb][0] + bv.x) * sv.x + ev.x);
        float v01 = elu((acc[nb][1] + bv.y) * sv.y + ev.y);
        float v10 = elu((acc[nb][2] + bv.x) * sv.x + ev.x);
        float v11 = elu((acc[nb][3] + bv.y) * sv.y + ev.y);
        __half h00, l00, h01, l01, h10, l10, h11, l11;
        split16(v00, h00, l00); split16(v01, h01, l01);
        split16(v10, h10, l10); split16(v11, h11, l11);
        *reinterpret_cast<__half2*>(sAh + r0 * AROW + j)       = __halves2half2(h00, h01);
        *reinterpret_cast<__half2*>(sAl + r0 * AROW + j)       = __halves2half2(l00, l01);
        *reinterpret_cast<__half2*>(sAh + (r0 + 8) * AROW + j) = __halves2half2(h10, h11);
        *reinterpret_cast<__half2*>(sAl + (r0 + 8) * AROW + j) = __halves2half2(l10, l11);
    }
    __syncthreads();   // all warps done reading W1 tiles

    // stage W2^T hi/lo (pure copy)
    {
        const uint4* s2h = reinterpret_cast<const uint4*>(g_wh + (size_t)(widx + 1) * 4096);
        const uint4* s2l = reinterpret_cast<const uint4*>(g_wl + (size_t)(widx + 1) * 4096);
#pragma unroll
        for (int i = t; i < 512; i += 128) {
            int n = i >> 3, kc = i & 7;
            *reinterpret_cast<uint4*>(sWh + n * AROW + kc * 8) = s2h[i];
            *reinterpret_cast<uint4*>(sWl + n * AROW + kc * 8) = s2l[i];
        }
    }
    __syncthreads();

#pragma unroll
    for (int nb = 0; nb < 8; nb++)
#pragma unroll
        for (int u = 0; u < 4; u++) acc[nb][u] = 0.f;

    // ---------- GEMM2 (split HMMA) ----------
#pragma unroll
    for (int kb = 0; kb < 4; kb++) {
        int ko = kb * 16 + 2 * tq;
        const __half* ah0p = sAh + r0 * AROW + ko;
        const __half* ah1p = sAh + (r0 + 8) * AROW + ko;
        const __half* al0p = sAl + r0 * AROW + ko;
        const __half* al1p = sAl + (r0 + 8) * AROW + ko;
        unsigned ah0 = *reinterpret_cast<const unsigned*>(ah0p);
        unsigned ah1 = *reinterpret_cast<const unsigned*>(ah1p);
        unsigned ah2 = *reinterpret_cast<const unsigned*>(ah0p + 8);
        unsigned ah3 = *reinterpret_cast<const unsigned*>(ah1p + 8);
        unsigned al0 = *reinterpret_cast<const unsigned*>(al0p);
        unsigned al1 = *reinterpret_cast<const unsigned*>(al1p);
        unsigned al2 = *reinterpret_cast<const unsigned*>(al0p + 8);
        unsigned al3 = *reinterpret_cast<const unsigned*>(al1p + 8);
#pragma unroll
        for (int nb = 0; nb < 8; nb++) {
            int boff = (8 * nb + g) * AROW + ko;
            unsigned bh0 = *reinterpret_cast<const unsigned*>(sWh + boff);
            unsigned bh1 = *reinterpret_cast<const unsigned*>(sWh + boff + 8);
            unsigned bl0 = *reinterpret_cast<const unsigned*>(sWl + boff);
            unsigned bl1 = *reinterpret_cast<const unsigned*>(sWl + boff + 8);
            mma16816(acc[nb], ah0, ah1, ah2, ah3, bh0, bh1);
            mma16816(acc[nb], ah0, ah1, ah2, ah3, bl0, bl1);
            mma16816(acc[nb], al0, al1, al2, al3, bh0, bh1);
        }
    }

    // epilogue 2: bias + outer ELU
    // layers 1-2 (write_fp16): write split hi/lo mirrors only
    // final layer: write fp32 g_h only (pool input)
    int grow0 = base + r0;
    int grow1 = grow0 + 8;
#pragma unroll
    for (int nb = 0; nb < 8; nb++) {
        int j = 8 * nb + 2 * tq;
        float2 bv = *reinterpret_cast<const float2*>(&sb2[j]);
        float o00 = elu(acc[nb][0] + bv.x);
        float o01 = elu(acc[nb][1] + bv.y);
        float o10 = elu(acc[nb][2] + bv.x);
        float o11 = elu(acc[nb][3] + bv.y);
        if (write_fp16) {
            if (grow0 < N_NODES) {
                __half h0, l0, h1, l1;
                split16(o00, h0, l0); split16(o01, h1, l1);
                *reinterpret_cast<__half2*>(g_hh + (size_t)grow0 * 64 + j) = __halves2half2(h0, h1);
                *reinterpret_cast<__half2*>(g_hl + (size_t)grow0 * 64 + j) = __halves2half2(l0, l1);
            }
            if (grow1 < N_NODES) {
                __half h0, l0, h1, l1;
                split16(o10, h0, l0); split16(o11, h1, l1);
                *reinterpret_cast<__half2*>(g_hh + (size_t)grow1 * 64 + j) = __halves2half2(h0, h1);
                *reinterpret_cast<__half2*>(g_hl + (size_t)grow1 * 64 + j) = __halves2half2(l0, l1);
            }
        } else {
            if (grow0 < N_NODES)
                *reinterpret_cast<float2*>(g_h + (size_t)grow0 * 64 + j) = make_float2(o00, o01);
            if (grow1 < N_NODES)
                *reinterpret_cast<float2*>(g_h + (size_t)grow1 * 64 + j) = make_float2(o10, o11);
        }
    }
}

// ---------------- mean pool (bounds inlined) ----------------
__global__ void k_pool(const int* __restrict__ batch) {
    int g = blockIdx.x;
    __shared__ int sbounds[2];
    if (threadIdx.x < 2) {
        int target = g + threadIdx.x;       // first batch[m] >= target
        int lo = 0, hi = N_NODES;
        while (lo < hi) {
            int mid = (lo + hi) >> 1;
            if (__ldg(batch + mid) < target) lo = mid + 1; else hi = mid;
        }
        sbounds[threadIdx.x] = lo;
    }
    __syncthreads();
    int start = sbounds[0], end = sbounds[1];

    int f = threadIdx.x & 63;
    int s = threadIdx.x >> 6;
    float acc = 0.f;
    for (int i = start + s; i < end; i += 4)
        acc += g_h[(size_t)i * 64 + f];
    __shared__ float red[256];
    red[threadIdx.x] = acc;
    __syncthreads();
    if (s == 0) {
        float v = red[f] + red[f + 64] + red[f + 128] + red[f + 192];
        float cnt = (float)(end - start);
        g_pooled[g * 64 + f] = v / fmaxf(cnt, 1.0f);
    }
}

// ---------------- head ----------------
__global__ void __launch_bounds__(64) k_head(
    const float* __restrict__ Wr1, const float* __restrict__ br1,
    const float* __restrict__ Wr2, const float* __restrict__ br2,
    const float* __restrict__ Wo,  const float* __restrict__ bo,
    float* __restrict__ out)
{
    __shared__ float Ws[64 * 64];
    __shared__ float s_p[64 * 65];
    __shared__ float sb[64];
    __shared__ float sWo[64];

    const int t = threadIdx.x;
    const int gbase = blockIdx.x * 64;

    sb[t]  = br1[t];
    sWo[t] = Wo[t];
#pragma unroll
    for (int i = t; i < 4096; i += 64) Ws[i] = Wr1[i];
#pragma unroll
    for (int i = 4 * t; i < 4096; i += 256) {
        int r = i >> 6, c = i & 63;
        float4 v = *reinterpret_cast<const float4*>(g_pooled + (size_t)(gbase + r) * 64 + c);
        s_p[r * 65 + c + 0] = v.x;
        s_p[r * 65 + c + 1] = v.y;
        s_p[r * 65 + c + 2] = v.z;
        s_p[r * 65 + c + 3] = v.w;
    }
    __syncthreads();

    const float* myrow = s_p + t * 65;
    float tt[64];

#pragma unroll
    for (int jt = 0; jt < 64; jt += 8) {
        float acc[8];
#pragma unroll
        for (int u = 0; u < 8; u++) acc[u] = 0.f;
#pragma unroll 4
        for (int k = 0; k < 64; k++) {
            float a = myrow[k];
            const float* w = Ws + k * 64 + jt;
            float4 w0 = *reinterpret_cast<const float4*>(w);
            float4 w1 = *reinterpret_cast<const float4*>(w + 4);
            acc[0] += a * w0.x; acc[1] += a * w0.y;
            acc[2] += a * w0.z; acc[3] += a * w0.w;
            acc[4] += a * w1.x; acc[5] += a * w1.y;
            acc[6] += a * w1.z; acc[7] += a * w1.w;
        }
#pragma unroll
        for (int u = 0; u < 8; u++) tt[jt + u] = elu(acc[u] + sb[jt + u]);
    }

#pragma unroll
    for (int j = 0; j < 64; j++) s_p[t * 65 + j] = tt[j];
    __syncthreads();
#pragma unroll
    for (int i = t; i < 4096; i += 64) Ws[i] = Wr2[i];
    sb[t] = br2[t];
    __syncthreads();

    float oacc = 0.f;
#pragma unroll
    for (int jt = 0; jt < 64; jt += 8) {
        float acc[8];
#pragma unroll
        for (int u = 0; u < 8; u++) acc[u] = 0.f;
#pragma unroll 4
        for (int k = 0; k < 64; k++) {
            float a = myrow[k];
            const float* w = Ws + k * 64 + jt;
            float4 w0 = *reinterpret_cast<const float4*>(w);
            float4 w1 = *reinterpret_cast<const float4*>(w + 4);
            acc[0] += a * w0.x; acc[1] += a * w0.y;
            acc[2] += a * w0.z; acc[3] += a * w0.w;
            acc[4] += a * w1.x; acc[5] += a * w1.y;
            acc[6] += a * w1.z; acc[7] += a * w1.w;
        }
#pragma unroll
        for (int u = 0; u < 8; u++)
            oacc += (acc[u] + sb[jt + u]) * sWo[jt + u];
    }
    out[gbase + t] = oacc + bo[0];
}

// ---------------- launcher ----------------
extern "C" void kernel_launch(void* const* d_in, const int* in_sizes, int n_in,
                              void* d_out, int out_size) {
    const int*   x     = (const int*)d_in[0];
    const int*   ei    = (const int*)d_in[1];
    const int*   batch = (const int*)d_in[2];
    const float* emb   = (const float*)d_in[3];
    const int* src = ei;
    const int* dst = ei + N_EDGES;
    float* out = (float*)d_out;

    const int TPB = 256;
    const int gnod = (N_NODES + TPB - 1) / TPB;
    const int gedg = (N_EDGES + TPB - 1) / TPB;
    const int gmlp = (N_NODES + 63) / 64;
    const int ggat = (N_NODES + 15) / 16;

    // launch 1: weight pre-split + cnt zeroing (merged)
    k_split_zero<<<gnod, TPB>>>(
        (const float*)d_in[4],  (const float*)d_in[8],   // W1a, W2a
        (const float*)d_in[10], (const float*)d_in[14],  // W1b, W2b
        (const float*)d_in[16], (const float*)d_in[20]); // W1c, W2c
    k_fill<<<gedg, TPB>>>(src, dst);                     // launch 2

    for (int L = 0; L < 3; L++) {
        const float* b1  = (const float*)d_in[4 + 6 * L + 1];
        const float* gam = (const float*)d_in[4 + 6 * L + 2];
        const float* bet = (const float*)d_in[4 + 6 * L + 3];
        const float* b2  = (const float*)d_in[4 + 6 * L + 5];

        if (L == 0)
            k_gather1<<<ggat, 256>>>(x, emb);            // launch 3
        else
            k_gather<<<ggat, 256>>>();
        // launch 4 = k_mlp (layer 1) -> ncu capture slot
        k_mlp<<<gmlp, 128>>>(2 * L, b1, gam, bet, b2, (L < 2) ? 1 : 0);
    }

    k_pool<<<N_GRAPHS, 256>>>(batch);
    k_head<<<2, 64>>>((const float*)d_in[22], (const float*)d_in[23],
                      (const float*)d_in[24], (const float*)d_in[25],
                      (const float*)d_in[26], (const float*)d_in[27],
                      out);
}

// round 13
// speedup vs baseline: 1.2982x; 1.0044x over previous
#include <cuda_runtime.h>
#include <cuda_bf16.h>
#include <cuda_fp16.h>
#include <math.h>

#define N_NODES 100000
#define N_EDGES 1200000
#define N_GRAPHS 128
#define MAX_DEG 64            // Poisson(12): P(deg>=64) ~ 1e-30, guarded anyway
#define AROW 72               // smem row stride in halves (144B): conflict-free fragments

// ---------------- scratch ----------------
__device__ float  g_h[(size_t)N_NODES * 64];            // final-layer output (pool input)
__device__ __align__(16) __half g_hh[(size_t)N_NODES * 64];  // h hi mirror
__device__ __align__(16) __half g_hl[(size_t)N_NODES * 64];  // h lo mirror
__device__ __align__(16) __half g_aggh[(size_t)N_NODES * 64]; // agg hi (pre-split)
__device__ __align__(16) __half g_aggl[(size_t)N_NODES * 64]; // agg lo (pre-split)
__device__ float  g_pooled[N_GRAPHS * 64];

__device__ int g_cnt[N_NODES];
__device__ int g_adj[(size_t)N_NODES * MAX_DEG];

// pre-split transposed weights: [matrix][n*64+k], matrices 2L=W1, 2L+1=W2
__device__ __align__(16) __half g_wh[6 * 4096];
__device__ __align__(16) __half g_wl[6 * 4096];

__device__ __forceinline__ float elu(float v) {
    return v > 0.f ? v : expm1f(v);
}

// ---- HMMA m16n8k16 row.col f16f16f32 ----
__device__ __forceinline__ void mma16816(float* d,
    unsigned a0, unsigned a1, unsigned a2, unsigned a3,
    unsigned b0, unsigned b1)
{
    asm volatile(
        "mma.sync.aligned.m16n8k16.row.col.f32.f16.f16.f32 "
        "{%0,%1,%2,%3}, {%4,%5,%6,%7}, {%8,%9}, {%0,%1,%2,%3};"
        : "+f"(d[0]), "+f"(d[1]), "+f"(d[2]), "+f"(d[3])
        : "r"(a0), "r"(a1), "r"(a2), "r"(a3), "r"(b0), "r"(b1));
}

// ---- ldmatrix m8n8.x4 ----
__device__ __forceinline__ void ldsm4(unsigned& r0, unsigned& r1,
                                      unsigned& r2, unsigned& r3, unsigned addr)
{
    asm volatile("ldmatrix.sync.aligned.m8n8.x4.shared.b16 {%0,%1,%2,%3}, [%4];"
                 : "=r"(r0), "=r"(r1), "=r"(r2), "=r"(r3) : "r"(addr));
}

__device__ __forceinline__ unsigned smem_u32(const void* p) {
    return (unsigned)__cvta_generic_to_shared(p);
}

// split float into fp16 hi + fp16 lo (a ~= hi + lo)
__device__ __forceinline__ void split16(float a, __half& hi, __half& lo) {
    hi = __float2half_rn(a);
    lo = __float2half_rn(a - __half2float(hi));
}

// split float4 into hi/lo half2 pairs
__device__ __forceinline__ void split4(float4 v, uint2& ph, uint2& pl) {
    __half hx, lx, hy, ly, hz, lz, hw, lw;
    split16(v.x, hx, lx); split16(v.y, hy, ly);
    split16(v.z, hz, lz); split16(v.w, hw, lw);
    __half2 h0 = __halves2half2(hx, hy), h1 = __halves2half2(hz, hw);
    __half2 l0 = __halves2half2(lx, ly), l1 = __halves2half2(lz, lw);
    ph.x = *reinterpret_cast<unsigned*>(&h0);
    ph.y = *reinterpret_cast<unsigned*>(&h1);
    pl.x = *reinterpret_cast<unsigned*>(&l0);
    pl.y = *reinterpret_cast<unsigned*>(&l1);
}

// ------- weight pre-split (once per launch) + g_cnt zeroing, merged ---------
__global__ void k_split_zero(const float* __restrict__ w0, const float* __restrict__ w1,
                             const float* __restrict__ w2, const float* __restrict__ w3,
                             const float* __restrict__ w4, const float* __restrict__ w5)
{
    int i = blockIdx.x * blockDim.x + threadIdx.x;
    if (i < N_NODES) g_cnt[i] = 0;
    if (i < 6 * 4096) {
        int m = i >> 12, j = i & 4095;
        const float* W;
        switch (m) {
            case 0: W = w0; break;
            case 1: W = w1; break;
            case 2: W = w2; break;
            case 3: W = w3; break;
            case 4: W = w4; break;
            default: W = w5; break;
        }
        float v = __ldg(W + j);
        int k = j >> 6, n = j & 63;           // W[k][n] -> Wt[n][k]
        __half hi, lo;
        split16(v, hi, lo);
        g_wh[m * 4096 + n * 64 + k] = hi;
        g_wl[m * 4096 + n * 64 + k] = lo;
    }
}

__global__ void k_fill(const int* __restrict__ src, const int* __restrict__ dst) {
    int e = blockIdx.x * blockDim.x + threadIdx.x;
    if (e >= N_EDGES) return;
    int d = __ldg(dst + e);
    int slot = atomicAdd(&g_cnt[d], 1);
    if (slot < MAX_DEG)
        g_adj[(size_t)d * MAX_DEG + slot] = __ldg(src + e);
}

// ------- layer-1 gather from embedding, writes pre-split agg ---------------
__global__ void __launch_bounds__(256) k_gather1(const int* __restrict__ x,
                                                 const float* __restrict__ emb) {
    int t = threadIdx.x;
    int n = blockIdx.x * 16 + (t >> 4);
    int c = t & 15;
    if (n >= N_NODES) return;
    const float4* __restrict__ e4 = reinterpret_cast<const float4*>(emb);
    int xn = __ldg(x + n);
    float4 acc = e4[(size_t)xn * 16 + c];
    const int* __restrict__ alist = g_adj + (size_t)n * MAX_DEG;
    int e = min(g_cnt[n], MAX_DEG);
    for (int i = 0; i < e; i++) {
        int s = __ldg(alist + i);
        int xs = __ldg(x + s);
        float4 v = e4[(size_t)xs * 16 + c];
        acc.x += v.x; acc.y += v.y; acc.z += v.z; acc.w += v.w;
    }
    uint2 ph, pl;
    split4(acc, ph, pl);
    reinterpret_cast<uint2*>(g_aggh)[(size_t)n * 16 + c] = ph;
    reinterpret_cast<uint2*>(g_aggl)[(size_t)n * 16 + c] = pl;
}

// ------- gather (layers 2-3): agg[n] = (hh+hl)[n] + sum hh[nb], pre-split ---
__global__ void __launch_bounds__(256) k_gather() {
    int t = threadIdx.x;
    int n = blockIdx.x * 16 + (t >> 4);
    int c = t & 15;
    if (n >= N_NODES) return;
    const uint2* __restrict__ hh2 = reinterpret_cast<const uint2*>(g_hh);
    const uint2* __restrict__ hl2 = reinterpret_cast<const uint2*>(g_hl);
    uint2 sh = __ldg(&hh2[(size_t)n * 16 + c]);
    uint2 sl = __ldg(&hl2[(size_t)n * 16 + c]);
    float2 a0 = __half22float2(*reinterpret_cast<__half2*>(&sh.x));
    float2 a1 = __half22float2(*reinterpret_cast<__half2*>(&sh.y));
    float2 b0 = __half22float2(*reinterpret_cast<__half2*>(&sl.x));
    float2 b1 = __half22float2(*reinterpret_cast<__half2*>(&sl.y));
    float4 acc = make_float4(a0.x + b0.x, a0.y + b0.y, a1.x + b1.x, a1.y + b1.y);

    const int* __restrict__ alist = g_adj + (size_t)n * MAX_DEG;
    int e = min(g_cnt[n], MAX_DEG);
    int nxt = (e > 0) ? __ldg(alist) : 0;
    for (int i = 0; i < e; i++) {
        int cur = nxt;
        if (i + 1 < e) nxt = __ldg(alist + i + 1);
        uint2 v = __ldg(&hh2[(size_t)cur * 16 + c]);
        float2 f0 = __half22float2(*reinterpret_cast<__half2*>(&v.x));
        float2 f1 = __half22float2(*reinterpret_cast<__half2*>(&v.y));
        acc.x += f0.x; acc.y += f0.y; acc.z += f1.x; acc.w += f1.y;
    }
    uint2 ph, pl;
    split4(acc, ph, pl);
    reinterpret_cast<uint2*>(g_aggh)[(size_t)n * 16 + c] = ph;
    reinterpret_cast<uint2*>(g_aggl)[(size_t)n * 16 + c] = pl;
}

// ---------------- fused MLP+BN+ELU via split-fp16 HMMA + ldmatrix -----------
// 128 threads = 4 warps; warp w owns rows 16w..16w+15 of the 64-node tile.
// All fragments loaded via ldmatrix.x4 (4 frags per instruction).
__global__ void __launch_bounds__(128) k_mlp(
    int widx,
    const float* __restrict__ b1,
    const float* __restrict__ gam, const float* __restrict__ bet,
    const float* __restrict__ b2,
    int write_fp16)
{
    __shared__ __half sAh[64 * AROW];
    __shared__ __half sAl[64 * AROW];
    __shared__ __half sWh[64 * AROW];
    __shared__ __half sWl[64 * AROW];
    __shared__ float sb1[64], ssc[64], sbe[64], sb2[64];

    const int t = threadIdx.x;
    const int w = t >> 5;
    const int lane = t & 31;
    const int g = lane >> 2;       // 0..7
    const int tq = lane & 3;       // 0..3
    const int base = blockIdx.x * 64;

    if (t < 64) {
        sb1[t] = b1[t];
        ssc[t] = gam[t] * rsqrtf(1.0f + 1e-5f);
        sbe[t] = bet[t];
        sb2[t] = b2[t];
    }

    // stage W1^T hi/lo: pure vectorized copy (8 halves per uint4)
    {
        const uint4* s1h = reinterpret_cast<const uint4*>(g_wh + (size_t)widx * 4096);
        const uint4* s1l = reinterpret_cast<const uint4*>(g_wl + (size_t)widx * 4096);
#pragma unroll
        for (int i = t; i < 512; i += 128) {
            int n = i >> 3, kc = i & 7;
            *reinterpret_cast<uint4*>(sWh + n * AROW + kc * 8) = s1h[i];
            *reinterpret_cast<uint4*>(sWl + n * AROW + kc * 8) = s1l[i];
        }
    }
    // stage activations: pure vectorized copy of pre-split hi/lo
    {
        const uint4* ah4 = reinterpret_cast<const uint4*>(g_aggh);
        const uint4* al4 = reinterpret_cast<const uint4*>(g_aggl);
        const uint4 z = make_uint4(0, 0, 0, 0);
#pragma unroll
        for (int i = t; i < 512; i += 128) {
            int r = i >> 3, c8 = i & 7;
            int row = base + r;
            uint4 vh = z, vl = z;
            if (row < N_NODES) {
                vh = ah4[(size_t)row * 8 + c8];
                vl = al4[(size_t)row * 8 + c8];
            }
            *reinterpret_cast<uint4*>(sAh + r * AROW + c8 * 8) = vh;
            *reinterpret_cast<uint4*>(sAl + r * AROW + c8 * 8) = vl;
        }
    }
    __syncthreads();

    const int r0 = 16 * w + g;          // local row (first half)

    // ---- ldmatrix lane address setup ----
    // A: matrices (m-lo/k-lo, m-hi/k-lo, m-lo/k-hi, m-hi/k-hi)
    //    lane row = 16w + (lane & 15), k offset = (lane >> 4) * 8
    const int rowA  = 16 * w + (lane & 15);
    const int koffA = (lane >> 4) * 8;
    unsigned aAh = smem_u32(sAh + rowA * AROW + koffA);
    unsigned aAl = smem_u32(sAl + rowA * AROW + koffA);
    // B: per pair p covers nb=2p (b0,b1) and nb=2p+1 (b0,b1)
    //    lane n = 16p + (lane&7) + ((lane>>4)<<3), k offset = ((lane>>3)&1)*8
    const int nB    = (lane & 7) + ((lane >> 4) << 3);
    const int koffB = ((lane >> 3) & 1) * 8;
    unsigned aBh0 = smem_u32(sWh + nB * AROW + koffB);
    unsigned aBl0 = smem_u32(sWl + nB * AROW + koffB);
    const unsigned pStride = 16 * AROW * 2;   // 16 n-rows per pair, bytes

    float acc[8][4];
#pragma unroll
    for (int nb = 0; nb < 8; nb++)
#pragma unroll
        for (int u = 0; u < 4; u++) acc[nb][u] = 0.f;

    // ---------- GEMM1 (split HMMA, ldmatrix fragments) ----------
#pragma unroll
    for (int kb = 0; kb < 4; kb++) {
        unsigned ah0, ah1, ah2, ah3, al0, al1, al2, al3;
        ldsm4(ah0, ah1, ah2, ah3, aAh + kb * 32);
        ldsm4(al0, al1, al2, al3, aAl + kb * 32);
#pragma unroll
        for (int p = 0; p < 4; p++) {
            unsigned bh0, bh1, bh2, bh3, bl0, bl1, bl2, bl3;
            ldsm4(bh0, bh1, bh2, bh3, aBh0 + p * pStride + kb * 32);
            ldsm4(bl0, bl1, bl2, bl3, aBl0 + p * pStride + kb * 32);
            mma16816(acc[2 * p],     ah0, ah1, ah2, ah3, bh0, bh1);
            mma16816(acc[2 * p],     ah0, ah1, ah2, ah3, bl0, bl1);
            mma16816(acc[2 * p],     al0, al1, al2, al3, bh0, bh1);
            mma16816(acc[2 * p + 1], ah0, ah1, ah2, ah3, bh2, bh3);
            mma16816(acc[2 * p + 1], ah0, ah1, ah2, ah3, bl2, bl3);
            mma16816(acc[2 * p + 1], al0, al1, al2, al3, bh2, bh3);
        }
    }

    // epilogue 1: BN affine + ELU -> own rows, split fp16
#pragma unroll
    for (int nb = 0; nb < 8; nb++) {
        int j = 8 * nb + 2 * tq;
        float2 bv = *reinterpret_cast<const float2*>(&sb1[j]);
        float2 sv = *reinterpret_cast<const float2*>(&ssc[j]);
        float2 ev = *reinterpret_cast<const float2*>(&sbe[j]);
        float v00 = elu((acc[nb][0] + bv.x) * sv.x + ev.x);
        float v01 = elu((acc[nb][1] + bv.y) * sv.y + ev.y);
        float v10 = elu((acc[nb][2] + bv.x) * sv.x + ev.x);
        float v11 = elu((acc[nb][3] + bv.y) * sv.y + ev.y);
        __half h00, l00, h01, l01, h10, l10, h11, l11;
        split16(v00, h00, l00); split16(v01, h01, l01);
        split16(v10, h10, l10); split16(v11, h11, l11);
        *reinterpret_cast<__half2*>(sAh + r0 * AROW + j)       = __halves2half2(h00, h01);
        *reinterpret_cast<__half2*>(sAl + r0 * AROW + j)       = __halves2half2(l00, l01);
        *reinterpret_cast<__half2*>(sAh + (r0 + 8) * AROW + j) = __halves2half2(h10, h11);
        *reinterpret_cast<__half2*>(sAl + (r0 + 8) * AROW + j) = __halves2half2(l10, l11);
    }
    __syncthreads();   // all warps done reading W1 tiles

    // stage W2^T hi/lo (pure copy)
    {
        const uint4* s2h = reinterpret_cast<const uint4*>(g_wh + (size_t)(widx + 1) * 4096);
        const uint4* s2l = reinterpret_cast<const uint4*>(g_wl + (size_t)(widx + 1) * 4096);
#pragma unroll
        for (int i = t; i < 512; i += 128) {
            int n = i >> 3, kc = i & 7;
            *reinterpret_cast<uint4*>(sWh + n * AROW + kc * 8) = s2h[i];
            *reinterpret_cast<uint4*>(sWl + n * AROW + kc * 8) = s2l[i];
        }
    }
    __syncthreads();

#pragma unroll
    for (int nb = 0; nb < 8; nb++)
#pragma unroll
        for (int u = 0; u < 4; u++) acc[nb][u] = 0.f;

    // ---------- GEMM2 (split HMMA, ldmatrix fragments) ----------
#pragma unroll
    for (int kb = 0; kb < 4; kb++) {
        unsigned ah0, ah1, ah2, ah3, al0, al1, al2, al3;
        ldsm4(ah0, ah1, ah2, ah3, aAh + kb * 32);
        ldsm4(al0, al1, al2, al3, aAl + kb * 32);
#pragma unroll
        for (int p = 0; p < 4; p++) {
            unsigned bh0, bh1, bh2, bh3, bl0, bl1, bl2, bl3;
            ldsm4(bh0, bh1, bh2, bh3, aBh0 + p * pStride + kb * 32);
            ldsm4(bl0, bl1, bl2, bl3, aBl0 + p * pStride + kb * 32);
            mma16816(acc[2 * p],     ah0, ah1, ah2, ah3, bh0, bh1);
            mma16816(acc[2 * p],     ah0, ah1, ah2, ah3, bl0, bl1);
            mma16816(acc[2 * p],     al0, al1, al2, al3, bh0, bh1);
            mma16816(acc[2 * p + 1], ah0, ah1, ah2, ah3, bh2, bh3);
            mma16816(acc[2 * p + 1], ah0, ah1, ah2, ah3, bl2, bl3);
            mma16816(acc[2 * p + 1], al0, al1, al2, al3, bh2, bh3);
        }
    }

    // epilogue 2: bias + outer ELU
    // layers 1-2 (write_fp16): write split hi/lo mirrors only
    // final layer: write fp32 g_h only (pool input)
    int grow0 = base + r0;
    int grow1 = grow0 + 8;
#pragma unroll
    for (int nb = 0; nb < 8; nb++) {
        int j = 8 * nb + 2 * tq;
        float2 bv = *reinterpret_cast<const float2*>(&sb2[j]);
        float o00 = elu(acc[nb][0] + bv.x);
        float o01 = elu(acc[nb][1] + bv.y);
        float o10 = elu(acc[nb][2] + bv.x);
        float o11 = elu(acc[nb][3] + bv.y);
        if (write_fp16) {
            if (grow0 < N_NODES) {
                __half h0, l0, h1, l1;
                split16(o00, h0, l0); split16(o01, h1, l1);
                *reinterpret_cast<__half2*>(g_hh + (size_t)grow0 * 64 + j) = __halves2half2(h0, h1);
                *reinterpret_cast<__half2*>(g_hl + (size_t)grow0 * 64 + j) = __halves2half2(l0, l1);
            }
            if (grow1 < N_NODES) {
                __half h0, l0, h1, l1;
                split16(o10, h0, l0); split16(o11, h1, l1);
                *reinterpret_cast<__half2*>(g_hh + (size_t)grow1 * 64 + j) = __halves2half2(h0, h1);
                *reinterpret_cast<__half2*>(g_hl + (size_t)grow1 * 64 + j) = __halves2half2(l0, l1);
            }
        } else {
            if (grow0 < N_NODES)
                *reinterpret_cast<float2*>(g_h + (size_t)grow0 * 64 + j) = make_float2(o00, o01);
            if (grow1 < N_NODES)
                *reinterpret_cast<float2*>(g_h + (size_t)grow1 * 64 + j) = make_float2(o10, o11);
        }
    }
}

// ---------------- mean pool (bounds inlined) ----------------
__global__ void k_pool(const int* __restrict__ batch) {
    int g = blockIdx.x;
    __shared__ int sbounds[2];
    if (threadIdx.x < 2) {
        int target = g + threadIdx.x;       // first batch[m] >= target
        int lo = 0, hi = N_NODES;
        while (lo < hi) {
            int mid = (lo + hi) >> 1;
            if (__ldg(batch + mid) < target) lo = mid + 1; else hi = mid;
        }
        sbounds[threadIdx.x] = lo;
    }
    __syncthreads();
    int start = sbounds[0], end = sbounds[1];

    int f = threadIdx.x & 63;
    int s = threadIdx.x >> 6;
    float acc = 0.f;
    for (int i = start + s; i < end; i += 4)
        acc += g_h[(size_t)i * 64 + f];
    __shared__ float red[256];
    red[threadIdx.x] = acc;
    __syncthreads();
    if (s == 0) {
        float v = red[f] + red[f + 64] + red[f + 128] + red[f + 192];
        float cnt = (float)(end - start);
        g_pooled[g * 64 + f] = v / fmaxf(cnt, 1.0f);
    }
}

// ---------------- head ----------------
__global__ void __launch_bounds__(64) k_head(
    const float* __restrict__ Wr1, const float* __restrict__ br1,
    const float* __restrict__ Wr2, const float* __restrict__ br2,
    const float* __restrict__ Wo,  const float* __restrict__ bo,
    float* __restrict__ out)
{
    __shared__ float Ws[64 * 64];
    __shared__ float s_p[64 * 65];
    __shared__ float sb[64];
    __shared__ float sWo[64];

    const int t = threadIdx.x;
    const int gbase = blockIdx.x * 64;

    sb[t]  = br1[t];
    sWo[t] = Wo[t];
#pragma unroll
    for (int i = t; i < 4096; i += 64) Ws[i] = Wr1[i];
#pragma unroll
    for (int i = 4 * t; i < 4096; i += 256) {
        int r = i >> 6, c = i & 63;
        float4 v = *reinterpret_cast<const float4*>(g_pooled + (size_t)(gbase + r) * 64 + c);
        s_p[r * 65 + c + 0] = v.x;
        s_p[r * 65 + c + 1] = v.y;
        s_p[r * 65 + c + 2] = v.z;
        s_p[r * 65 + c + 3] = v.w;
    }
    __syncthreads();

    const float* myrow = s_p + t * 65;
    float tt[64];

#pragma unroll
    for (int jt = 0; jt < 64; jt += 8) {
        float acc[8];
#pragma unroll
        for (int u = 0; u < 8; u++) acc[u] = 0.f;
#pragma unroll 4
        for (int k = 0; k < 64; k++) {
            float a = myrow[k];
            const float* w = Ws + k * 64 + jt;
            float4 w0 = *reinterpret_cast<const float4*>(w);
            float4 w1 = *reinterpret_cast<const float4*>(w + 4);
            acc[0] += a * w0.x; acc[1] += a * w0.y;
            acc[2] += a * w0.z; acc[3] += a * w0.w;
            acc[4] += a * w1.x; acc[5] += a * w1.y;
            acc[6] += a * w1.z; acc[7] += a * w1.w;
        }
#pragma unroll
        for (int u = 0; u < 8; u++) tt[jt + u] = elu(acc[u] + sb[jt + u]);
    }

#pragma unroll
    for (int j = 0; j < 64; j++) s_p[t * 65 + j] = tt[j];
    __syncthreads();
#pragma unroll
    for (int i = t; i < 4096; i += 64) Ws[i] = Wr2[i];
    sb[t] = br2[t];
    __syncthreads();

    float oacc = 0.f;
#pragma unroll
    for (int jt = 0; jt < 64; jt += 8) {
        float acc[8];
#pragma unroll
        for (int u = 0; u < 8; u++) acc[u] = 0.f;
#pragma unroll 4
        for (int k = 0; k < 64; k++) {
            float a = myrow[k];
            const float* w = Ws + k * 64 + jt;
            float4 w0 = *reinterpret_cast<const float4*>(w);
            float4 w1 = *reinterpret_cast<const float4*>(w + 4);
            acc[0] += a * w0.x; acc[1] += a * w0.y;
            acc[2] += a * w0.z; acc[3] += a * w0.w;
            acc[4] += a * w1.x; acc[5] += a * w1.y;
            acc[6] += a * w1.z; acc[7] += a * w1.w;
        }
#pragma unroll
        for (int u = 0; u < 8; u++)
            oacc += (acc[u] + sb[jt + u]) * sWo[jt + u];
    }
    out[gbase + t] = oacc + bo[0];
}

// ---------------- launcher ----------------
extern "C" void kernel_launch(void* const* d_in, const int* in_sizes, int n_in,
                              void* d_out, int out_size) {
    const int*   x     = (const int*)d_in[0];
    const int*   ei    = (const int*)d_in[1];
    const int*   batch = (const int*)d_in[2];
    const float* emb   = (const float*)d_in[3];
    const int* src = ei;
    const int* dst = ei + N_EDGES;
    float* out = (float*)d_out;

    const int TPB = 256;
    const int gnod = (N_NODES + TPB - 1) / TPB;
    const int gedg = (N_EDGES + TPB - 1) / TPB;
    const int gmlp = (N_NODES + 63) / 64;
    const int ggat = (N_NODES + 15) / 16;

    // launch 1: weight pre-split + cnt zeroing (merged)
    k_split_zero<<<gnod, TPB>>>(
        (const float*)d_in[4],  (const float*)d_in[8],   // W1a, W2a
        (const float*)d_in[10], (const float*)d_in[14],  // W1b, W2b
        (const float*)d_in[16], (const float*)d_in[20]); // W1c, W2c
    k_fill<<<gedg, TPB>>>(src, dst);                     // launch 2

    for (int L = 0; L < 3; L++) {
        const float* b1  = (const float*)d_in[4 + 6 * L + 1];
        const float* gam = (const float*)d_in[4 + 6 * L + 2];
        const float* bet = (const float*)d_in[4 + 6 * L + 3];
        const float* b2  = (const float*)d_in[4 + 6 * L + 5];

        if (L == 0)
            k_gather1<<<ggat, 256>>>(x, emb);            // launch 3
        else
            k_gather<<<ggat, 256>>>();
        // launch 4 = k_mlp (layer 1) -> ncu capture slot
        k_mlp<<<gmlp, 128>>>(2 * L, b1, gam, bet, b2, (L < 2) ? 1 : 0);
    }

    k_pool<<<N_GRAPHS, 256>>>(batch);
    k_head<<<2, 64>>>((const float*)d_in[22], (const float*)d_in[23],
                      (const float*)d_in[24], (const float*)d_in[25],
                      (const float*)d_in[26], (const float*)d_in[27],
                      out);
}

// round 14
// speedup vs baseline: 1.3159x; 1.0137x over previous
#include <cuda_runtime.h>
#include <cuda_bf16.h>
#include <cuda_fp16.h>
#include <math.h>

#define N_NODES 100000
#define N_EDGES 1200000
#define N_GRAPHS 128
#define MAX_DEG 64            // Poisson(12): P(deg>=64) ~ 1e-30, guarded anyway
#define AROW 72               // smem row stride in halves (144B): conflict-free fragments

// ---------------- scratch ----------------
__device__ float  g_h[(size_t)N_NODES * 64];            // final-layer output (pool input)
__device__ __align__(16) __half g_hh[(size_t)N_NODES * 64];  // h hi mirror
__device__ __align__(16) __half g_hl[(size_t)N_NODES * 64];  // h lo mirror
__device__ __align__(16) __half g_aggh[(size_t)N_NODES * 64]; // agg hi (pre-split)
__device__ __align__(16) __half g_aggl[(size_t)N_NODES * 64]; // agg lo (pre-split)
__device__ float  g_pooled[N_GRAPHS * 64];

__device__ int g_cnt[N_NODES];
__device__ int g_adj[(size_t)N_NODES * MAX_DEG];

// pre-split transposed weights: [matrix][n*64+k], matrices 2L=W1, 2L+1=W2
__device__ __align__(16) __half g_wh[6 * 4096];
__device__ __align__(16) __half g_wl[6 * 4096];

__device__ __forceinline__ float elu(float v) {
    return v > 0.f ? v : expm1f(v);
}

// ---- HMMA m16n8k16 row.col f16f16f32 ----
__device__ __forceinline__ void mma16816(float* d,
    unsigned a0, unsigned a1, unsigned a2, unsigned a3,
    unsigned b0, unsigned b1)
{
    asm volatile(
        "mma.sync.aligned.m16n8k16.row.col.f32.f16.f16.f32 "
        "{%0,%1,%2,%3}, {%4,%5,%6,%7}, {%8,%9}, {%0,%1,%2,%3};"
        : "+f"(d[0]), "+f"(d[1]), "+f"(d[2]), "+f"(d[3])
        : "r"(a0), "r"(a1), "r"(a2), "r"(a3), "r"(b0), "r"(b1));
}

// ---- ldmatrix m8n8.x4 ----
__device__ __forceinline__ void ldsm4(unsigned& r0, unsigned& r1,
                                      unsigned& r2, unsigned& r3, unsigned addr)
{
    asm volatile("ldmatrix.sync.aligned.m8n8.x4.shared.b16 {%0,%1,%2,%3}, [%4];"
                 : "=r"(r0), "=r"(r1), "=r"(r2), "=r"(r3) : "r"(addr));
}

__device__ __forceinline__ unsigned smem_u32(const void* p) {
    return (unsigned)__cvta_generic_to_shared(p);
}

// split float into fp16 hi + fp16 lo (a ~= hi + lo)
__device__ __forceinline__ void split16(float a, __half& hi, __half& lo) {
    hi = __float2half_rn(a);
    lo = __float2half_rn(a - __half2float(hi));
}

// split float4 into hi/lo half2 pairs
__device__ __forceinline__ void split4(float4 v, uint2& ph, uint2& pl) {
    __half hx, lx, hy, ly, hz, lz, hw, lw;
    split16(v.x, hx, lx); split16(v.y, hy, ly);
    split16(v.z, hz, lz); split16(v.w, hw, lw);
    __half2 h0 = __halves2half2(hx, hy), h1 = __halves2half2(hz, hw);
    __half2 l0 = __halves2half2(lx, ly), l1 = __halves2half2(lz, lw);
    ph.x = *reinterpret_cast<unsigned*>(&h0);
    ph.y = *reinterpret_cast<unsigned*>(&h1);
    pl.x = *reinterpret_cast<unsigned*>(&l0);
    pl.y = *reinterpret_cast<unsigned*>(&l1);
}

// ------- weight pre-split (once per launch) + g_cnt zeroing, merged ---------
__global__ void k_split_zero(const float* __restrict__ w0, const float* __restrict__ w1,
                             const float* __restrict__ w2, const float* __restrict__ w3,
                             const float* __restrict__ w4, const float* __restrict__ w5)
{
    int i = blockIdx.x * blockDim.x + threadIdx.x;
    if (i < N_NODES) g_cnt[i] = 0;
    if (i < 6 * 4096) {
        int m = i >> 12, j = i & 4095;
        const float* W;
        switch (m) {
            case 0: W = w0; break;
            case 1: W = w1; break;
            case 2: W = w2; break;
            case 3: W = w3; break;
            case 4: W = w4; break;
            default: W = w5; break;
        }
        float v = __ldg(W + j);
        int k = j >> 6, n = j & 63;           // W[k][n] -> Wt[n][k]
        __half hi, lo;
        split16(v, hi, lo);
        g_wh[m * 4096 + n * 64 + k] = hi;
        g_wl[m * 4096 + n * 64 + k] = lo;
    }
}

__global__ void k_fill(const int* __restrict__ src, const int* __restrict__ dst) {
    int e = blockIdx.x * blockDim.x + threadIdx.x;
    if (e >= N_EDGES) return;
    int d = __ldg(dst + e);
    int slot = atomicAdd(&g_cnt[d], 1);
    if (slot < MAX_DEG)
        g_adj[(size_t)d * MAX_DEG + slot] = __ldg(src + e);
}

// ------- layer-1 gather from embedding, writes pre-split agg ---------------
__global__ void __launch_bounds__(256) k_gather1(const int* __restrict__ x,
                                                 const float* __restrict__ emb) {
    int t = threadIdx.x;
    int n = blockIdx.x * 16 + (t >> 4);
    int c = t & 15;
    if (n >= N_NODES) return;
    const float4* __restrict__ e4 = reinterpret_cast<const float4*>(emb);
    int xn = __ldg(x + n);
    float4 acc = e4[(size_t)xn * 16 + c];
    const int* __restrict__ alist = g_adj + (size_t)n * MAX_DEG;
    int e = min(g_cnt[n], MAX_DEG);
    for (int i = 0; i < e; i++) {
        int s = __ldg(alist + i);
        int xs = __ldg(x + s);
        float4 v = e4[(size_t)xs * 16 + c];
        acc.x += v.x; acc.y += v.y; acc.z += v.z; acc.w += v.w;
    }
    uint2 ph, pl;
    split4(acc, ph, pl);
    reinterpret_cast<uint2*>(g_aggh)[(size_t)n * 16 + c] = ph;
    reinterpret_cast<uint2*>(g_aggl)[(size_t)n * 16 + c] = pl;
}

// ------- gather (layers 2-3): agg[n] = (hh+hl)[n] + sum hh[nb], pre-split ---
__global__ void __launch_bounds__(256) k_gather() {
    int t = threadIdx.x;
    int n = blockIdx.x * 16 + (t >> 4);
    int c = t & 15;
    if (n >= N_NODES) return;
    const uint2* __restrict__ hh2 = reinterpret_cast<const uint2*>(g_hh);
    const uint2* __restrict__ hl2 = reinterpret_cast<const uint2*>(g_hl);
    uint2 sh = __ldg(&hh2[(size_t)n * 16 + c]);
    uint2 sl = __ldg(&hl2[(size_t)n * 16 + c]);
    float2 a0 = __half22float2(*reinterpret_cast<__half2*>(&sh.x));
    float2 a1 = __half22float2(*reinterpret_cast<__half2*>(&sh.y));
    float2 b0 = __half22float2(*reinterpret_cast<__half2*>(&sl.x));
    float2 b1 = __half22float2(*reinterpret_cast<__half2*>(&sl.y));
    float4 acc = make_float4(a0.x + b0.x, a0.y + b0.y, a1.x + b1.x, a1.y + b1.y);

    const int* __restrict__ alist = g_adj + (size_t)n * MAX_DEG;
    int e = min(g_cnt[n], MAX_DEG);
    int nxt = (e > 0) ? __ldg(alist) : 0;
    for (int i = 0; i < e; i++) {
        int cur = nxt;
        if (i + 1 < e) nxt = __ldg(alist + i + 1);
        uint2 v = __ldg(&hh2[(size_t)cur * 16 + c]);
        float2 f0 = __half22float2(*reinterpret_cast<__half2*>(&v.x));
        float2 f1 = __half22float2(*reinterpret_cast<__half2*>(&v.y));
        acc.x += f0.x; acc.y += f0.y; acc.z += f1.x; acc.w += f1.y;
    }
    uint2 ph, pl;
    split4(acc, ph, pl);
    reinterpret_cast<uint2*>(g_aggh)[(size_t)n * 16 + c] = ph;
    reinterpret_cast<uint2*>(g_aggl)[(size_t)n * 16 + c] = pl;
}

// ---------------- fused MLP+BN+ELU via split-fp16 HMMA + ldmatrix -----------
// 256 threads = 8 warps; warp w owns rows 16*(w>>1)..+15, n-half (w&1)*32.
// Per-warp: 4 n-blocks, 48 MMAs. 2 warps share each 16-row group.
__global__ void __launch_bounds__(256) k_mlp(
    int widx,
    const float* __restrict__ b1,
    const float* __restrict__ gam, const float* __restrict__ bet,
    const float* __restrict__ b2,
    int write_fp16)
{
    __shared__ __half sAh[64 * AROW];
    __shared__ __half sAl[64 * AROW];
    __shared__ __half sWh[64 * AROW];
    __shared__ __half sWl[64 * AROW];
    __shared__ float sb1[64], ssc[64], sbe[64], sb2[64];

    const int t = threadIdx.x;
    const int w = t >> 5;
    const int lane = t & 31;
    const int g = lane >> 2;       // 0..7
    const int tq = lane & 3;       // 0..3
    const int base = blockIdx.x * 64;
    const int rg16 = (w >> 1) * 16;      // row group
    const int nh   = (w & 1) * 32;       // n-half column offset

    if (t < 64) {
        sb1[t] = b1[t];
        ssc[t] = gam[t] * rsqrtf(1.0f + 1e-5f);
        sbe[t] = bet[t];
        sb2[t] = b2[t];
    }

    // stage W1^T hi/lo: pure vectorized copy (8 halves per uint4)
    {
        const uint4* s1h = reinterpret_cast<const uint4*>(g_wh + (size_t)widx * 4096);
        const uint4* s1l = reinterpret_cast<const uint4*>(g_wl + (size_t)widx * 4096);
#pragma unroll
        for (int i = t; i < 512; i += 256) {
            int n = i >> 3, kc = i & 7;
            *reinterpret_cast<uint4*>(sWh + n * AROW + kc * 8) = s1h[i];
            *reinterpret_cast<uint4*>(sWl + n * AROW + kc * 8) = s1l[i];
        }
    }
    // stage activations: pure vectorized copy of pre-split hi/lo
    {
        const uint4* ah4 = reinterpret_cast<const uint4*>(g_aggh);
        const uint4* al4 = reinterpret_cast<const uint4*>(g_aggl);
        const uint4 z = make_uint4(0, 0, 0, 0);
#pragma unroll
        for (int i = t; i < 512; i += 256) {
            int r = i >> 3, c8 = i & 7;
            int row = base + r;
            uint4 vh = z, vl = z;
            if (row < N_NODES) {
                vh = ah4[(size_t)row * 8 + c8];
                vl = al4[(size_t)row * 8 + c8];
            }
            *reinterpret_cast<uint4*>(sAh + r * AROW + c8 * 8) = vh;
            *reinterpret_cast<uint4*>(sAl + r * AROW + c8 * 8) = vl;
        }
    }
    __syncthreads();

    const int r0 = rg16 + g;            // local row (first half)

    // ---- ldmatrix lane address setup ----
    // A: lane row = rg16 + (lane & 15), k offset = (lane >> 4) * 8
    const int rowA  = rg16 + (lane & 15);
    const int koffA = (lane >> 4) * 8;
    unsigned aAh = smem_u32(sAh + rowA * AROW + koffA);
    unsigned aAl = smem_u32(sAl + rowA * AROW + koffA);
    // B: warp covers n in [nh, nh+32); pair p covers local nb=2p,2p+1
    //    lane n = nh + 16p + (lane&7) + ((lane>>4)<<3), k off = ((lane>>3)&1)*8
    const int nB    = nh + (lane & 7) + ((lane >> 4) << 3);
    const int koffB = ((lane >> 3) & 1) * 8;
    unsigned aBh0 = smem_u32(sWh + nB * AROW + koffB);
    unsigned aBl0 = smem_u32(sWl + nB * AROW + koffB);
    const unsigned pStride = 16 * AROW * 2;   // 16 n-rows per pair, bytes

    float acc[4][4];
#pragma unroll
    for (int nb = 0; nb < 4; nb++)
#pragma unroll
        for (int u = 0; u < 4; u++) acc[nb][u] = 0.f;

    // ---------- GEMM1 (split HMMA, ldmatrix fragments) ----------
#pragma unroll
    for (int kb = 0; kb < 4; kb++) {
        unsigned ah0, ah1, ah2, ah3, al0, al1, al2, al3;
        ldsm4(ah0, ah1, ah2, ah3, aAh + kb * 32);
        ldsm4(al0, al1, al2, al3, aAl + kb * 32);
#pragma unroll
        for (int p = 0; p < 2; p++) {
            unsigned bh0, bh1, bh2, bh3, bl0, bl1, bl2, bl3;
            ldsm4(bh0, bh1, bh2, bh3, aBh0 + p * pStride + kb * 32);
            ldsm4(bl0, bl1, bl2, bl3, aBl0 + p * pStride + kb * 32);
            mma16816(acc[2 * p],     ah0, ah1, ah2, ah3, bh0, bh1);
            mma16816(acc[2 * p],     ah0, ah1, ah2, ah3, bl0, bl1);
            mma16816(acc[2 * p],     al0, al1, al2, al3, bh0, bh1);
            mma16816(acc[2 * p + 1], ah0, ah1, ah2, ah3, bh2, bh3);
            mma16816(acc[2 * p + 1], ah0, ah1, ah2, ah3, bl2, bl3);
            mma16816(acc[2 * p + 1], al0, al1, al2, al3, bh2, bh3);
        }
    }

    // epilogue 1: BN affine + ELU -> own rows/cols, split fp16
#pragma unroll
    for (int nb = 0; nb < 4; nb++) {
        int j = nh + 8 * nb + 2 * tq;
        float2 bv = *reinterpret_cast<const float2*>(&sb1[j]);
        float2 sv = *reinterpret_cast<const float2*>(&ssc[j]);
        float2 ev = *reinterpret_cast<const float2*>(&sbe[j]);
        float v00 = elu((acc[nb][0] + bv.x) * sv.x + ev.x);
        float v01 = elu((acc[nb][1] + bv.y) * sv.y + ev.y);
        float v10 = elu((acc[nb][2] + bv.x) * sv.x + ev.x);
        float v11 = elu((acc[nb][3] + bv.y) * sv.y + ev.y);
        __half h00, l00, h01, l01, h10, l10, h11, l11;
        split16(v00, h00, l00); split16(v01, h01, l01);
        split16(v10, h10, l10); split16(v11, h11, l11);
        *reinterpret_cast<__half2*>(sAh + r0 * AROW + j)       = __halves2half2(h00, h01);
        *reinterpret_cast<__half2*>(sAl + r0 * AROW + j)       = __halves2half2(l00, l01);
        *reinterpret_cast<__half2*>(sAh + (r0 + 8) * AROW + j) = __halves2half2(h10, h11);
        *reinterpret_cast<__half2*>(sAl + (r0 + 8) * AROW + j) = __halves2half2(l10, l11);
    }
    __syncthreads();   // all warps done reading W1 tiles

    // stage W2^T hi/lo (pure copy)
    {
        const uint4* s2h = reinterpret_cast<const uint4*>(g_wh + (size_t)(widx + 1) * 4096);
        const uint4* s2l = reinterpret_cast<const uint4*>(g_wl + (size_t)(widx + 1) * 4096);
#pragma unroll
        for (int i = t; i < 512; i += 256) {
            int n = i >> 3, kc = i & 7;
            *reinterpret_cast<uint4*>(sWh + n * AROW + kc * 8) = s2h[i];
            *reinterpret_cast<uint4*>(sWl + n * AROW + kc * 8) = s2l[i];
        }
    }
    __syncthreads();

#pragma unroll
    for (int nb = 0; nb < 4; nb++)
#pragma unroll
        for (int u = 0; u < 4; u++) acc[nb][u] = 0.f;

    // ---------- GEMM2 (split HMMA, ldmatrix fragments) ----------
#pragma unroll
    for (int kb = 0; kb < 4; kb++) {
        unsigned ah0, ah1, ah2, ah3, al0, al1, al2, al3;
        ldsm4(ah0, ah1, ah2, ah3, aAh + kb * 32);
        ldsm4(al0, al1, al2, al3, aAl + kb * 32);
#pragma unroll
        for (int p = 0; p < 2; p++) {
            unsigned bh0, bh1, bh2, bh3, bl0, bl1, bl2, bl3;
            ldsm4(bh0, bh1, bh2, bh3, aBh0 + p * pStride + kb * 32);
            ldsm4(bl0, bl1, bl2, bl3, aBl0 + p * pStride + kb * 32);
            mma16816(acc[2 * p],     ah0, ah1, ah2, ah3, bh0, bh1);
            mma16816(acc[2 * p],     ah0, ah1, ah2, ah3, bl0, bl1);
            mma16816(acc[2 * p],     al0, al1, al2, al3, bh0, bh1);
            mma16816(acc[2 * p + 1], ah0, ah1, ah2, ah3, bh2, bh3);
            mma16816(acc[2 * p + 1], ah0, ah1, ah2, ah3, bl2, bl3);
            mma16816(acc[2 * p + 1], al0, al1, al2, al3, bh2, bh3);
        }
    }

    // epilogue 2: bias + outer ELU
    // layers 1-2 (write_fp16): write split hi/lo mirrors only
    // final layer: write fp32 g_h only (pool input)
    int grow0 = base + r0;
    int grow1 = grow0 + 8;
#pragma unroll
    for (int nb = 0; nb < 4; nb++) {
        int j = nh + 8 * nb + 2 * tq;
        float2 bv = *reinterpret_cast<const float2*>(&sb2[j]);
        float o00 = elu(acc[nb][0] + bv.x);
        float o01 = elu(acc[nb][1] + bv.y);
        float o10 = elu(acc[nb][2] + bv.x);
        float o11 = elu(acc[nb][3] + bv.y);
        if (write_fp16) {
            if (grow0 < N_NODES) {
                __half h0, l0, h1, l1;
                split16(o00, h0, l0); split16(o01, h1, l1);
                *reinterpret_cast<__half2*>(g_hh + (size_t)grow0 * 64 + j) = __halves2half2(h0, h1);
                *reinterpret_cast<__half2*>(g_hl + (size_t)grow0 * 64 + j) = __halves2half2(l0, l1);
            }
            if (grow1 < N_NODES) {
                __half h0, l0, h1, l1;
                split16(o10, h0, l0); split16(o11, h1, l1);
                *reinterpret_cast<__half2*>(g_hh + (size_t)grow1 * 64 + j) = __halves2half2(h0, h1);
                *reinterpret_cast<__half2*>(g_hl + (size_t)grow1 * 64 + j) = __halves2half2(l0, l1);
            }
        } else {
            if (grow0 < N_NODES)
                *reinterpret_cast<float2*>(g_h + (size_t)grow0 * 64 + j) = make_float2(o00, o01);
            if (grow1 < N_NODES)
                *reinterpret_cast<float2*>(g_h + (size_t)grow1 * 64 + j) = make_float2(o10, o11);
        }
    }
}

// ---------------- mean pool (bounds inlined) ----------------
__global__ void k_pool(const int* __restrict__ batch) {
    int g = blockIdx.x;
    __shared__ int sbounds[2];
    if (threadIdx.x < 2) {
        int target = g + threadIdx.x;       // first batch[m] >= target
        int lo = 0, hi = N_NODES;
        while (lo < hi) {
            int mid = (lo + hi) >> 1;
            if (__ldg(batch + mid) < target) lo = mid + 1; else hi = mid;
        }
        sbounds[threadIdx.x] = lo;
    }
    __syncthreads();
    int start = sbounds[0], end = sbounds[1];

    int f = threadIdx.x & 63;
    int s = threadIdx.x >> 6;
    float acc = 0.f;
    for (int i = start + s; i < end; i += 4)
        acc += g_h[(size_t)i * 64 + f];
    __shared__ float red[256];
    red[threadIdx.x] = acc;
    __syncthreads();
    if (s == 0) {
        float v = red[f] + red[f + 64] + red[f + 128] + red[f + 192];
        float cnt = (float)(end - start);
        g_pooled[g * 64 + f] = v / fmaxf(cnt, 1.0f);
    }
}

// ---------------- head ----------------
__global__ void __launch_bounds__(64) k_head(
    const float* __restrict__ Wr1, const float* __restrict__ br1,
    const float* __restrict__ Wr2, const float* __restrict__ br2,
    const float* __restrict__ Wo,  const float* __restrict__ bo,
    float* __restrict__ out)
{
    __shared__ float Ws[64 * 64];
    __shared__ float s_p[64 * 65];
    __shared__ float sb[64];
    __shared__ float sWo[64];

    const int t = threadIdx.x;
    const int gbase = blockIdx.x * 64;

    sb[t]  = br1[t];
    sWo[t] = Wo[t];
#pragma unroll
    for (int i = t; i < 4096; i += 64) Ws[i] = Wr1[i];
#pragma unroll
    for (int i = 4 * t; i < 4096; i += 256) {
        int r = i >> 6, c = i & 63;
        float4 v = *reinterpret_cast<const float4*>(g_pooled + (size_t)(gbase + r) * 64 + c);
        s_p[r * 65 + c + 0] = v.x;
        s_p[r * 65 + c + 1] = v.y;
        s_p[r * 65 + c + 2] = v.z;
        s_p[r * 65 + c + 3] = v.w;
    }
    __syncthreads();

    const float* myrow = s_p + t * 65;
    float tt[64];

#pragma unroll
    for (int jt = 0; jt < 64; jt += 8) {
        float acc[8];
#pragma unroll
        for (int u = 0; u < 8; u++) acc[u] = 0.f;
#pragma unroll 4
        for (int k = 0; k < 64; k++) {
            float a = myrow[k];
            const float* w = Ws + k * 64 + jt;
            float4 w0 = *reinterpret_cast<const float4*>(w);
            float4 w1 = *reinterpret_cast<const float4*>(w + 4);
            acc[0] += a * w0.x; acc[1] += a * w0.y;
            acc[2] += a * w0.z; acc[3] += a * w0.w;
            acc[4] += a * w1.x; acc[5] += a * w1.y;
            acc[6] += a * w1.z; acc[7] += a * w1.w;
        }
#pragma unroll
        for (int u = 0; u < 8; u++) tt[jt + u] = elu(acc[u] + sb[jt + u]);
    }

#pragma unroll
    for (int j = 0; j < 64; j++) s_p[t * 65 + j] = tt[j];
    __syncthreads();
#pragma unroll
    for (int i = t; i < 4096; i += 64) Ws[i] = Wr2[i];
    sb[t] = br2[t];
    __syncthreads();

    float oacc = 0.f;
#pragma unroll
    for (int jt = 0; jt < 64; jt += 8) {
        float acc[8];
#pragma unroll
        for (int u = 0; u < 8; u++) acc[u] = 0.f;
#pragma unroll 4
        for (int k = 0; k < 64; k++) {
            float a = myrow[k];
            const float* w = Ws + k * 64 + jt;
            float4 w0 = *reinterpret_cast<const float4*>(w);
            float4 w1 = *reinterpret_cast<const float4*>(w + 4);
            acc[0] += a * w0.x; acc[1] += a * w0.y;
            acc[2] += a * w0.z; acc[3] += a * w0.w;
            acc[4] += a * w1.x; acc[5] += a * w1.y;
            acc[6] += a * w1.z; acc[7] += a * w1.w;
        }
#pragma unroll
        for (int u = 0; u < 8; u++)
            oacc += (acc[u] + sb[jt + u]) * sWo[jt + u];
    }
    out[gbase + t] = oacc + bo[0];
}

// ---------------- launcher ----------------
extern "C" void kernel_launch(void* const* d_in, const int* in_sizes, int n_in,
                              void* d_out, int out_size) {
    const int*   x     = (const int*)d_in[0];
    const int*   ei    = (const int*)d_in[1];
    const int*   batch = (const int*)d_in[2];
    const float* emb   = (const float*)d_in[3];
    const int* src = ei;
    const int* dst = ei + N_EDGES;
    float* out = (float*)d_out;

    const int TPB = 256;
    const int gnod = (N_NODES + TPB - 1) / TPB;
    const int gedg = (N_EDGES + TPB - 1) / TPB;
    const int gmlp = (N_NODES + 63) / 64;
    const int ggat = (N_NODES + 15) / 16;

    // launch 1: weight pre-split + cnt zeroing (merged)
    k_split_zero<<<gnod, TPB>>>(
        (const float*)d_in[4],  (const float*)d_in[8],   // W1a, W2a
        (const float*)d_in[10], (const float*)d_in[14],  // W1b, W2b
        (const float*)d_in[16], (const float*)d_in[20]); // W1c, W2c
    k_fill<<<gedg, TPB>>>(src, dst);                     // launch 2

    for (int L = 0; L < 3; L++) {
        const float* b1  = (const float*)d_in[4 + 6 * L + 1];
        const float* gam = (const float*)d_in[4 + 6 * L + 2];
        const float* bet = (const float*)d_in[4 + 6 * L + 3];
        const float* b2  = (const float*)d_in[4 + 6 * L + 5];

        if (L == 0)
            k_gather1<<<ggat, 256>>>(x, emb);            // launch 3
        else
            k_gather<<<ggat, 256>>>();
        // launch 4 = k_mlp (layer 1) -> ncu capture slot
        k_mlp<<<gmlp, 256>>>(2 * L, b1, gam, bet, b2, (L < 2) ? 1 : 0);
    }

    k_pool<<<N_GRAPHS, 256>>>(batch);
    k_head<<<2, 64>>>((const float*)d_in[22], (const float*)d_in[23],
                      (const float*)d_in[24], (const float*)d_in[25],
                      (const float*)d_in[26], (const float*)d_in[27],
                      out);
}

// round 15
// speedup vs baseline: 1.3250x; 1.0069x over previous
#include <cuda_runtime.h>
#include <cuda_bf16.h>
#include <cuda_fp16.h>
#include <math.h>

#define N_NODES 100000
#define N_EDGES 1200000
#define N_GRAPHS 128
#define MAX_DEG 64            // Poisson(12): P(deg>=64) ~ 1e-30, guarded anyway
#define AROW 72               // smem row stride in halves (144B): conflict-free fragments

// ---------------- scratch ----------------
__device__ float  g_h[(size_t)N_NODES * 64];            // final-layer output (pool input)
__device__ __align__(16) __half g_hh[(size_t)N_NODES * 64];  // h hi mirror
__device__ __align__(16) __half g_hl[(size_t)N_NODES * 64];  // h lo mirror
__device__ __align__(16) __half g_aggh[(size_t)N_NODES * 64]; // agg hi (pre-split)
__device__ __align__(16) __half g_aggl[(size_t)N_NODES * 64]; // agg lo (pre-split)
__device__ float  g_pooled[N_GRAPHS * 64];

__device__ int g_cnt[N_NODES];
__device__ int g_adj[(size_t)N_NODES * MAX_DEG];

// pre-split transposed weights: [matrix][n*64+k], matrices 2L=W1, 2L+1=W2
__device__ __align__(16) __half g_wh[6 * 4096];
__device__ __align__(16) __half g_wl[6 * 4096];

__device__ __forceinline__ float elu(float v) {
    return v > 0.f ? v : expm1f(v);
}

// ---- HMMA m16n8k16 row.col f16f16f32 ----
__device__ __forceinline__ void mma16816(float* d,
    unsigned a0, unsigned a1, unsigned a2, unsigned a3,
    unsigned b0, unsigned b1)
{
    asm volatile(
        "mma.sync.aligned.m16n8k16.row.col.f32.f16.f16.f32 "
        "{%0,%1,%2,%3}, {%4,%5,%6,%7}, {%8,%9}, {%0,%1,%2,%3};"
        : "+f"(d[0]), "+f"(d[1]), "+f"(d[2]), "+f"(d[3])
        : "r"(a0), "r"(a1), "r"(a2), "r"(a3), "r"(b0), "r"(b1));
}

// ---- ldmatrix m8n8.x4 ----
__device__ __forceinline__ void ldsm4(unsigned& r0, unsigned& r1,
                                      unsigned& r2, unsigned& r3, unsigned addr)
{
    asm volatile("ldmatrix.sync.aligned.m8n8.x4.shared.b16 {%0,%1,%2,%3}, [%4];"
                 : "=r"(r0), "=r"(r1), "=r"(r2), "=r"(r3) : "r"(addr));
}

__device__ __forceinline__ unsigned smem_u32(const void* p) {
    return (unsigned)__cvta_generic_to_shared(p);
}

__device__ __forceinline__ void bar_sync(int id, int cnt) {
    asm volatile("bar.sync %0, %1;" :: "r"(id), "r"(cnt) : "memory");
}

// split float into fp16 hi + fp16 lo (a ~= hi + lo)
__device__ __forceinline__ void split16(float a, __half& hi, __half& lo) {
    hi = __float2half_rn(a);
    lo = __float2half_rn(a - __half2float(hi));
}

// split float4 into hi/lo half2 pairs
__device__ __forceinline__ void split4(float4 v, uint2& ph, uint2& pl) {
    __half hx, lx, hy, ly, hz, lz, hw, lw;
    split16(v.x, hx, lx); split16(v.y, hy, ly);
    split16(v.z, hz, lz); split16(v.w, hw, lw);
    __half2 h0 = __halves2half2(hx, hy), h1 = __halves2half2(hz, hw);
    __half2 l0 = __halves2half2(lx, ly), l1 = __halves2half2(lz, lw);
    ph.x = *reinterpret_cast<unsigned*>(&h0);
    ph.y = *reinterpret_cast<unsigned*>(&h1);
    pl.x = *reinterpret_cast<unsigned*>(&l0);
    pl.y = *reinterpret_cast<unsigned*>(&l1);
}

// ------- weight pre-split (once per launch) + g_cnt zeroing, merged ---------
__global__ void k_split_zero(const float* __restrict__ w0, const float* __restrict__ w1,
                             const float* __restrict__ w2, const float* __restrict__ w3,
                             const float* __restrict__ w4, const float* __restrict__ w5)
{
    int i = blockIdx.x * blockDim.x + threadIdx.x;
    if (i < N_NODES) g_cnt[i] = 0;
    if (i < 6 * 4096) {
        int m = i >> 12, j = i & 4095;
        const float* W;
        switch (m) {
            case 0: W = w0; break;
            case 1: W = w1; break;
            case 2: W = w2; break;
            case 3: W = w3; break;
            case 4: W = w4; break;
            default: W = w5; break;
        }
        float v = __ldg(W + j);
        int k = j >> 6, n = j & 63;           // W[k][n] -> Wt[n][k]
        __half hi, lo;
        split16(v, hi, lo);
        g_wh[m * 4096 + n * 64 + k] = hi;
        g_wl[m * 4096 + n * 64 + k] = lo;
    }
}

__global__ void k_fill(const int* __restrict__ src, const int* __restrict__ dst) {
    int e = blockIdx.x * blockDim.x + threadIdx.x;
    if (e >= N_EDGES) return;
    int d = __ldg(dst + e);
    int slot = atomicAdd(&g_cnt[d], 1);
    if (slot < MAX_DEG)
        g_adj[(size_t)d * MAX_DEG + slot] = __ldg(src + e);
}

// ------- layer-1 gather from embedding, writes pre-split agg ---------------
__global__ void __launch_bounds__(256) k_gather1(const int* __restrict__ x,
                                                 const float* __restrict__ emb) {
    int t = threadIdx.x;
    int n = blockIdx.x * 16 + (t >> 4);
    int c = t & 15;
    if (n >= N_NODES) return;
    const float4* __restrict__ e4 = reinterpret_cast<const float4*>(emb);
    int xn = __ldg(x + n);
    float4 acc = e4[(size_t)xn * 16 + c];
    const int* __restrict__ alist = g_adj + (size_t)n * MAX_DEG;
    int e = min(g_cnt[n], MAX_DEG);
    for (int i = 0; i < e; i++) {
        int s = __ldg(alist + i);
        int xs = __ldg(x + s);
        float4 v = e4[(size_t)xs * 16 + c];
        acc.x += v.x; acc.y += v.y; acc.z += v.z; acc.w += v.w;
    }
    uint2 ph, pl;
    split4(acc, ph, pl);
    reinterpret_cast<uint2*>(g_aggh)[(size_t)n * 16 + c] = ph;
    reinterpret_cast<uint2*>(g_aggl)[(size_t)n * 16 + c] = pl;
}

// ------- gather (layers 2-3): agg[n] = (hh+hl)[n] + sum hh[nb], pre-split ---
__global__ void __launch_bounds__(256) k_gather() {
    int t = threadIdx.x;
    int n = blockIdx.x * 16 + (t >> 4);
    int c = t & 15;
    if (n >= N_NODES) return;
    const uint2* __restrict__ hh2 = reinterpret_cast<const uint2*>(g_hh);
    const uint2* __restrict__ hl2 = reinterpret_cast<const uint2*>(g_hl);
    uint2 sh = __ldg(&hh2[(size_t)n * 16 + c]);
    uint2 sl = __ldg(&hl2[(size_t)n * 16 + c]);
    float2 a0 = __half22float2(*reinterpret_cast<__half2*>(&sh.x));
    float2 a1 = __half22float2(*reinterpret_cast<__half2*>(&sh.y));
    float2 b0 = __half22float2(*reinterpret_cast<__half2*>(&sl.x));
    float2 b1 = __half22float2(*reinterpret_cast<__half2*>(&sl.y));
    float4 acc = make_float4(a0.x + b0.x, a0.y + b0.y, a1.x + b1.x, a1.y + b1.y);

    const int* __restrict__ alist = g_adj + (size_t)n * MAX_DEG;
    int e = min(g_cnt[n], MAX_DEG);
    int nxt = (e > 0) ? __ldg(alist) : 0;
    for (int i = 0; i < e; i++) {
        int cur = nxt;
        if (i + 1 < e) nxt = __ldg(alist + i + 1);
        uint2 v = __ldg(&hh2[(size_t)cur * 16 + c]);
        float2 f0 = __half22float2(*reinterpret_cast<__half2*>(&v.x));
        float2 f1 = __half22float2(*reinterpret_cast<__half2*>(&v.y));
        acc.x += f0.x; acc.y += f0.y; acc.z += f1.x; acc.w += f1.y;
    }
    uint2 ph, pl;
    split4(acc, ph, pl);
    reinterpret_cast<uint2*>(g_aggh)[(size_t)n * 16 + c] = ph;
    reinterpret_cast<uint2*>(g_aggl)[(size_t)n * 16 + c] = pl;
}

// ---------------- fused MLP+BN+ELU via split-fp16 HMMA + ldmatrix -----------
// 256 threads = 8 warps; warp w owns rows 16*(w>>1)..+15, n-half (w&1)*32.
// W1 AND W2 staged upfront; mid-kernel sync is a 64-thread named barrier
// per warp pair (the only epi1->GEMM2 dependency is within the pair).
__global__ void __launch_bounds__(256) k_mlp(
    int widx,
    const float* __restrict__ b1,
    const float* __restrict__ gam, const float* __restrict__ bet,
    const float* __restrict__ b2,
    int write_fp16)
{
    __shared__ __half sAh[64 * AROW];
    __shared__ __half sAl[64 * AROW];
    __shared__ __half sW1h[64 * AROW];
    __shared__ __half sW1l[64 * AROW];
    __shared__ __half sW2h[64 * AROW];
    __shared__ __half sW2l[64 * AROW];
    __shared__ float sb1[64], ssc[64], sbe[64], sb2[64];

    const int t = threadIdx.x;
    const int w = t >> 5;
    const int lane = t & 31;
    const int g = lane >> 2;       // 0..7
    const int tq = lane & 3;       // 0..3
    const int base = blockIdx.x * 64;
    const int rg16 = (w >> 1) * 16;      // row group
    const int nh   = (w & 1) * 32;       // n-half column offset
    const int pairBar = 1 + (w >> 1);    // named barrier id per warp pair

    if (t < 64) {
        sb1[t] = b1[t];
        ssc[t] = gam[t] * rsqrtf(1.0f + 1e-5f);
        sbe[t] = bet[t];
        sb2[t] = b2[t];
    }

    // stage W1^T and W2^T hi/lo upfront: pure vectorized copy
    {
        const uint4* s1h = reinterpret_cast<const uint4*>(g_wh + (size_t)widx * 4096);
        const uint4* s1l = reinterpret_cast<const uint4*>(g_wl + (size_t)widx * 4096);
        const uint4* s2h = reinterpret_cast<const uint4*>(g_wh + (size_t)(widx + 1) * 4096);
        const uint4* s2l = reinterpret_cast<const uint4*>(g_wl + (size_t)(widx + 1) * 4096);
#pragma unroll
        for (int i = t; i < 512; i += 256) {
            int n = i >> 3, kc = i & 7;
            *reinterpret_cast<uint4*>(sW1h + n * AROW + kc * 8) = s1h[i];
            *reinterpret_cast<uint4*>(sW1l + n * AROW + kc * 8) = s1l[i];
            *reinterpret_cast<uint4*>(sW2h + n * AROW + kc * 8) = s2h[i];
            *reinterpret_cast<uint4*>(sW2l + n * AROW + kc * 8) = s2l[i];
        }
    }
    // stage activations: pure vectorized copy of pre-split hi/lo
    {
        const uint4* ah4 = reinterpret_cast<const uint4*>(g_aggh);
        const uint4* al4 = reinterpret_cast<const uint4*>(g_aggl);
        const uint4 z = make_uint4(0, 0, 0, 0);
#pragma unroll
        for (int i = t; i < 512; i += 256) {
            int r = i >> 3, c8 = i & 7;
            int row = base + r;
            uint4 vh = z, vl = z;
            if (row < N_NODES) {
                vh = ah4[(size_t)row * 8 + c8];
                vl = al4[(size_t)row * 8 + c8];
            }
            *reinterpret_cast<uint4*>(sAh + r * AROW + c8 * 8) = vh;
            *reinterpret_cast<uint4*>(sAl + r * AROW + c8 * 8) = vl;
        }
    }
    __syncthreads();

    const int r0 = rg16 + g;            // local row (first half)

    // ---- ldmatrix lane address setup ----
    const int rowA  = rg16 + (lane & 15);
    const int koffA = (lane >> 4) * 8;
    unsigned aAh = smem_u32(sAh + rowA * AROW + koffA);
    unsigned aAl = smem_u32(sAl + rowA * AROW + koffA);
    const int nB    = nh + (lane & 7) + ((lane >> 4) << 3);
    const int koffB = ((lane >> 3) & 1) * 8;
    unsigned aB1h = smem_u32(sW1h + nB * AROW + koffB);
    unsigned aB1l = smem_u32(sW1l + nB * AROW + koffB);
    unsigned aB2h = smem_u32(sW2h + nB * AROW + koffB);
    unsigned aB2l = smem_u32(sW2l + nB * AROW + koffB);
    const unsigned pStride = 16 * AROW * 2;   // 16 n-rows per pair, bytes

    float acc[4][4];
#pragma unroll
    for (int nb = 0; nb < 4; nb++)
#pragma unroll
        for (int u = 0; u < 4; u++) acc[nb][u] = 0.f;

    // ---------- GEMM1 (split HMMA, ldmatrix fragments) ----------
#pragma unroll
    for (int kb = 0; kb < 4; kb++) {
        unsigned ah0, ah1, ah2, ah3, al0, al1, al2, al3;
        ldsm4(ah0, ah1, ah2, ah3, aAh + kb * 32);
        ldsm4(al0, al1, al2, al3, aAl + kb * 32);
#pragma unroll
        for (int p = 0; p < 2; p++) {
            unsigned bh0, bh1, bh2, bh3, bl0, bl1, bl2, bl3;
            ldsm4(bh0, bh1, bh2, bh3, aB1h + p * pStride + kb * 32);
            ldsm4(bl0, bl1, bl2, bl3, aB1l + p * pStride + kb * 32);
            mma16816(acc[2 * p],     ah0, ah1, ah2, ah3, bh0, bh1);
            mma16816(acc[2 * p],     ah0, ah1, ah2, ah3, bl0, bl1);
            mma16816(acc[2 * p],     al0, al1, al2, al3, bh0, bh1);
            mma16816(acc[2 * p + 1], ah0, ah1, ah2, ah3, bh2, bh3);
            mma16816(acc[2 * p + 1], ah0, ah1, ah2, ah3, bl2, bl3);
            mma16816(acc[2 * p + 1], al0, al1, al2, al3, bh2, bh3);
        }
    }

    // epilogue 1: BN affine + ELU -> own rows/cols, split fp16
#pragma unroll
    for (int nb = 0; nb < 4; nb++) {
        int j = nh + 8 * nb + 2 * tq;
        float2 bv = *reinterpret_cast<const float2*>(&sb1[j]);
        float2 sv = *reinterpret_cast<const float2*>(&ssc[j]);
        float2 ev = *reinterpret_cast<const float2*>(&sbe[j]);
        float v00 = elu((acc[nb][0] + bv.x) * sv.x + ev.x);
        float v01 = elu((acc[nb][1] + bv.y) * sv.y + ev.y);
        float v10 = elu((acc[nb][2] + bv.x) * sv.x + ev.x);
        float v11 = elu((acc[nb][3] + bv.y) * sv.y + ev.y);
        __half h00, l00, h01, l01, h10, l10, h11, l11;
        split16(v00, h00, l00); split16(v01, h01, l01);
        split16(v10, h10, l10); split16(v11, h11, l11);
        *reinterpret_cast<__half2*>(sAh + r0 * AROW + j)       = __halves2half2(h00, h01);
        *reinterpret_cast<__half2*>(sAl + r0 * AROW + j)       = __halves2half2(l00, l01);
        *reinterpret_cast<__half2*>(sAh + (r0 + 8) * AROW + j) = __halves2half2(h10, h11);
        *reinterpret_cast<__half2*>(sAl + (r0 + 8) * AROW + j) = __halves2half2(l10, l11);
    }
    // only the warp pair sharing these 16 rows must sync (64 threads)
    bar_sync(pairBar, 64);

#pragma unroll
    for (int nb = 0; nb < 4; nb++)
#pragma unroll
        for (int u = 0; u < 4; u++) acc[nb][u] = 0.f;

    // ---------- GEMM2 (split HMMA, ldmatrix fragments) ----------
#pragma unroll
    for (int kb = 0; kb < 4; kb++) {
        unsigned ah0, ah1, ah2, ah3, al0, al1, al2, al3;
        ldsm4(ah0, ah1, ah2, ah3, aAh + kb * 32);
        ldsm4(al0, al1, al2, al3, aAl + kb * 32);
#pragma unroll
        for (int p = 0; p < 2; p++) {
            unsigned bh0, bh1, bh2, bh3, bl0, bl1, bl2, bl3;
            ldsm4(bh0, bh1, bh2, bh3, aB2h + p * pStride + kb * 32);
            ldsm4(bl0, bl1, bl2, bl3, aB2l + p * pStride + kb * 32);
            mma16816(acc[2 * p],     ah0, ah1, ah2, ah3, bh0, bh1);
            mma16816(acc[2 * p],     ah0, ah1, ah2, ah3, bl0, bl1);
            mma16816(acc[2 * p],     al0, al1, al2, al3, bh0, bh1);
            mma16816(acc[2 * p + 1], ah0, ah1, ah2, ah3, bh2, bh3);
            mma16816(acc[2 * p + 1], ah0, ah1, ah2, ah3, bl2, bl3);
            mma16816(acc[2 * p + 1], al0, al1, al2, al3, bh2, bh3);
        }
    }

    // epilogue 2: bias + outer ELU
    int grow0 = base + r0;
    int grow1 = grow0 + 8;
#pragma unroll
    for (int nb = 0; nb < 4; nb++) {
        int j = nh + 8 * nb + 2 * tq;
        float2 bv = *reinterpret_cast<const float2*>(&sb2[j]);
        float o00 = elu(acc[nb][0] + bv.x);
        float o01 = elu(acc[nb][1] + bv.y);
        float o10 = elu(acc[nb][2] + bv.x);
        float o11 = elu(acc[nb][3] + bv.y);
        if (write_fp16) {
            if (grow0 < N_NODES) {
                __half h0, l0, h1, l1;
                split16(o00, h0, l0); split16(o01, h1, l1);
                *reinterpret_cast<__half2*>(g_hh + (size_t)grow0 * 64 + j) = __halves2half2(h0, h1);
                *reinterpret_cast<__half2*>(g_hl + (size_t)grow0 * 64 + j) = __halves2half2(l0, l1);
            }
            if (grow1 < N_NODES) {
                __half h0, l0, h1, l1;
                split16(o10, h0, l0); split16(o11, h1, l1);
                *reinterpret_cast<__half2*>(g_hh + (size_t)grow1 * 64 + j) = __halves2half2(h0, h1);
                *reinterpret_cast<__half2*>(g_hl + (size_t)grow1 * 64 + j) = __halves2half2(l0, l1);
            }
        } else {
            if (grow0 < N_NODES)
                *reinterpret_cast<float2*>(g_h + (size_t)grow0 * 64 + j) = make_float2(o00, o01);
            if (grow1 < N_NODES)
                *reinterpret_cast<float2*>(g_h + (size_t)grow1 * 64 + j) = make_float2(o10, o11);
        }
    }
}

// ---------------- mean pool (bounds inlined) ----------------
__global__ void k_pool(const int* __restrict__ batch) {
    int g = blockIdx.x;
    __shared__ int sbounds[2];
    if (threadIdx.x < 2) {
        int target = g + threadIdx.x;       // first batch[m] >= target
        int lo = 0, hi = N_NODES;
        while (lo < hi) {
            int mid = (lo + hi) >> 1;
            if (__ldg(batch + mid) < target) lo = mid + 1; else hi = mid;
        }
        sbounds[threadIdx.x] = lo;
    }
    __syncthreads();
    int start = sbounds[0], end = sbounds[1];

    int f = threadIdx.x & 63;
    int s = threadIdx.x >> 6;
    float acc = 0.f;
    for (int i = start + s; i < end; i += 4)
        acc += g_h[(size_t)i * 64 + f];
    __shared__ float red[256];
    red[threadIdx.x] = acc;
    __syncthreads();
    if (s == 0) {
        float v = red[f] + red[f + 64] + red[f + 128] + red[f + 192];
        float cnt = (float)(end - start);
        g_pooled[g * 64 + f] = v / fmaxf(cnt, 1.0f);
    }
}

// ---------------- head ----------------
__global__ void __launch_bounds__(64) k_head(
    const float* __restrict__ Wr1, const float* __restrict__ br1,
    const float* __restrict__ Wr2, const float* __restrict__ br2,
    const float* __restrict__ Wo,  const float* __restrict__ bo,
    float* __restrict__ out)
{
    __shared__ float Ws[64 * 64];
    __shared__ float s_p[64 * 65];
    __shared__ float sb[64];
    __shared__ float sWo[64];

    const int t = threadIdx.x;
    const int gbase = blockIdx.x * 64;

    sb[t]  = br1[t];
    sWo[t] = Wo[t];
#pragma unroll
    for (int i = t; i < 4096; i += 64) Ws[i] = Wr1[i];
#pragma unroll
    for (int i = 4 * t; i < 4096; i += 256) {
        int r = i >> 6, c = i & 63;
        float4 v = *reinterpret_cast<const float4*>(g_pooled + (size_t)(gbase + r) * 64 + c);
        s_p[r * 65 + c + 0] = v.x;
        s_p[r * 65 + c + 1] = v.y;
        s_p[r * 65 + c + 2] = v.z;
        s_p[r * 65 + c + 3] = v.w;
    }
    __syncthreads();

    const float* myrow = s_p + t * 65;
    float tt[64];

#pragma unroll
    for (int jt = 0; jt < 64; jt += 8) {
        float acc[8];
#pragma unroll
        for (int u = 0; u < 8; u++) acc[u] = 0.f;
#pragma unroll 4
        for (int k = 0; k < 64; k++) {
            float a = myrow[k];
            const float* w = Ws + k * 64 + jt;
            float4 w0 = *reinterpret_cast<const float4*>(w);
            float4 w1 = *reinterpret_cast<const float4*>(w + 4);
            acc[0] += a * w0.x; acc[1] += a * w0.y;
            acc[2] += a * w0.z; acc[3] += a * w0.w;
            acc[4] += a * w1.x; acc[5] += a * w1.y;
            acc[6] += a * w1.z; acc[7] += a * w1.w;
        }
#pragma unroll
        for (int u = 0; u < 8; u++) tt[jt + u] = elu(acc[u] + sb[jt + u]);
    }

#pragma unroll
    for (int j = 0; j < 64; j++) s_p[t * 65 + j] = tt[j];
    __syncthreads();
#pragma unroll
    for (int i = t; i < 4096; i += 64) Ws[i] = Wr2[i];
    sb[t] = br2[t];
    __syncthreads();

    float oacc = 0.f;
#pragma unroll
    for (int jt = 0; jt < 64; jt += 8) {
        float acc[8];
#pragma unroll
        for (int u = 0; u < 8; u++) acc[u] = 0.f;
#pragma unroll 4
        for (int k = 0; k < 64; k++) {
            float a = myrow[k];
            const float* w = Ws + k * 64 + jt;
            float4 w0 = *reinterpret_cast<const float4*>(w);
            float4 w1 = *reinterpret_cast<const float4*>(w + 4);
            acc[0] += a * w0.x; acc[1] += a * w0.y;
            acc[2] += a * w0.z; acc[3] += a * w0.w;
            acc[4] += a * w1.x; acc[5] += a * w1.y;
            acc[6] += a * w1.z; acc[7] += a * w1.w;
        }
#pragma unroll
        for (int u = 0; u < 8; u++)
            oacc += (acc[u] + sb[jt + u]) * sWo[jt + u];
    }
    out[gbase + t] = oacc + bo[0];
}

// ---------------- launcher ----------------
extern "C" void kernel_launch(void* const* d_in, const int* in_sizes, int n_in,
                              void* d_out, int out_size) {
    const int*   x     = (const int*)d_in[0];
    const int*   ei    = (const int*)d_in[1];
    const int*   batch = (const int*)d_in[2];
    const float* emb   = (const float*)d_in[3];
    const int* src = ei;
    const int* dst = ei + N_EDGES;
    float* out = (float*)d_out;

    const int TPB = 256;
    const int gnod = (N_NODES + TPB - 1) / TPB;
    const int gedg = (N_EDGES + TPB - 1) / TPB;
    const int gmlp = (N_NODES + 63) / 64;
    const int ggat = (N_NODES + 15) / 16;

    // launch 1: weight pre-split + cnt zeroing (merged)
    k_split_zero<<<gnod, TPB>>>(
        (const float*)d_in[4],  (const float*)d_in[8],   // W1a, W2a
        (const float*)d_in[10], (const float*)d_in[14],  // W1b, W2b
        (const float*)d_in[16], (const float*)d_in[20]); // W1c, W2c
    k_fill<<<gedg, TPB>>>(src, dst);                     // launch 2

    for (int L = 0; L < 3; L++) {
        const float* b1  = (const float*)d_in[4 + 6 * L + 1];
        const float* gam = (const float*)d_in[4 + 6 * L + 2];
        const float* bet = (const float*)d_in[4 + 6 * L + 3];
        const float* b2  = (const float*)d_in[4 + 6 * L + 5];

        if (L == 0)
            k_gather1<<<ggat, 256>>>(x, emb);            // launch 3
        else
            k_gather<<<ggat, 256>>>();
        // launch 4 = k_mlp (layer 1) -> ncu capture slot
        k_mlp<<<gmlp, 256>>>(2 * L, b1, gam, bet, b2, (L < 2) ? 1 : 0);
    }

    k_pool<<<N_GRAPHS, 256>>>(batch);
    k_head<<<2, 64>>>((const float*)d_in[22], (const float*)d_in[23],
                      (const float*)d_in[24], (const float*)d_in[25],
                      (const float*)d_in[26], (const float*)d_in[27],
                      out);
}

// round 16
// speedup vs baseline: 1.3395x; 1.0109x over previous
#include <cuda_runtime.h>
#include <cuda_bf16.h>
#include <cuda_fp16.h>
#include <math.h>

#define N_NODES 100000
#define N_EDGES 1200000
#define N_GRAPHS 128
#define VOCAB 10000
#define MAX_DEG 64            // Poisson(12): P(deg>=64) ~ 1e-30, guarded anyway
#define AROW 72               // smem row stride in halves (144B): conflict-free fragments

// ---------------- scratch ----------------
__device__ float  g_h[(size_t)N_NODES * 64];            // final-layer output (pool input)
__device__ __align__(16) __half g_hh[(size_t)N_NODES * 64];  // h hi mirror
__device__ __align__(16) __half g_hl[(size_t)N_NODES * 64];  // h lo mirror
__device__ __align__(16) __half g_aggh[(size_t)N_NODES * 64]; // agg hi (pre-split)
__device__ __align__(16) __half g_aggl[(size_t)N_NODES * 64]; // agg lo (pre-split)
__device__ __align__(16) __half g_embh[(size_t)VOCAB * 64];   // fp16 mirror of emb
__device__ float  g_pooled[N_GRAPHS * 64];

__device__ int g_cnt[N_NODES];
__device__ int g_adj[(size_t)N_NODES * MAX_DEG];

// pre-split transposed weights: [matrix][n*64+k], matrices 2L=W1, 2L+1=W2
__device__ __align__(16) __half g_wh[6 * 4096];
__device__ __align__(16) __half g_wl[6 * 4096];

__device__ __forceinline__ float elu(float v) {
    return v > 0.f ? v : expm1f(v);
}

// ---- HMMA m16n8k16 row.col f16f16f32 ----
__device__ __forceinline__ void mma16816(float* d,
    unsigned a0, unsigned a1, unsigned a2, unsigned a3,
    unsigned b0, unsigned b1)
{
    asm volatile(
        "mma.sync.aligned.m16n8k16.row.col.f32.f16.f16.f32 "
        "{%0,%1,%2,%3}, {%4,%5,%6,%7}, {%8,%9}, {%0,%1,%2,%3};"
        : "+f"(d[0]), "+f"(d[1]), "+f"(d[2]), "+f"(d[3])
        : "r"(a0), "r"(a1), "r"(a2), "r"(a3), "r"(b0), "r"(b1));
}

// ---- ldmatrix m8n8.x4 ----
__device__ __forceinline__ void ldsm4(unsigned& r0, unsigned& r1,
                                      unsigned& r2, unsigned& r3, unsigned addr)
{
    asm volatile("ldmatrix.sync.aligned.m8n8.x4.shared.b16 {%0,%1,%2,%3}, [%4];"
                 : "=r"(r0), "=r"(r1), "=r"(r2), "=r"(r3) : "r"(addr));
}

__device__ __forceinline__ unsigned smem_u32(const void* p) {
    return (unsigned)__cvta_generic_to_shared(p);
}

__device__ __forceinline__ void bar_sync(int id, int cnt) {
    asm volatile("bar.sync %0, %1;" :: "r"(id), "r"(cnt) : "memory");
}

// split float into fp16 hi + fp16 lo (a ~= hi + lo)
__device__ __forceinline__ void split16(float a, __half& hi, __half& lo) {
    hi = __float2half_rn(a);
    lo = __float2half_rn(a - __half2float(hi));
}

// split float4 into hi/lo half2 pairs
__device__ __forceinline__ void split4(float4 v, uint2& ph, uint2& pl) {
    __half hx, lx, hy, ly, hz, lz, hw, lw;
    split16(v.x, hx, lx); split16(v.y, hy, ly);
    split16(v.z, hz, lz); split16(v.w, hw, lw);
    __half2 h0 = __halves2half2(hx, hy), h1 = __halves2half2(hz, hw);
    __half2 l0 = __halves2half2(lx, ly), l1 = __halves2half2(lz, lw);
    ph.x = *reinterpret_cast<unsigned*>(&h0);
    ph.y = *reinterpret_cast<unsigned*>(&h1);
    pl.x = *reinterpret_cast<unsigned*>(&l0);
    pl.y = *reinterpret_cast<unsigned*>(&l1);
}

// ------- weight pre-split + emb fp16 mirror + g_cnt zeroing, merged ---------
__global__ void k_split_zero(const float* __restrict__ w0, const float* __restrict__ w1,
                             const float* __restrict__ w2, const float* __restrict__ w3,
                             const float* __restrict__ w4, const float* __restrict__ w5,
                             const float* __restrict__ emb)
{
    int i = blockIdx.x * blockDim.x + threadIdx.x;
    if (i < N_NODES) g_cnt[i] = 0;
    if (i < 6 * 4096) {
        int m = i >> 12, j = i & 4095;
        const float* W;
        switch (m) {
            case 0: W = w0; break;
            case 1: W = w1; break;
            case 2: W = w2; break;
            case 3: W = w3; break;
            case 4: W = w4; break;
            default: W = w5; break;
        }
        float v = __ldg(W + j);
        int k = j >> 6, n = j & 63;           // W[k][n] -> Wt[n][k]
        __half hi, lo;
        split16(v, hi, lo);
        g_wh[m * 4096 + n * 64 + k] = hi;
        g_wl[m * 4096 + n * 64 + k] = lo;
    }
    if (i < VOCAB * 64)
        g_embh[i] = __float2half_rn(__ldg(emb + i));
}

__global__ void k_fill(const int* __restrict__ src, const int* __restrict__ dst) {
    int e = blockIdx.x * blockDim.x + threadIdx.x;
    if (e >= N_EDGES) return;
    int d = __ldg(dst + e);
    int slot = atomicAdd(&g_cnt[d], 1);
    if (slot < MAX_DEG)
        g_adj[(size_t)d * MAX_DEG + slot] = __ldg(src + e);
}

// ------- layer-1 gather: self fp32 from emb, neighbors fp16 from g_embh -----
__global__ void __launch_bounds__(256) k_gather1(const int* __restrict__ x,
                                                 const float* __restrict__ emb) {
    int t = threadIdx.x;
    int n = blockIdx.x * 16 + (t >> 4);
    int c = t & 15;
    if (n >= N_NODES) return;
    const float4* __restrict__ e4 = reinterpret_cast<const float4*>(emb);
    const uint2* __restrict__ eh2 = reinterpret_cast<const uint2*>(g_embh);
    int xn = __ldg(x + n);
    float4 acc = e4[(size_t)xn * 16 + c];
    const int* __restrict__ alist = g_adj + (size_t)n * MAX_DEG;
    int e = min(g_cnt[n], MAX_DEG);
    for (int i = 0; i < e; i++) {
        int s = __ldg(alist + i);
        int xs = __ldg(x + s);
        uint2 v = __ldg(&eh2[(size_t)xs * 16 + c]);
        float2 f0 = __half22float2(*reinterpret_cast<__half2*>(&v.x));
        float2 f1 = __half22float2(*reinterpret_cast<__half2*>(&v.y));
        acc.x += f0.x; acc.y += f0.y; acc.z += f1.x; acc.w += f1.y;
    }
    uint2 ph, pl;
    split4(acc, ph, pl);
    reinterpret_cast<uint2*>(g_aggh)[(size_t)n * 16 + c] = ph;
    reinterpret_cast<uint2*>(g_aggl)[(size_t)n * 16 + c] = pl;
}

// ------- gather (layers 2-3): agg[n] = (hh+hl)[n] + sum hh[nb], pre-split ---
__global__ void __launch_bounds__(256) k_gather() {
    int t = threadIdx.x;
    int n = blockIdx.x * 16 + (t >> 4);
    int c = t & 15;
    if (n >= N_NODES) return;
    const uint2* __restrict__ hh2 = reinterpret_cast<const uint2*>(g_hh);
    const uint2* __restrict__ hl2 = reinterpret_cast<const uint2*>(g_hl);
    uint2 sh = __ldg(&hh2[(size_t)n * 16 + c]);
    uint2 sl = __ldg(&hl2[(size_t)n * 16 + c]);
    float2 a0 = __half22float2(*reinterpret_cast<__half2*>(&sh.x));
    float2 a1 = __half22float2(*reinterpret_cast<__half2*>(&sh.y));
    float2 b0 = __half22float2(*reinterpret_cast<__half2*>(&sl.x));
    float2 b1 = __half22float2(*reinterpret_cast<__half2*>(&sl.y));
    float4 acc = make_float4(a0.x + b0.x, a0.y + b0.y, a1.x + b1.x, a1.y + b1.y);

    const int* __restrict__ alist = g_adj + (size_t)n * MAX_DEG;
    int e = min(g_cnt[n], MAX_DEG);
    int nxt = (e > 0) ? __ldg(alist) : 0;
    for (int i = 0; i < e; i++) {
        int cur = nxt;
        if (i + 1 < e) nxt = __ldg(alist + i + 1);
        uint2 v = __ldg(&hh2[(size_t)cur * 16 + c]);
        float2 f0 = __half22float2(*reinterpret_cast<__half2*>(&v.x));
        float2 f1 = __half22float2(*reinterpret_cast<__half2*>(&v.y));
        acc.x += f0.x; acc.y += f0.y; acc.z += f1.x; acc.w += f1.y;
    }
    uint2 ph, pl;
    split4(acc, ph, pl);
    reinterpret_cast<uint2*>(g_aggh)[(size_t)n * 16 + c] = ph;
    reinterpret_cast<uint2*>(g_aggl)[(size_t)n * 16 + c] = pl;
}

// ---------------- fused MLP+BN+ELU via split-fp16 HMMA + ldmatrix -----------
// 256 threads = 8 warps; warp w owns rows 16*(w>>1)..+15, n-half (w&1)*32.
// W1 AND W2 staged upfront; mid-kernel sync is a 64-thread named barrier
// per warp pair (the only epi1->GEMM2 dependency is within the pair).
__global__ void __launch_bounds__(256) k_mlp(
    int widx,
    const float* __restrict__ b1,
    const float* __restrict__ gam, const float* __restrict__ bet,
    const float* __restrict__ b2,
    int write_fp16)
{
    __shared__ __half sAh[64 * AROW];
    __shared__ __half sAl[64 * AROW];
    __shared__ __half sW1h[64 * AROW];
    __shared__ __half sW1l[64 * AROW];
    __shared__ __half sW2h[64 * AROW];
    __shared__ __half sW2l[64 * AROW];
    __shared__ float sb1[64], ssc[64], sbe[64], sb2[64];

    const int t = threadIdx.x;
    const int w = t >> 5;
    const int lane = t & 31;
    const int g = lane >> 2;       // 0..7
    const int tq = lane & 3;       // 0..3
    const int base = blockIdx.x * 64;
    const int rg16 = (w >> 1) * 16;      // row group
    const int nh   = (w & 1) * 32;       // n-half column offset
    const int pairBar = 1 + (w >> 1);    // named barrier id per warp pair

    if (t < 64) {
        sb1[t] = b1[t];
        ssc[t] = gam[t] * rsqrtf(1.0f + 1e-5f);
        sbe[t] = bet[t];
        sb2[t] = b2[t];
    }

    // stage W1^T and W2^T hi/lo upfront: pure vectorized copy
    {
        const uint4* s1h = reinterpret_cast<const uint4*>(g_wh + (size_t)widx * 4096);
        const uint4* s1l = reinterpret_cast<const uint4*>(g_wl + (size_t)widx * 4096);
        const uint4* s2h = reinterpret_cast<const uint4*>(g_wh + (size_t)(widx + 1) * 4096);
        const uint4* s2l = reinterpret_cast<const uint4*>(g_wl + (size_t)(widx + 1) * 4096);
#pragma unroll
        for (int i = t; i < 512; i += 256) {
            int n = i >> 3, kc = i & 7;
            *reinterpret_cast<uint4*>(sW1h + n * AROW + kc * 8) = s1h[i];
            *reinterpret_cast<uint4*>(sW1l + n * AROW + kc * 8) = s1l[i];
            *reinterpret_cast<uint4*>(sW2h + n * AROW + kc * 8) = s2h[i];
            *reinterpret_cast<uint4*>(sW2l + n * AROW + kc * 8) = s2l[i];
        }
    }
    // stage activations: pure vectorized copy of pre-split hi/lo
    {
        const uint4* ah4 = reinterpret_cast<const uint4*>(g_aggh);
        const uint4* al4 = reinterpret_cast<const uint4*>(g_aggl);
        const uint4 z = make_uint4(0, 0, 0, 0);
#pragma unroll
        for (int i = t; i < 512; i += 256) {
            int r = i >> 3, c8 = i & 7;
            int row = base + r;
            uint4 vh = z, vl = z;
            if (row < N_NODES) {
                vh = ah4[(size_t)row * 8 + c8];
                vl = al4[(size_t)row * 8 + c8];
            }
            *reinterpret_cast<uint4*>(sAh + r * AROW + c8 * 8) = vh;
            *reinterpret_cast<uint4*>(sAl + r * AROW + c8 * 8) = vl;
        }
    }
    __syncthreads();

    const int r0 = rg16 + g;            // local row (first half)

    // ---- ldmatrix lane address setup ----
    const int rowA  = rg16 + (lane & 15);
    const int koffA = (lane >> 4) * 8;
    unsigned aAh = smem_u32(sAh + rowA * AROW + koffA);
    unsigned aAl = smem_u32(sAl + rowA * AROW + koffA);
    const int nB    = nh + (lane & 7) + ((lane >> 4) << 3);
    const int koffB = ((lane >> 3) & 1) * 8;
    unsigned aB1h = smem_u32(sW1h + nB * AROW + koffB);
    unsigned aB1l = smem_u32(sW1l + nB * AROW + koffB);
    unsigned aB2h = smem_u32(sW2h + nB * AROW + koffB);
    unsigned aB2l = smem_u32(sW2l + nB * AROW + koffB);
    const unsigned pStride = 16 * AROW * 2;   // 16 n-rows per pair, bytes

    float acc[4][4];
#pragma unroll
    for (int nb = 0; nb < 4; nb++)
#pragma unroll
        for (int u = 0; u < 4; u++) acc[nb][u] = 0.f;

    // ---------- GEMM1 (split HMMA, ldmatrix fragments) ----------
#pragma unroll
    for (int kb = 0; kb < 4; kb++) {
        unsigned ah0, ah1, ah2, ah3, al0, al1, al2, al3;
        ldsm4(ah0, ah1, ah2, ah3, aAh + kb * 32);
        ldsm4(al0, al1, al2, al3, aAl + kb * 32);
#pragma unroll
        for (int p = 0; p < 2; p++) {
            unsigned bh0, bh1, bh2, bh3, bl0, bl1, bl2, bl3;
            ldsm4(bh0, bh1, bh2, bh3, aB1h + p * pStride + kb * 32);
            ldsm4(bl0, bl1, bl2, bl3, aB1l + p * pStride + kb * 32);
            mma16816(acc[2 * p],     ah0, ah1, ah2, ah3, bh0, bh1);
            mma16816(acc[2 * p],     ah0, ah1, ah2, ah3, bl0, bl1);
            mma16816(acc[2 * p],     al0, al1, al2, al3, bh0, bh1);
            mma16816(acc[2 * p + 1], ah0, ah1, ah2, ah3, bh2, bh3);
            mma16816(acc[2 * p + 1], ah0, ah1, ah2, ah3, bl2, bl3);
            mma16816(acc[2 * p + 1], al0, al1, al2, al3, bh2, bh3);
        }
    }

    // epilogue 1: BN affine + ELU -> own rows/cols, split fp16
#pragma unroll
    for (int nb = 0; nb < 4; nb++) {
        int j = nh + 8 * nb + 2 * tq;
        float2 bv = *reinterpret_cast<const float2*>(&sb1[j]);
        float2 sv = *reinterpret_cast<const float2*>(&ssc[j]);
        float2 ev = *reinterpret_cast<const float2*>(&sbe[j]);
        float v00 = elu((acc[nb][0] + bv.x) * sv.x + ev.x);
        float v01 = elu((acc[nb][1] + bv.y) * sv.y + ev.y);
        float v10 = elu((acc[nb][2] + bv.x) * sv.x + ev.x);
        float v11 = elu((acc[nb][3] + bv.y) * sv.y + ev.y);
        __half h00, l00, h01, l01, h10, l10, h11, l11;
        split16(v00, h00, l00); split16(v01, h01, l01);
        split16(v10, h10, l10); split16(v11, h11, l11);
        *reinterpret_cast<__half2*>(sAh + r0 * AROW + j)       = __halves2half2(h00, h01);
        *reinterpret_cast<__half2*>(sAl + r0 * AROW + j)       = __halves2half2(l00, l01);
        *reinterpret_cast<__half2*>(sAh + (r0 + 8) * AROW + j) = __halves2half2(h10, h11);
        *reinterpret_cast<__half2*>(sAl + (r0 + 8) * AROW + j) = __halves2half2(l10, l11);
    }
    // only the warp pair sharing these 16 rows must sync (64 threads)
    bar_sync(pairBar, 64);

#pragma unroll
    for (int nb = 0; nb < 4; nb++)
#pragma unroll
        for (int u = 0; u < 4; u++) acc[nb][u] = 0.f;

    // ---------- GEMM2 (split HMMA, ldmatrix fragments) ----------
#pragma unroll
    for (int kb = 0; kb < 4; kb++) {
        unsigned ah0, ah1, ah2, ah3, al0, al1, al2, al3;
        ldsm4(ah0, ah1, ah2, ah3, aAh + kb * 32);
        ldsm4(al0, al1, al2, al3, aAl + kb * 32);
#pragma unroll
        for (int p = 0; p < 2; p++) {
            unsigned bh0, bh1, bh2, bh3, bl0, bl1, bl2, bl3;
            ldsm4(bh0, bh1, bh2, bh3, aB2h + p * pStride + kb * 32);
            ldsm4(bl0, bl1, bl2, bl3, aB2l + p * pStride + kb * 32);
            mma16816(acc[2 * p],     ah0, ah1, ah2, ah3, bh0, bh1);
            mma16816(acc[2 * p],     ah0, ah1, ah2, ah3, bl0, bl1);
            mma16816(acc[2 * p],     al0, al1, al2, al3, bh0, bh1);
            mma16816(acc[2 * p + 1], ah0, ah1, ah2, ah3, bh2, bh3);
            mma16816(acc[2 * p + 1], ah0, ah1, ah2, ah3, bl2, bl3);
            mma16816(acc[2 * p + 1], al0, al1, al2, al3, bh2, bh3);
        }
    }

    // epilogue 2: bias + outer ELU
    int grow0 = base + r0;
    int grow1 = grow0 + 8;
#pragma unroll
    for (int nb = 0; nb < 4; nb++) {
        int j = nh + 8 * nb + 2 * tq;
        float2 bv = *reinterpret_cast<const float2*>(&sb2[j]);
        float o00 = elu(acc[nb][0] + bv.x);
        float o01 = elu(acc[nb][1] + bv.y);
        float o10 = elu(acc[nb][2] + bv.x);
        float o11 = elu(acc[nb][3] + bv.y);
        if (write_fp16) {
            if (grow0 < N_NODES) {
                __half h0, l0, h1, l1;
                split16(o00, h0, l0); split16(o01, h1, l1);
                *reinterpret_cast<__half2*>(g_hh + (size_t)grow0 * 64 + j) = __halves2half2(h0, h1);
                *reinterpret_cast<__half2*>(g_hl + (size_t)grow0 * 64 + j) = __halves2half2(l0, l1);
            }
            if (grow1 < N_NODES) {
                __half h0, l0, h1, l1;
                split16(o10, h0, l0); split16(o11, h1, l1);
                *reinterpret_cast<__half2*>(g_hh + (size_t)grow1 * 64 + j) = __halves2half2(h0, h1);
                *reinterpret_cast<__half2*>(g_hl + (size_t)grow1 * 64 + j) = __halves2half2(l0, l1);
            }
        } else {
            if (grow0 < N_NODES)
                *reinterpret_cast<float2*>(g_h + (size_t)grow0 * 64 + j) = make_float2(o00, o01);
            if (grow1 < N_NODES)
                *reinterpret_cast<float2*>(g_h + (size_t)grow1 * 64 + j) = make_float2(o10, o11);
        }
    }
}

// ---------------- mean pool (bounds inlined) ----------------
__global__ void k_pool(const int* __restrict__ batch) {
    int g = blockIdx.x;
    __shared__ int sbounds[2];
    if (threadIdx.x < 2) {
        int target = g + threadIdx.x;       // first batch[m] >= target
        int lo = 0, hi = N_NODES;
        while (lo < hi) {
            int mid = (lo + hi) >> 1;
            if (__ldg(batch + mid) < target) lo = mid + 1; else hi = mid;
        }
        sbounds[threadIdx.x] = lo;
    }
    __syncthreads();
    int start = sbounds[0], end = sbounds[1];

    int f = threadIdx.x & 63;
    int s = threadIdx.x >> 6;
    float acc = 0.f;
    for (int i = start + s; i < end; i += 4)
        acc += g_h[(size_t)i * 64 + f];
    __shared__ float red[256];
    red[threadIdx.x] = acc;
    __syncthreads();
    if (s == 0) {
        float v = red[f] + red[f + 64] + red[f + 128] + red[f + 192];
        float cnt = (float)(end - start);
        g_pooled[g * 64 + f] = v / fmaxf(cnt, 1.0f);
    }
}

// ---------------- head ----------------
__global__ void __launch_bounds__(64) k_head(
    const float* __restrict__ Wr1, const float* __restrict__ br1,
    const float* __restrict__ Wr2, const float* __restrict__ br2,
    const float* __restrict__ Wo,  const float* __restrict__ bo,
    float* __restrict__ out)
{
    __shared__ float Ws[64 * 64];
    __shared__ float s_p[64 * 65];
    __shared__ float sb[64];
    __shared__ float sWo[64];

    const int t = threadIdx.x;
    const int gbase = blockIdx.x * 64;

    sb[t]  = br1[t];
    sWo[t] = Wo[t];
#pragma unroll
    for (int i = t; i < 4096; i += 64) Ws[i] = Wr1[i];
#pragma unroll
    for (int i = 4 * t; i < 4096; i += 256) {
        int r = i >> 6, c = i & 63;
        float4 v = *reinterpret_cast<const float4*>(g_pooled + (size_t)(gbase + r) * 64 + c);
        s_p[r * 65 + c + 0] = v.x;
        s_p[r * 65 + c + 1] = v.y;
        s_p[r * 65 + c + 2] = v.z;
        s_p[r * 65 + c + 3] = v.w;
    }
    __syncthreads();

    const float* myrow = s_p + t * 65;
    float tt[64];

#pragma unroll
    for (int jt = 0; jt < 64; jt += 8) {
        float acc[8];
#pragma unroll
        for (int u = 0; u < 8; u++) acc[u] = 0.f;
#pragma unroll 4
        for (int k = 0; k < 64; k++) {
            float a = myrow[k];
            const float* w = Ws + k * 64 + jt;
            float4 w0 = *reinterpret_cast<const float4*>(w);
            float4 w1 = *reinterpret_cast<const float4*>(w + 4);
            acc[0] += a * w0.x; acc[1] += a * w0.y;
            acc[2] += a * w0.z; acc[3] += a * w0.w;
            acc[4] += a * w1.x; acc[5] += a * w1.y;
            acc[6] += a * w1.z; acc[7] += a * w1.w;
        }
#pragma unroll
        for (int u = 0; u < 8; u++) tt[jt + u] = elu(acc[u] + sb[jt + u]);
    }

#pragma unroll
    for (int j = 0; j < 64; j++) s_p[t * 65 + j] = tt[j];
    __syncthreads();
#pragma unroll
    for (int i = t; i < 4096; i += 64) Ws[i] = Wr2[i];
    sb[t] = br2[t];
    __syncthreads();

    float oacc = 0.f;
#pragma unroll
    for (int jt = 0; jt < 64; jt += 8) {
        float acc[8];
#pragma unroll
        for (int u = 0; u < 8; u++) acc[u] = 0.f;
#pragma unroll 4
        for (int k = 0; k < 64; k++) {
            float a = myrow[k];
            const float* w = Ws + k * 64 + jt;
            float4 w0 = *reinterpret_cast<const float4*>(w);
            float4 w1 = *reinterpret_cast<const float4*>(w + 4);
            acc[0] += a * w0.x; acc[1] += a * w0.y;
            acc[2] += a * w0.z; acc[3] += a * w0.w;
            acc[4] += a * w1.x; acc[5] += a * w1.y;
            acc[6] += a * w1.z; acc[7] += a * w1.w;
        }
#pragma unroll
        for (int u = 0; u < 8; u++)
            oacc += (acc[u] + sb[jt + u]) * sWo[jt + u];
    }
    out[gbase + t] = oacc + bo[0];
}

// ---------------- launcher ----------------
extern "C" void kernel_launch(void* const* d_in, const int* in_sizes, int n_in,
                              void* d_out, int out_size) {
    const int*   x     = (const int*)d_in[0];
    const int*   ei    = (const int*)d_in[1];
    const int*   batch = (const int*)d_in[2];
    const float* emb   = (const float*)d_in[3];
    const int* src = ei;
    const int* dst = ei + N_EDGES;
    float* out = (float*)d_out;

    const int TPB = 256;
    const int gsplit = (VOCAB * 64 + TPB - 1) / TPB;   // covers emb, weights, cnt
    const int gedg = (N_EDGES + TPB - 1) / TPB;
    const int gmlp = (N_NODES + 63) / 64;
    const int ggat = (N_NODES + 15) / 16;

    // launch 1: weight pre-split + emb fp16 mirror + cnt zeroing (merged)
    k_split_zero<<<gsplit, TPB>>>(
        (const float*)d_in[4],  (const float*)d_in[8],   // W1a, W2a
        (const float*)d_in[10], (const float*)d_in[14],  // W1b, W2b
        (const float*)d_in[16], (const float*)d_in[20],  // W1c, W2c
        emb);
    k_fill<<<gedg, TPB>>>(src, dst);                     // launch 2

    for (int L = 0; L < 3; L++) {
        const float* b1  = (const float*)d_in[4 + 6 * L + 1];
        const float* gam = (const float*)d_in[4 + 6 * L + 2];
        const float* bet = (const float*)d_in[4 + 6 * L + 3];
        const float* b2  = (const float*)d_in[4 + 6 * L + 5];

        if (L == 0)
            k_gather1<<<ggat, 256>>>(x, emb);            // launch 3
        else
            k_gather<<<ggat, 256>>>();
        // launch 4 = k_mlp (layer 1) -> ncu capture slot
        k_mlp<<<gmlp, 256>>>(2 * L, b1, gam, bet, b2, (L < 2) ? 1 : 0);
    }

    k_pool<<<N_GRAPHS, 256>>>(batch);
    k_head<<<2, 64>>>((const float*)d_in[22], (const float*)d_in[23],
                      (const float*)d_in[24], (const float*)d_in[25],
                      (const float*)d_in[26], (const float*)d_in[27],
                      out);
}